// round 8
// baseline (speedup 1.0000x reference)
#include <cuda_runtime.h>
#include <cuda_fp16.h>
#include <mma.h>
#include <cstdint>

using namespace nvcuda;

// B=4, L=4096, C=1024, M=128, P=4, S=64, H=8, hd=128
// NSEG=256, TOKS=16384, context T=132

__device__ float d_scratch[162100000ull];

__device__ __forceinline__ void cp16(uint32_t s, const void* g) {
    asm volatile("cp.async.cg.shared.global [%0], [%1], 16;\n" :: "r"(s), "l"(g) : "memory");
}

// ===========================================================================
// fp16 wmma GEMM (small-N / mem-net path): 128x128 tile, Ktile 64, f32 out
// ===========================================================================
#define HLD 72
#define HSTS 9216
#define GSM 147456

__device__ __forceinline__ void load_tile_h(const __half* Ag0, const __half* Wg0,
                                            int K, int it, __half* As, __half* Bs, int tid)
{
    const __half* Ag = Ag0 + it*64;
    const __half* Wg = Wg0 + it*64;
    uint32_t sA = (uint32_t)__cvta_generic_to_shared(As);
    uint32_t sB = (uint32_t)__cvta_generic_to_shared(Bs);
    #pragma unroll
    for (int i = 0; i < 4; i++) {
        int ch = tid + i*256;
        int r = ch >> 3, c = (ch & 7) << 3;
        cp16(sA + (uint32_t)(r*HLD + c)*2u, Ag + (size_t)r*K + c);
        cp16(sB + (uint32_t)(r*HLD + c)*2u, Wg + (size_t)r*K + c);
    }
}

__global__ __launch_bounds__(256)
void gemm_h_kernel(const __half* __restrict__ A, const __half* __restrict__ W,
                   float* __restrict__ Cout, int M, int N, int K)
{
    extern __shared__ __align__(16) __half smh[];
    __half* As = smh;
    __half* Bs = smh + 4*HSTS;

    const int tid  = threadIdx.x;
    const int warp = tid >> 5;
    const int wm   = warp & 3;
    const int wn   = warp >> 2;
    const int m0   = blockIdx.y * 128;
    const int n0   = blockIdx.x * 128;
    const int nk   = K >> 6;

    const __half* Ag0 = A + (size_t)m0*K;
    const __half* Wg0 = W + (size_t)n0*K;

    wmma::fragment<wmma::accumulator,16,16,16,float> cf[2][4];
    #pragma unroll
    for (int i = 0; i < 2; i++)
        #pragma unroll
        for (int j = 0; j < 4; j++)
            wmma::fill_fragment(cf[i][j], 0.0f);

    #pragma unroll
    for (int s = 0; s < 3; s++) {
        if (s < nk) load_tile_h(Ag0, Wg0, K, s, As + s*HSTS, Bs + s*HSTS, tid);
        asm volatile("cp.async.commit_group;\n" ::: "memory");
    }

    for (int it = 0; it < nk; it++) {
        if (it + 3 < nk) {
            int slot = (it + 3) & 3;
            load_tile_h(Ag0, Wg0, K, it + 3, As + slot*HSTS, Bs + slot*HSTS, tid);
        }
        asm volatile("cp.async.commit_group;\n" ::: "memory");
        asm volatile("cp.async.wait_group 3;\n" ::: "memory");
        __syncthreads();

        const __half* Ab = As + (it & 3)*HSTS;
        const __half* Bb = Bs + (it & 3)*HSTS;
        #pragma unroll
        for (int kk = 0; kk < 64; kk += 16) {
            wmma::fragment<wmma::matrix_a,16,16,16,__half,wmma::row_major> af[2];
            wmma::fragment<wmma::matrix_b,16,16,16,__half,wmma::col_major> bf[4];
            #pragma unroll
            for (int i = 0; i < 2; i++)
                wmma::load_matrix_sync(af[i], Ab + (wm*32 + i*16)*HLD + kk, HLD);
            #pragma unroll
            for (int j = 0; j < 4; j++)
                wmma::load_matrix_sync(bf[j], Bb + (wn*64 + j*16)*HLD + kk, HLD);
            #pragma unroll
            for (int i = 0; i < 2; i++)
                #pragma unroll
                for (int j = 0; j < 4; j++)
                    wmma::mma_sync(cf[i][j], af[i], bf[j], cf[i][j]);
        }
        __syncthreads();
    }

    #pragma unroll
    for (int i = 0; i < 2; i++)
        #pragma unroll
        for (int j = 0; j < 4; j++)
            wmma::store_matrix_sync(&Cout[(size_t)(m0 + wm*32 + i*16)*N + n0 + wn*64 + j*16],
                                    cf[i][j], N, wmma::mem_row_major);
}

// ===========================================================================
// fp16 wmma GEMM main path: 256x128 CTA tile, 64x64 warp tile, Ktile 32,
// 4 stages, slab-staged epilogue.
// MODE 0: f32 out.  MODE 1: half out.
// MODE 3: gate fusion  u = sigmoid(acc + bias[col]) * aux1 + aux2  -> half
// MODE 4: f32 out + bias[col]
// ===========================================================================
#define H2LD 40
#define H2_AS 10240
#define H2_BS 5120
#define GSM2 ((4*(H2_AS + H2_BS))*2)

__device__ __forceinline__ void load_tile_h2(const __half* Ag0, const __half* Wg0,
                                             int K, int it, __half* As, __half* Bs, int tid)
{
    const __half* Ag = Ag0 + it*32;
    const __half* Wg = Wg0 + it*32;
    uint32_t sA = (uint32_t)__cvta_generic_to_shared(As);
    uint32_t sB = (uint32_t)__cvta_generic_to_shared(Bs);
    #pragma unroll
    for (int i = 0; i < 4; i++) {
        int ch = tid + i*256;
        int r = ch >> 2, c = (ch & 3) << 3;
        cp16(sA + (uint32_t)(r*H2LD + c)*2u, Ag + (size_t)r*K + c);
    }
    #pragma unroll
    for (int i = 0; i < 2; i++) {
        int ch = tid + i*256;
        int r = ch >> 2, c = (ch & 3) << 3;
        cp16(sB + (uint32_t)(r*H2LD + c)*2u, Wg + (size_t)r*K + c);
    }
}

template<int MODE>
__global__ __launch_bounds__(256)
void gemm_h2_kernel(const __half* __restrict__ A, const __half* __restrict__ W,
                    void* __restrict__ Cout, const float* __restrict__ bias,
                    const float* __restrict__ aux1, const float* __restrict__ aux2,
                    int M, int N, int K)
{
    extern __shared__ __align__(16) __half smh[];
    __half* As = smh;
    __half* Bs = smh + 4*H2_AS;

    const int tid  = threadIdx.x;
    const int warp = tid >> 5;
    const int lane = tid & 31;
    const int wm   = warp & 3;
    const int wn   = warp >> 2;
    const int m0   = blockIdx.y * 256;
    const int n0   = blockIdx.x * 128;
    const int nk   = K >> 5;

    const __half* Ag0 = A + (size_t)m0*K;
    const __half* Wg0 = W + (size_t)n0*K;

    wmma::fragment<wmma::accumulator,16,16,16,float> cf[4][4];
    #pragma unroll
    for (int i = 0; i < 4; i++)
        #pragma unroll
        for (int j = 0; j < 4; j++)
            wmma::fill_fragment(cf[i][j], 0.0f);

    #pragma unroll
    for (int s = 0; s < 3; s++) {
        if (s < nk) load_tile_h2(Ag0, Wg0, K, s, As + s*H2_AS, Bs + s*H2_BS, tid);
        asm volatile("cp.async.commit_group;\n" ::: "memory");
    }

    for (int it = 0; it < nk; it++) {
        if (it + 3 < nk) {
            int slot = (it + 3) & 3;
            load_tile_h2(Ag0, Wg0, K, it + 3, As + slot*H2_AS, Bs + slot*H2_BS, tid);
        }
        asm volatile("cp.async.commit_group;\n" ::: "memory");
        asm volatile("cp.async.wait_group 3;\n" ::: "memory");
        __syncthreads();

        const __half* Ab = As + (it & 3)*H2_AS;
        const __half* Bb = Bs + (it & 3)*H2_BS;
        #pragma unroll
        for (int kk = 0; kk < 32; kk += 16) {
            wmma::fragment<wmma::matrix_a,16,16,16,__half,wmma::row_major> af[4];
            wmma::fragment<wmma::matrix_b,16,16,16,__half,wmma::col_major> bf[4];
            #pragma unroll
            for (int i = 0; i < 4; i++)
                wmma::load_matrix_sync(af[i], Ab + (wm*64 + i*16)*H2LD + kk, H2LD);
            #pragma unroll
            for (int j = 0; j < 4; j++)
                wmma::load_matrix_sync(bf[j], Bb + (wn*64 + j*16)*H2LD + kk, H2LD);
            #pragma unroll
            for (int i = 0; i < 4; i++)
                #pragma unroll
                for (int j = 0; j < 4; j++)
                    wmma::mma_sync(cf[i][j], af[i], bf[j], cf[i][j]);
        }
        __syncthreads();
    }

    // ---- slab-staged epilogue: per warp, 16x64 f32 stage in reused smem
    float* stage = reinterpret_cast<float*>(smh) + warp*1024;
    #pragma unroll
    for (int i = 0; i < 4; i++) {
        #pragma unroll
        for (int j = 0; j < 4; j++)
            wmma::store_matrix_sync(stage + j*16, cf[i][j], 64, wmma::mem_row_major);
        __syncwarp();

        int mb = m0 + wm*64 + i*16;
        int nb = n0 + wn*64;
        #pragma unroll
        for (int p = 0; p < 4; p++) {
            int linear = p*32 + lane;
            int rr = linear >> 3, c8 = (linear & 7) << 3;
            const float* s = stage + rr*64 + c8;
            float v[8];
            *reinterpret_cast<float4*>(v)     = *reinterpret_cast<const float4*>(s);
            *reinterpret_cast<float4*>(v + 4) = *reinterpret_cast<const float4*>(s + 4);
            size_t base = (size_t)(mb + rr)*N + nb + c8;

            if (MODE == 0) {
                float* dst = (float*)Cout + base;
                *reinterpret_cast<float4*>(dst)     = *reinterpret_cast<float4*>(v);
                *reinterpret_cast<float4*>(dst + 4) = *reinterpret_cast<float4*>(v + 4);
            } else if (MODE == 1) {
                __half2 o[4];
                #pragma unroll
                for (int t = 0; t < 4; t++) o[t] = __floats2half2_rn(v[2*t], v[2*t+1]);
                *reinterpret_cast<float4*>((__half*)Cout + base) = *reinterpret_cast<float4*>(o);
            } else if (MODE == 3) {
                float gb8[8], a8[8], x8[8];
                *reinterpret_cast<float4*>(gb8)     = *reinterpret_cast<const float4*>(bias + nb + c8);
                *reinterpret_cast<float4*>(gb8 + 4) = *reinterpret_cast<const float4*>(bias + nb + c8 + 4);
                *reinterpret_cast<float4*>(a8)      = *reinterpret_cast<const float4*>(aux1 + base);
                *reinterpret_cast<float4*>(a8 + 4)  = *reinterpret_cast<const float4*>(aux1 + base + 4);
                *reinterpret_cast<float4*>(x8)      = *reinterpret_cast<const float4*>(aux2 + base);
                *reinterpret_cast<float4*>(x8 + 4)  = *reinterpret_cast<const float4*>(aux2 + base + 4);
                __half2 o[4];
                #pragma unroll
                for (int t = 0; t < 4; t++) {
                    float g0 = 1.0f / (1.0f + __expf(-(v[2*t]   + gb8[2*t])));
                    float g1 = 1.0f / (1.0f + __expf(-(v[2*t+1] + gb8[2*t+1])));
                    o[t] = __floats2half2_rn(g0*a8[2*t] + x8[2*t], g1*a8[2*t+1] + x8[2*t+1]);
                }
                *reinterpret_cast<float4*>((__half*)Cout + base) = *reinterpret_cast<float4*>(o);
            } else {  // MODE 4
                float b8[8];
                *reinterpret_cast<float4*>(b8)     = *reinterpret_cast<const float4*>(bias + nb + c8);
                *reinterpret_cast<float4*>(b8 + 4) = *reinterpret_cast<const float4*>(bias + nb + c8 + 4);
                #pragma unroll
                for (int e = 0; e < 8; e++) v[e] += b8[e];
                float* dst = (float*)Cout + base;
                *reinterpret_cast<float4*>(dst)     = *reinterpret_cast<float4*>(v);
                *reinterpret_cast<float4*>(dst + 4) = *reinterpret_cast<float4*>(v + 4);
            }
        }
        __syncwarp();
    }
}

// ===========================================================================
// tf32 pipelined GEMM for weight prep: C = A @ B, B=[K,N] row-major
// ===========================================================================
#define STRIDE_S 4608

__device__ void gemm32_body(const float* __restrict__ A, const float* __restrict__ B,
                            float* __restrict__ C, int N, int K,
                            int am0, int n0, int cm0)
{
    extern __shared__ __align__(16) float sm[];
    float* As = sm;
    float* Bs = sm + 4*STRIDE_S;

    const int tid  = threadIdx.x;
    const int warp = tid >> 5;
    const int wm   = warp & 3;
    const int wn   = warp >> 2;
    const int nk   = K >> 5;

    wmma::fragment<wmma::accumulator,16,16,8,float> cf[2][4];
    #pragma unroll
    for (int i = 0; i < 2; i++)
        #pragma unroll
        for (int j = 0; j < 4; j++)
            wmma::fill_fragment(cf[i][j], 0.0f);

    auto load32 = [&](int it, float* Asb, float* Bsb) {
        const float* Ag = A + (size_t)am0*K + it*32;
        const float* Bg = B + (size_t)(it*32)*N + n0;
        uint32_t sA = (uint32_t)__cvta_generic_to_shared(Asb);
        uint32_t sB = (uint32_t)__cvta_generic_to_shared(Bsb);
        #pragma unroll
        for (int i = 0; i < 4; i++) {
            int ch = tid + i*256;
            int r = ch >> 3, c = (ch & 7) << 2;
            cp16(sA + (uint32_t)(r*36 + c)*4u, Ag + (size_t)r*K + c);
            int kk = ch >> 5, c2 = (ch & 31) << 2;
            cp16(sB + (uint32_t)(kk*132 + c2)*4u, Bg + (size_t)kk*N + c2);
        }
    };

    #pragma unroll
    for (int s = 0; s < 3; s++) {
        if (s < nk) load32(s, As + s*STRIDE_S, Bs + s*STRIDE_S);
        asm volatile("cp.async.commit_group;\n" ::: "memory");
    }

    for (int it = 0; it < nk; it++) {
        if (it + 3 < nk) {
            int slot = (it + 3) & 3;
            load32(it + 3, As + slot*STRIDE_S, Bs + slot*STRIDE_S);
        }
        asm volatile("cp.async.commit_group;\n" ::: "memory");
        asm volatile("cp.async.wait_group 3;\n" ::: "memory");
        __syncthreads();

        const float* Ab = As + (it & 3)*STRIDE_S;
        const float* Bb = Bs + (it & 3)*STRIDE_S;
        #pragma unroll
        for (int kk = 0; kk < 32; kk += 8) {
            wmma::fragment<wmma::matrix_a,16,16,8,wmma::precision::tf32,wmma::row_major> af[2];
            wmma::fragment<wmma::matrix_b,16,16,8,wmma::precision::tf32,wmma::row_major> bf[4];
            #pragma unroll
            for (int i = 0; i < 2; i++) {
                wmma::load_matrix_sync(af[i], Ab + (wm*32 + i*16)*36 + kk, 36);
                #pragma unroll
                for (int t = 0; t < af[i].num_elements; t++)
                    af[i].x[t] = wmma::__float_to_tf32(af[i].x[t]);
            }
            #pragma unroll
            for (int j = 0; j < 4; j++) {
                wmma::load_matrix_sync(bf[j], Bb + kk*132 + wn*64 + j*16, 132);
                #pragma unroll
                for (int t = 0; t < bf[j].num_elements; t++)
                    bf[j].x[t] = wmma::__float_to_tf32(bf[j].x[t]);
            }
            #pragma unroll
            for (int i = 0; i < 2; i++)
                #pragma unroll
                for (int j = 0; j < 4; j++)
                    wmma::mma_sync(cf[i][j], af[i], bf[j], cf[i][j]);
        }
        __syncthreads();
    }

    #pragma unroll
    for (int i = 0; i < 2; i++)
        #pragma unroll
        for (int j = 0; j < 4; j++)
            wmma::store_matrix_sync(&C[(size_t)(cm0 + wm*32 + i*16)*N + n0 + wn*64 + j*16],
                                    cf[i][j], N, wmma::mem_row_major);
}

__global__ __launch_bounds__(256)
void wall_prep_kernel(const float* mWq, const float* mWk, const float* mWv,
                      const float* memW1,
                      const float* Wq, const float* Wk, const float* Wv,
                      float* WallS, float* W1qS)
{
    int by = blockIdx.y;
    const float *A, *B; float* Cb; int am0;
    if (by < 8)       { A = mWq;   B = Wq; Cb = WallS;            am0 = by*128; }
    else if (by < 16) { A = mWk;   B = Wk; Cb = WallS + 1048576;  am0 = (by-8)*128; }
    else if (by < 24) { A = mWv;   B = Wv; Cb = WallS + 2097152;  am0 = (by-16)*128; }
    else              { A = memW1; B = Wq; Cb = W1qS;             am0 = 0; }
    gemm32_body(A, B, Cb, 1024, 1024, am0, blockIdx.x*128, am0);
}

__global__ __launch_bounds__(256)
void wkrv_prep_kernel(const float* WallS, const float* mem_oW, float* WkrvS)
{
    int by = blockIdx.y;
    const float* A = (by < 8) ? (WallS + 1048576) : (WallS + 2097152);
    int am0 = (by & 7)*128;
    gemm32_body(A, mem_oW, WkrvS, 128, 1024, am0, 0, by*128);
}

// ===========================================================================
// elementwise / small kernels
// ===========================================================================
__global__ __launch_bounds__(256)
void f2h_kernel(const float* __restrict__ in, __half* __restrict__ out, size_t n)
{
    for (size_t i = ((size_t)blockIdx.x*blockDim.x + threadIdx.x)*4; i < n;
         i += (size_t)gridDim.x*blockDim.x*4) {
        float4 v = *reinterpret_cast<const float4*>(in + i);
        __half2* o = reinterpret_cast<__half2*>(out + i);
        o[0] = __floats2half2_rn(v.x, v.y);
        o[1] = __floats2half2_rn(v.z, v.w);
    }
}

__global__ __launch_bounds__(128)
void ln_mem_kernel(const float* __restrict__ pre, const float* __restrict__ bias,
                   const float* __restrict__ g, const float* __restrict__ b,
                   const float* __restrict__ mstate, __half* __restrict__ out, int do_silu)
{
    int r = blockIdx.x, t = threadIdx.x;
    float v = pre[(size_t)r*128 + t] + bias[t];
    if (do_silu) v = v / (1.0f + __expf(-v));

    float s = v, q = v*v;
    #pragma unroll
    for (int o = 16; o; o >>= 1) {
        s += __shfl_xor_sync(0xffffffffu, s, o);
        q += __shfl_xor_sync(0xffffffffu, q, o);
    }
    __shared__ float red[8];
    if ((t & 31) == 0) { red[t>>5] = s; red[4 + (t>>5)] = q; }
    __syncthreads();
    float S = red[0]+red[1]+red[2]+red[3];
    float Q = red[4]+red[5]+red[6]+red[7];
    float mu  = S * (1.0f/128.0f);
    float var = Q * (1.0f/128.0f) - mu*mu;
    float o = g[t]*(v - mu)*rsqrtf(var + 1e-5f) + b[t];
    if (mstate) o += mstate[t];
    out[(size_t)r*128 + t] = __float2half(o);
}

__global__ __launch_bounds__(256)
void biasln_c_kernel(float* __restrict__ a, const float* __restrict__ bo,
                     const float* __restrict__ g, const float* __restrict__ b,
                     __half* __restrict__ lo)
{
    size_t base = (size_t)blockIdx.x * 1024;
    int t = threadIdx.x;
    float4 v  = *reinterpret_cast<float4*>(a + base + t*4);
    float4 bb = *reinterpret_cast<const float4*>(bo + t*4);
    v.x += bb.x; v.y += bb.y; v.z += bb.z; v.w += bb.w;
    *reinterpret_cast<float4*>(a + base + t*4) = v;

    float s = v.x + v.y + v.z + v.w;
    float q = v.x*v.x + v.y*v.y + v.z*v.z + v.w*v.w;
    #pragma unroll
    for (int o = 16; o; o >>= 1) {
        s += __shfl_xor_sync(0xffffffffu, s, o);
        q += __shfl_xor_sync(0xffffffffu, q, o);
    }
    __shared__ float red[16];
    if ((t & 31) == 0) { red[t>>5] = s; red[8 + (t>>5)] = q; }
    __syncthreads();
    float S = 0.f, Q = 0.f;
    #pragma unroll
    for (int i = 0; i < 8; i++) { S += red[i]; Q += red[8+i]; }
    float mu  = S * (1.0f/1024.0f);
    float var = Q * (1.0f/1024.0f) - mu*mu;
    float rs  = rsqrtf(var + 1e-5f);

    float4 gg = *reinterpret_cast<const float4*>(g + t*4);
    float4 b2 = *reinterpret_cast<const float4*>(b + t*4);
    __half2* o = reinterpret_cast<__half2*>(lo + base + t*4);
    o[0] = __floats2half2_rn(gg.x*(v.x - mu)*rs + b2.x, gg.y*(v.y - mu)*rs + b2.y);
    o[1] = __floats2half2_rn(gg.z*(v.z - mu)*rs + b2.z, gg.w*(v.w - mu)*rs + b2.w);
}

__global__ __launch_bounds__(256)
void fuse_bias_kernel(const float* __restrict__ WkK, const float* __restrict__ WvV,
                      const float* __restrict__ mob,
                      const float* __restrict__ bk, const float* __restrict__ bv,
                      float* __restrict__ bkr, float* __restrict__ bvr)
{
    int i = blockIdx.x & 1023;
    bool isv = blockIdx.x >= 1024;
    const float* W = isv ? WvV : WkK;
    float s = 0.f;
    for (int k = threadIdx.x; k < 1024; k += 256) s += W[(size_t)i*1024 + k] * mob[k];
    #pragma unroll
    for (int o = 16; o; o >>= 1) s += __shfl_xor_sync(0xffffffffu, s, o);
    __shared__ float red[8];
    if ((threadIdx.x & 31) == 0) red[threadIdx.x >> 5] = s;
    __syncthreads();
    if (threadIdx.x == 0) {
        float S = 0.f;
        #pragma unroll
        for (int w = 0; w < 8; w++) S += red[w];
        (isv ? bvr : bkr)[i] = S + (isv ? bv : bk)[i];
    }
}

__global__ __launch_bounds__(256)
void pm_proj_kernel(const float* __restrict__ pm,
                    const float* __restrict__ WkK, const float* __restrict__ WvV,
                    const float* __restrict__ bk, const float* __restrict__ bv,
                    float* __restrict__ kp, float* __restrict__ vp)
{
    int id  = blockIdx.x;
    bool isv = id >= 4096;
    int p = (id & 4095) >> 10;
    int i = id & 1023;
    const float* W = isv ? WvV : WkK;
    float s = 0.f;
    for (int k = threadIdx.x; k < 1024; k += 256) s += pm[p*1024 + k] * W[(size_t)i*1024 + k];
    #pragma unroll
    for (int o = 16; o; o >>= 1) s += __shfl_xor_sync(0xffffffffu, s, o);
    __shared__ float red[8];
    if ((threadIdx.x & 31) == 0) red[threadIdx.x >> 5] = s;
    __syncthreads();
    if (threadIdx.x == 0) {
        float S = 0.f;
        #pragma unroll
        for (int w = 0; w < 8; w++) S += red[w];
        (isv ? vp : kp)[p*1024 + i] = S + (isv ? bv : bk)[i];
    }
}

// ===========================================================================
// fp16 attention: block per (segment, head); 8 warps; half in, half out
// ===========================================================================
#define PS_LD 148
#define QK_LD 136
#define PH_LD 152
#define ATTN_SMEM (64*PS_LD*4 + (64*QK_LD + 144*QK_LD + 144*QK_LD + 64*PH_LD)*2)

__global__ __launch_bounds__(256)
void attn_kernel(const __half* __restrict__ qkv,
                 const __half* __restrict__ kvr,
                 const float* __restrict__ kp, const float* __restrict__ vp,
                 const float* __restrict__ bq, const float* __restrict__ bk,
                 const float* __restrict__ bkr,
                 const float* __restrict__ bv, const float* __restrict__ bvr,
                 __half* __restrict__ outh)
{
    extern __shared__ __align__(16) float sm[];
    float*  ps  = sm;
    __half* qsh = reinterpret_cast<__half*>(sm + 64*PS_LD);
    __half* ksh = qsh + 64*QK_LD;
    __half* vsh = ksh + 144*QK_LD;
    __half* ph  = vsh + 144*QK_LD;

    const int seg  = blockIdx.x;
    const int h    = blockIdx.y;
    const int tid  = threadIdx.x;
    const int warp = tid >> 5;
    const int lane = tid & 31;
    const int c0   = h * 128;
    const float scale = 0.08838834764831845f;

    for (int i = tid; i < 64*16; i += 256) {
        int r = i >> 4, c8 = (i & 15) << 3;
        float4 raw = *reinterpret_cast<const float4*>(qkv + (size_t)(seg*64 + r)*3072 + c0 + c8);
        const __half2* hp = reinterpret_cast<const __half2*>(&raw);
        float bv8[8];
        *reinterpret_cast<float4*>(bv8)     = *reinterpret_cast<const float4*>(bq + c0 + c8);
        *reinterpret_cast<float4*>(bv8 + 4) = *reinterpret_cast<const float4*>(bq + c0 + c8 + 4);
        __half2 o[4];
        #pragma unroll
        for (int t = 0; t < 4; t++) {
            float2 f = __half22float2(hp[t]);
            o[t] = __floats2half2_rn((f.x + bv8[2*t])*scale, (f.y + bv8[2*t+1])*scale);
        }
        *reinterpret_cast<float4*>(qsh + r*QK_LD + c8) = *reinterpret_cast<float4*>(o);
    }
    for (int i = tid; i < 144*16; i += 256) {
        int r = i >> 4, c8 = (i & 15) << 3;
        float vals[8] = {0,0,0,0,0,0,0,0};
        if (r < 64) {
            float4 raw = *reinterpret_cast<const float4*>(kvr + (size_t)(seg*64 + r)*2048 + c0 + c8);
            const __half2* hp = reinterpret_cast<const __half2*>(&raw);
            float b8[8];
            *reinterpret_cast<float4*>(b8)     = *reinterpret_cast<const float4*>(bkr + c0 + c8);
            *reinterpret_cast<float4*>(b8 + 4) = *reinterpret_cast<const float4*>(bkr + c0 + c8 + 4);
            #pragma unroll
            for (int t = 0; t < 4; t++) {
                float2 f = __half22float2(hp[t]);
                vals[2*t] = f.x + b8[2*t]; vals[2*t+1] = f.y + b8[2*t+1];
            }
        } else if (r < 68) {
            *reinterpret_cast<float4*>(vals)     = *reinterpret_cast<const float4*>(kp + (size_t)(r-64)*1024 + c0 + c8);
            *reinterpret_cast<float4*>(vals + 4) = *reinterpret_cast<const float4*>(kp + (size_t)(r-64)*1024 + c0 + c8 + 4);
        } else if (r < 132) {
            float4 raw = *reinterpret_cast<const float4*>(qkv + (size_t)(seg*64 + r - 68)*3072 + 1024 + c0 + c8);
            const __half2* hp = reinterpret_cast<const __half2*>(&raw);
            float b8[8];
            *reinterpret_cast<float4*>(b8)     = *reinterpret_cast<const float4*>(bk + c0 + c8);
            *reinterpret_cast<float4*>(b8 + 4) = *reinterpret_cast<const float4*>(bk + c0 + c8 + 4);
            #pragma unroll
            for (int t = 0; t < 4; t++) {
                float2 f = __half22float2(hp[t]);
                vals[2*t] = f.x + b8[2*t]; vals[2*t+1] = f.y + b8[2*t+1];
            }
        }
        __half2 o[4];
        #pragma unroll
        for (int t = 0; t < 4; t++) o[t] = __floats2half2_rn(vals[2*t], vals[2*t+1]);
        *reinterpret_cast<float4*>(ksh + r*QK_LD + c8) = *reinterpret_cast<float4*>(o);
    }
    for (int i = tid; i < 144*16; i += 256) {
        int r = i >> 4, c8 = (i & 15) << 3;
        float vals[8] = {0,0,0,0,0,0,0,0};
        if (r < 64) {
            float4 raw = *reinterpret_cast<const float4*>(kvr + (size_t)(seg*64 + r)*2048 + 1024 + c0 + c8);
            const __half2* hp = reinterpret_cast<const __half2*>(&raw);
            float b8[8];
            *reinterpret_cast<float4*>(b8)     = *reinterpret_cast<const float4*>(bvr + c0 + c8);
            *reinterpret_cast<float4*>(b8 + 4) = *reinterpret_cast<const float4*>(bvr + c0 + c8 + 4);
            #pragma unroll
            for (int t = 0; t < 4; t++) {
                float2 f = __half22float2(hp[t]);
                vals[2*t] = f.x + b8[2*t]; vals[2*t+1] = f.y + b8[2*t+1];
            }
        } else if (r < 68) {
            *reinterpret_cast<float4*>(vals)     = *reinterpret_cast<const float4*>(vp + (size_t)(r-64)*1024 + c0 + c8);
            *reinterpret_cast<float4*>(vals + 4) = *reinterpret_cast<const float4*>(vp + (size_t)(r-64)*1024 + c0 + c8 + 4);
        } else if (r < 132) {
            float4 raw = *reinterpret_cast<const float4*>(qkv + (size_t)(seg*64 + r - 68)*3072 + 2048 + c0 + c8);
            const __half2* hp = reinterpret_cast<const __half2*>(&raw);
            float b8[8];
            *reinterpret_cast<float4*>(b8)     = *reinterpret_cast<const float4*>(bv + c0 + c8);
            *reinterpret_cast<float4*>(b8 + 4) = *reinterpret_cast<const float4*>(bv + c0 + c8 + 4);
            #pragma unroll
            for (int t = 0; t < 4; t++) {
                float2 f = __half22float2(hp[t]);
                vals[2*t] = f.x + b8[2*t]; vals[2*t+1] = f.y + b8[2*t+1];
            }
        }
        __half2 o[4];
        #pragma unroll
        for (int t = 0; t < 4; t++) o[t] = __floats2half2_rn(vals[2*t], vals[2*t+1]);
        *reinterpret_cast<float4*>(vsh + r*QK_LD + c8) = *reinterpret_cast<float4*>(o);
    }
    __syncthreads();

    for (int t = warp; t < 36; t += 8) {
        int ms = (t / 9) * 16;
        int ns = (t % 9) * 16;
        wmma::fragment<wmma::accumulator,16,16,16,float> acc;
        wmma::fill_fragment(acc, 0.0f);
        #pragma unroll
        for (int kk = 0; kk < 128; kk += 16) {
            wmma::fragment<wmma::matrix_a,16,16,16,__half,wmma::row_major> af;
            wmma::fragment<wmma::matrix_b,16,16,16,__half,wmma::col_major> bf;
            wmma::load_matrix_sync(af, qsh + ms*QK_LD + kk, QK_LD);
            wmma::load_matrix_sync(bf, ksh + ns*QK_LD + kk, QK_LD);
            wmma::mma_sync(acc, af, bf, acc);
        }
        wmma::store_matrix_sync(ps + ms*PS_LD + ns, acc, PS_LD, wmma::mem_row_major);
    }
    __syncthreads();

    for (int r = warp*8; r < warp*8 + 8; r++) {
        float* row = ps + r*PS_LD;
        float m = -1e30f;
        for (int c = lane; c < 132; c += 32) m = fmaxf(m, row[c]);
        #pragma unroll
        for (int o = 16; o; o >>= 1) m = fmaxf(m, __shfl_xor_sync(0xffffffffu, m, o));
        float s = 0.f;
        for (int c = lane; c < 132; c += 32) { float e = __expf(row[c] - m); row[c] = e; s += e; }
        #pragma unroll
        for (int o = 16; o; o >>= 1) s += __shfl_xor_sync(0xffffffffu, s, o);
        float inv = 1.0f / s;
        for (int c = lane; c < 132; c += 32) ph[r*PH_LD + c] = __float2half(row[c]*inv);
        if (lane < 20) ph[r*PH_LD + 132 + lane] = __float2half(0.0f);
    }
    __syncthreads();

    for (int t = warp; t < 32; t += 8) {
        int ms = (t >> 3) * 16;
        int ds = (t & 7) * 16;
        wmma::fragment<wmma::accumulator,16,16,16,float> acc;
        wmma::fill_fragment(acc, 0.0f);
        #pragma unroll
        for (int kk = 0; kk < 144; kk += 16) {
            wmma::fragment<wmma::matrix_a,16,16,16,__half,wmma::row_major> af;
            wmma::fragment<wmma::matrix_b,16,16,16,__half,wmma::row_major> bf;
            wmma::load_matrix_sync(af, ph + ms*PH_LD + kk, PH_LD);
            wmma::load_matrix_sync(bf, vsh + kk*QK_LD + ds, QK_LD);
            wmma::mma_sync(acc, af, bf, acc);
        }
        wmma::store_matrix_sync(ps + ms*PS_LD + ds, acc, PS_LD, wmma::mem_row_major);
    }
    __syncthreads();

    for (int i = tid; i < 64*16; i += 256) {
        int r = i >> 4, c8 = (i & 15) << 3;
        const float* src = ps + r*PS_LD + c8;
        __half2 o[4];
        #pragma unroll
        for (int t = 0; t < 4; t++) o[t] = __floats2half2_rn(src[2*t], src[2*t+1]);
        *reinterpret_cast<float4*>(outh + (size_t)(seg*64 + r)*1024 + c0 + c8) =
            *reinterpret_cast<float4*>(o);
    }
}

// ===========================================================================
extern "C" void kernel_launch(void* const* d_in, const int* in_sizes, int n_in,
                              void* d_out, int out_size)
{
    const float* x      = (const float*)d_in[0];
    const float* pm     = (const float*)d_in[1];
    const float* Wq     = (const float*)d_in[2];
    const float* Wk     = (const float*)d_in[3];
    const float* Wv     = (const float*)d_in[4];
    const float* mem_W1 = (const float*)d_in[5];
    const float* mem_b1 = (const float*)d_in[6];
    const float* ln1_g  = (const float*)d_in[7];
    const float* ln1_b  = (const float*)d_in[8];
    const float* mem_W2 = (const float*)d_in[9];
    const float* mem_b2 = (const float*)d_in[10];
    const float* ln2_g  = (const float*)d_in[11];
    const float* ln2_b  = (const float*)d_in[12];
    const float* mem_oW = (const float*)d_in[13];
    const float* mem_ob = (const float*)d_in[14];
    const float* mstate = (const float*)d_in[15];
    const float* mha_Wq = (const float*)d_in[16];
    const float* mha_bq = (const float*)d_in[17];
    const float* mha_Wk = (const float*)d_in[18];
    const float* mha_bk = (const float*)d_in[19];
    const float* mha_Wv = (const float*)d_in[20];
    const float* mha_bv = (const float*)d_in[21];
    const float* mha_Wo = (const float*)d_in[22];
    const float* mha_bo = (const float*)d_in[23];
    const float* gn_g   = (const float*)d_in[24];
    const float* gn_b   = (const float*)d_in[25];
    const float* gate_W = (const float*)d_in[26];
    const float* gate_b = (const float*)d_in[27];
    const float* out_W  = (const float*)d_in[28];
    const float* out_b  = (const float*)d_in[29];
    float* out = (float*)d_out;

    void* sp; cudaGetSymbolAddress(&sp, d_scratch);
    float* S0 = (float*)sp;
    float* m1    = S0;
    float* A4    = m1    + 2097152ull;
    float* WallS = A4    + 16777216ull;
    float* WkrvS = WallS + 3145728ull;
    float* W1qS  = WkrvS + 262144ull;
    __half* xh    = (__half*)(W1qS + 131072ull);
    __half* qkvh  = xh    + 16777216ull;
    __half* kvrh  = qkvh  + 50331648ull;
    __half* A3h   = kvrh  + 33554432ull;
    __half* A5h   = A3h   + 16777216ull;
    __half* uh    = A5h   + 16777216ull;
    __half* m2ah  = uh    + 16777216ull;
    __half* m2h   = m2ah  + 2097152ull;
    __half* Wallh = m2h   + 2097152ull;
    __half* Wkrvh = Wallh + 3145728ull;
    __half* W1qh  = Wkrvh + 262144ull;
    __half* W2h   = W1qh  + 131072ull;
    __half* Woh   = W2h   + 16384ull;
    __half* gateh = Woh   + 1048576ull;
    __half* outh  = gateh + 1048576ull;
    float* kp  = (float*)(outh + 1048576ull);
    float* vp  = kp + 4096;
    float* bkr = vp + 4096;
    float* bvr = bkr + 1024;
    float* WkK = WallS + 1048576ull;
    float* WvV = WallS + 2097152ull;

    cudaFuncSetAttribute(gemm_h_kernel,      cudaFuncAttributeMaxDynamicSharedMemorySize, GSM);
    cudaFuncSetAttribute(gemm_h2_kernel<0>,  cudaFuncAttributeMaxDynamicSharedMemorySize, GSM2);
    cudaFuncSetAttribute(gemm_h2_kernel<1>,  cudaFuncAttributeMaxDynamicSharedMemorySize, GSM2);
    cudaFuncSetAttribute(gemm_h2_kernel<3>,  cudaFuncAttributeMaxDynamicSharedMemorySize, GSM2);
    cudaFuncSetAttribute(gemm_h2_kernel<4>,  cudaFuncAttributeMaxDynamicSharedMemorySize, GSM2);
    cudaFuncSetAttribute(wall_prep_kernel,   cudaFuncAttributeMaxDynamicSharedMemorySize, GSM);
    cudaFuncSetAttribute(wkrv_prep_kernel,   cudaFuncAttributeMaxDynamicSharedMemorySize, GSM);
    cudaFuncSetAttribute(attn_kernel,        cudaFuncAttributeMaxDynamicSharedMemorySize, ATTN_SMEM);

    dim3 blk(256);

    // ---- converts
    f2h_kernel<<<4096, 256>>>(x, xh, 16777216ull);
    f2h_kernel<<<512,  256>>>(mem_W2, W2h, 16384ull);
    f2h_kernel<<<2048, 256>>>(mha_Wo, Woh, 1048576ull);
    f2h_kernel<<<2048, 256>>>(gate_W, gateh, 1048576ull);
    f2h_kernel<<<2048, 256>>>(out_W, outh, 1048576ull);

    // ---- weight prep (tf32) + half conversion
    wall_prep_kernel<<<dim3(8,25), blk, GSM>>>(mha_Wq, mha_Wk, mha_Wv, mem_W1,
                                               Wq, Wk, Wv, WallS, W1qS);
    wkrv_prep_kernel<<<dim3(1,16), blk, GSM>>>(WallS, mem_oW, WkrvS);
    f2h_kernel<<<4096, 256>>>(WallS, Wallh, 3538944ull);
    fuse_bias_kernel<<<2048, 256>>>(WkK, WvV, mem_ob, mha_bk, mha_bv, bkr, bvr);
    pm_proj_kernel<<<8192, 256>>>(pm, WkK, WvV, mha_bk, mha_bv, kp, vp);

    // ---- memory net
    gemm_h_kernel<<<dim3(1,128), blk, GSM>>>(xh, W1qh, m1, 16384, 128, 1024);
    ln_mem_kernel<<<16384, 128>>>(m1, mem_b1, ln1_g, ln1_b, nullptr, m2ah, 1);
    gemm_h_kernel<<<dim3(1,128), blk, GSM>>>(m2ah, W2h, m1, 16384, 128, 128);
    ln_mem_kernel<<<16384, 128>>>(m1, mem_b2, ln2_g, ln2_b, mstate, m2h, 0);

    // ---- fused q|k|v + retrieved k|v (half outputs)
    gemm_h2_kernel<1><<<dim3(24,64), blk, GSM2>>>(xh,  Wallh, qkvh, nullptr, nullptr, nullptr, 16384, 3072, 1024);
    gemm_h2_kernel<1><<<dim3(16,64), blk, GSM2>>>(m2h, Wkrvh, kvrh, nullptr, nullptr, nullptr, 16384, 2048, 128);

    // ---- attention (half out)
    attn_kernel<<<dim3(256, 8), 256, ATTN_SMEM>>>(qkvh, kvrh, kp, vp,
                                                  mha_bq, mha_bk, bkr, mha_bv, bvr, A3h);

    // ---- output path
    gemm_h2_kernel<0><<<dim3(8,64), blk, GSM2>>>(A3h, Woh, A4, nullptr, nullptr, nullptr, 16384, 1024, 1024);
    biasln_c_kernel<<<16384, 256>>>(A4, mha_bo, gn_g, gn_b, A5h);
    // gate GEMM with fused sigmoid-blend epilogue: uh = sigmoid(acc+gate_b)*A4 + x
    gemm_h2_kernel<3><<<dim3(8,64), blk, GSM2>>>(A5h, gateh, uh, gate_b, A4, x, 16384, 1024, 1024);
    // final projection with fused out_b
    gemm_h2_kernel<4><<<dim3(8,64), blk, GSM2>>>(uh, outh, out, out_b, nullptr, nullptr, 16384, 1024, 1024);
}

// round 9
// speedup vs baseline: 1.0309x; 1.0309x over previous
#include <cuda_runtime.h>
#include <cuda_fp16.h>
#include <mma.h>
#include <cstdint>

using namespace nvcuda;

// B=4, L=4096, C=1024, M=128, P=4, S=64, H=8, hd=128
// NSEG=256, TOKS=16384, context T=132

__device__ float d_scratch[162100000ull];

__device__ __forceinline__ void cp16(uint32_t s, const void* g) {
    asm volatile("cp.async.cg.shared.global [%0], [%1], 16;\n" :: "r"(s), "l"(g) : "memory");
}

// ===========================================================================
// batched f32 -> f16 convert (13 tensors in one launch)
// ===========================================================================
struct ConvBatch {
    const float* src[13];
    __half*      dst[13];
    unsigned     n[13];
};

__global__ __launch_bounds__(256)
void conv_batch_kernel(ConvBatch cb)
{
    int t = blockIdx.y;
    size_t n = cb.n[t];
    const float* in = cb.src[t];
    __half* out = cb.dst[t];
    for (size_t i = ((size_t)blockIdx.x*256 + threadIdx.x)*4; i < n;
         i += (size_t)gridDim.x*256*4) {
        float4 v = *reinterpret_cast<const float4*>(in + i);
        __half2 o2[2];
        o2[0] = __floats2half2_rn(v.x, v.y);
        o2[1] = __floats2half2_rn(v.z, v.w);
        *reinterpret_cast<float2*>(out + i) = *reinterpret_cast<float2*>(o2);
    }
}

// ===========================================================================
// fp16 NT GEMM for weight prep: C(half)[.,N] = A[M,K](h, K-major) @ B[K,N](h, row-major)
// 128x128 tile, Ktile 64, 4 stages. smem = 4*(9216 + 8704) halves = 143360 B
// ===========================================================================
#define NT_AS 9216
#define NT_BS 8704
#define GSM_NT (4*(NT_AS + NT_BS)*2)

__device__ void gemm_nt_h_body(const __half* __restrict__ A, const __half* __restrict__ B,
                               __half* __restrict__ C, int N, int K,
                               int am0, int n0, int cm0)
{
    extern __shared__ __align__(16) __half smh[];
    __half* As = smh;             // 4 * 9216  (128 x 72)
    __half* Bs = smh + 4*NT_AS;   // 4 * 8704  (64 x 136)

    const int tid  = threadIdx.x;
    const int warp = tid >> 5;
    const int lane = tid & 31;
    const int wm   = warp & 3;
    const int wn   = warp >> 2;
    const int nk   = K >> 6;

    auto load = [&](int it, int s) {
        const __half* Ag = A + (size_t)am0*K + it*64;
        const __half* Bg = B + (size_t)(it*64)*N + n0;
        uint32_t sA = (uint32_t)__cvta_generic_to_shared(As + s*NT_AS);
        uint32_t sB = (uint32_t)__cvta_generic_to_shared(Bs + s*NT_BS);
        #pragma unroll
        for (int i = 0; i < 4; i++) {
            int ch = tid + i*256;
            int r = ch >> 3, c = (ch & 7) << 3;
            cp16(sA + (uint32_t)(r*72 + c)*2u, Ag + (size_t)r*K + c);
            int kk = ch >> 4, c2 = (ch & 15) << 3;
            cp16(sB + (uint32_t)(kk*136 + c2)*2u, Bg + (size_t)kk*N + c2);
        }
    };

    wmma::fragment<wmma::accumulator,16,16,16,float> cf[2][4];
    #pragma unroll
    for (int i = 0; i < 2; i++)
        #pragma unroll
        for (int j = 0; j < 4; j++)
            wmma::fill_fragment(cf[i][j], 0.0f);

    #pragma unroll
    for (int s = 0; s < 3; s++) {
        if (s < nk) load(s, s);
        asm volatile("cp.async.commit_group;\n" ::: "memory");
    }

    for (int it = 0; it < nk; it++) {
        if (it + 3 < nk) load(it + 3, (it + 3) & 3);
        asm volatile("cp.async.commit_group;\n" ::: "memory");
        asm volatile("cp.async.wait_group 3;\n" ::: "memory");
        __syncthreads();

        const __half* Ab = As + (it & 3)*NT_AS;
        const __half* Bb = Bs + (it & 3)*NT_BS;
        #pragma unroll
        for (int kk = 0; kk < 64; kk += 16) {
            wmma::fragment<wmma::matrix_a,16,16,16,__half,wmma::row_major> af[2];
            wmma::fragment<wmma::matrix_b,16,16,16,__half,wmma::row_major> bf[4];
            #pragma unroll
            for (int i = 0; i < 2; i++)
                wmma::load_matrix_sync(af[i], Ab + (wm*32 + i*16)*72 + kk, 72);
            #pragma unroll
            for (int j = 0; j < 4; j++)
                wmma::load_matrix_sync(bf[j], Bb + kk*136 + wn*64 + j*16, 136);
            #pragma unroll
            for (int i = 0; i < 2; i++)
                #pragma unroll
                for (int j = 0; j < 4; j++)
                    wmma::mma_sync(cf[i][j], af[i], bf[j], cf[i][j]);
        }
        __syncthreads();
    }

    // jagged staged epilogue -> half
    float* stage = reinterpret_cast<float*>(smh) + warp*256;
    #pragma unroll
    for (int i = 0; i < 2; i++)
        #pragma unroll
        for (int j = 0; j < 4; j++) {
            wmma::store_matrix_sync(stage, cf[i][j], 16, wmma::mem_row_major);
            __syncwarp();
            int mb = cm0 + wm*32 + i*16;
            int nb = n0 + wn*64 + j*16;
            #pragma unroll
            for (int e = lane; e < 256; e += 32) {
                int rr = e >> 4, cc = e & 15;
                C[(size_t)(mb + rr)*N + nb + cc] = __float2half(stage[e]);
            }
            __syncwarp();
        }
}

__global__ __launch_bounds__(256)
void wall_prep_h_kernel(const __half* mWq, const __half* mWk, const __half* mWv,
                        const __half* memW1,
                        const __half* Wq, const __half* Wk, const __half* Wv,
                        __half* Wallh, __half* W1qh)
{
    int by = blockIdx.y;
    const __half *A, *B; __half* Cb; int am0;
    if (by < 8)       { A = mWq;   B = Wq; Cb = Wallh;            am0 = by*128; }
    else if (by < 16) { A = mWk;   B = Wk; Cb = Wallh + 1048576;  am0 = (by-8)*128; }
    else if (by < 24) { A = mWv;   B = Wv; Cb = Wallh + 2097152;  am0 = (by-16)*128; }
    else              { A = memW1; B = Wq; Cb = W1qh;             am0 = 0; }
    gemm_nt_h_body(A, B, Cb, 1024, 1024, am0, blockIdx.x*128, am0);
}

__global__ __launch_bounds__(256)
void wkrv_prep_h_kernel(const __half* Wallh, const __half* moW, __half* Wkrvh)
{
    int by = blockIdx.y;
    const __half* A = (by < 8) ? (Wallh + 1048576) : (Wallh + 2097152);
    int am0 = (by & 7)*128;
    gemm_nt_h_body(A, moW, Wkrvh, 128, 1024, am0, 0, by*128);
}

// ===========================================================================
// memory-net fused GEMM + bias (+silu) + LayerNorm (+mstate): N=128
// grid (1,128). smem: mainloop 4*(9216+9216) halves = 147456 B; epilogue
// reuses it as f32 tile [128][132].
// ===========================================================================
#define HLD 72
#define HSTS 9216
#define GSM 147456

__device__ __forceinline__ void load_tile_h(const __half* Ag0, const __half* Wg0,
                                            int K, int it, __half* As, __half* Bs, int tid)
{
    const __half* Ag = Ag0 + it*64;
    const __half* Wg = Wg0 + it*64;
    uint32_t sA = (uint32_t)__cvta_generic_to_shared(As);
    uint32_t sB = (uint32_t)__cvta_generic_to_shared(Bs);
    #pragma unroll
    for (int i = 0; i < 4; i++) {
        int ch = tid + i*256;
        int r = ch >> 3, c = (ch & 7) << 3;
        cp16(sA + (uint32_t)(r*HLD + c)*2u, Ag + (size_t)r*K + c);
        cp16(sB + (uint32_t)(r*HLD + c)*2u, Wg + (size_t)r*K + c);
    }
}

template<int DO_SILU, int ADD_MSTATE>
__global__ __launch_bounds__(256)
void memnet_kernel(const __half* __restrict__ A, const __half* __restrict__ W,
                   const float* __restrict__ bias,
                   const float* __restrict__ g, const float* __restrict__ b,
                   const float* __restrict__ mstate,
                   __half* __restrict__ out, int K)
{
    extern __shared__ __align__(16) __half smh[];
    __half* As = smh;
    __half* Bs = smh + 4*HSTS;

    const int tid  = threadIdx.x;
    const int warp = tid >> 5;
    const int lane = tid & 31;
    const int wm   = warp & 3;
    const int wn   = warp >> 2;
    const int m0   = blockIdx.y * 128;
    const int nk   = K >> 6;

    const __half* Ag0 = A + (size_t)m0*K;

    wmma::fragment<wmma::accumulator,16,16,16,float> cf[2][4];
    #pragma unroll
    for (int i = 0; i < 2; i++)
        #pragma unroll
        for (int j = 0; j < 4; j++)
            wmma::fill_fragment(cf[i][j], 0.0f);

    #pragma unroll
    for (int s = 0; s < 3; s++) {
        if (s < nk) load_tile_h(Ag0, W, K, s, As + s*HSTS, Bs + s*HSTS, tid);
        asm volatile("cp.async.commit_group;\n" ::: "memory");
    }

    for (int it = 0; it < nk; it++) {
        if (it + 3 < nk) {
            int slot = (it + 3) & 3;
            load_tile_h(Ag0, W, K, it + 3, As + slot*HSTS, Bs + slot*HSTS, tid);
        }
        asm volatile("cp.async.commit_group;\n" ::: "memory");
        asm volatile("cp.async.wait_group 3;\n" ::: "memory");
        __syncthreads();

        const __half* Ab = As + (it & 3)*HSTS;
        const __half* Bb = Bs + (it & 3)*HSTS;
        #pragma unroll
        for (int kk = 0; kk < 64; kk += 16) {
            wmma::fragment<wmma::matrix_a,16,16,16,__half,wmma::row_major> af[2];
            wmma::fragment<wmma::matrix_b,16,16,16,__half,wmma::col_major> bf[4];
            #pragma unroll
            for (int i = 0; i < 2; i++)
                wmma::load_matrix_sync(af[i], Ab + (wm*32 + i*16)*HLD + kk, HLD);
            #pragma unroll
            for (int j = 0; j < 4; j++)
                wmma::load_matrix_sync(bf[j], Bb + (wn*64 + j*16)*HLD + kk, HLD);
            #pragma unroll
            for (int i = 0; i < 2; i++)
                #pragma unroll
                for (int j = 0; j < 4; j++)
                    wmma::mma_sync(cf[i][j], af[i], bf[j], cf[i][j]);
        }
        __syncthreads();
    }

    // fused epilogue: f32 tile in smem, then per-row bias(+silu)+LN(+mstate)
    float* tile = reinterpret_cast<float*>(smh);
    #pragma unroll
    for (int i = 0; i < 2; i++)
        #pragma unroll
        for (int j = 0; j < 4; j++)
            wmma::store_matrix_sync(tile + (wm*32 + i*16)*132 + wn*64 + j*16,
                                    cf[i][j], 132, wmma::mem_row_major);
    __syncthreads();

    float bb4[4], gg4[4], b24[4], ms4[4];
    *reinterpret_cast<float4*>(bb4) = *reinterpret_cast<const float4*>(bias + lane*4);
    *reinterpret_cast<float4*>(gg4) = *reinterpret_cast<const float4*>(g + lane*4);
    *reinterpret_cast<float4*>(b24) = *reinterpret_cast<const float4*>(b + lane*4);
    if (ADD_MSTATE)
        *reinterpret_cast<float4*>(ms4) = *reinterpret_cast<const float4*>(mstate + lane*4);

    #pragma unroll
    for (int rr = 0; rr < 16; rr++) {
        int row = warp*16 + rr;
        float4 v4 = *reinterpret_cast<const float4*>(tile + row*132 + lane*4);
        float t[4] = {v4.x + bb4[0], v4.y + bb4[1], v4.z + bb4[2], v4.w + bb4[3]};
        if (DO_SILU) {
            #pragma unroll
            for (int e = 0; e < 4; e++) t[e] = t[e] / (1.0f + __expf(-t[e]));
        }
        float s = t[0]+t[1]+t[2]+t[3];
        float q = t[0]*t[0]+t[1]*t[1]+t[2]*t[2]+t[3]*t[3];
        #pragma unroll
        for (int o = 16; o; o >>= 1) {
            s += __shfl_xor_sync(0xffffffffu, s, o);
            q += __shfl_xor_sync(0xffffffffu, q, o);
        }
        float mu  = s * (1.0f/128.0f);
        float var = q * (1.0f/128.0f) - mu*mu;
        float rs  = rsqrtf(var + 1e-5f);
        __half2 o2[2];
        float o0 = gg4[0]*(t[0]-mu)*rs + b24[0];
        float o1 = gg4[1]*(t[1]-mu)*rs + b24[1];
        float o2f = gg4[2]*(t[2]-mu)*rs + b24[2];
        float o3 = gg4[3]*(t[3]-mu)*rs + b24[3];
        if (ADD_MSTATE) { o0 += ms4[0]; o1 += ms4[1]; o2f += ms4[2]; o3 += ms4[3]; }
        o2[0] = __floats2half2_rn(o0, o1);
        o2[1] = __floats2half2_rn(o2f, o3);
        *reinterpret_cast<float2*>(out + (size_t)(m0 + row)*128 + lane*4) =
            *reinterpret_cast<float2*>(o2);
    }
}

// ===========================================================================
// fp16 wmma GEMM main path (R6 code): 256x128 CTA tile, 64x64 warp tile,
// Ktile 32, 4 stages.
// MODE 0: f32 direct store. MODE 1: half out (jagged stage).
// MODE 3: gate fusion  u = sigmoid(acc+bias)*aux1 + aux2 -> half (jagged)
// MODE 4: f32 + bias (jagged)
// ===========================================================================
#define H2LD 40
#define H2_AS 10240
#define H2_BS 5120
#define GSM2 ((4*(H2_AS + H2_BS))*2)

__device__ __forceinline__ void load_tile_h2(const __half* Ag0, const __half* Wg0,
                                             int K, int it, __half* As, __half* Bs, int tid)
{
    const __half* Ag = Ag0 + it*32;
    const __half* Wg = Wg0 + it*32;
    uint32_t sA = (uint32_t)__cvta_generic_to_shared(As);
    uint32_t sB = (uint32_t)__cvta_generic_to_shared(Bs);
    #pragma unroll
    for (int i = 0; i < 4; i++) {
        int ch = tid + i*256;
        int r = ch >> 2, c = (ch & 3) << 3;
        cp16(sA + (uint32_t)(r*H2LD + c)*2u, Ag + (size_t)r*K + c);
    }
    #pragma unroll
    for (int i = 0; i < 2; i++) {
        int ch = tid + i*256;
        int r = ch >> 2, c = (ch & 3) << 3;
        cp16(sB + (uint32_t)(r*H2LD + c)*2u, Wg + (size_t)r*K + c);
    }
}

template<int MODE>
__global__ __launch_bounds__(256)
void gemm_h2_kernel(const __half* __restrict__ A, const __half* __restrict__ W,
                    void* __restrict__ Cout, const float* __restrict__ bias,
                    const float* __restrict__ aux1, const float* __restrict__ aux2,
                    int M, int N, int K)
{
    extern __shared__ __align__(16) __half smh[];
    __half* As = smh;
    __half* Bs = smh + 4*H2_AS;

    const int tid  = threadIdx.x;
    const int warp = tid >> 5;
    const int lane = tid & 31;
    const int wm   = warp & 3;
    const int wn   = warp >> 2;
    const int m0   = blockIdx.y * 256;
    const int n0   = blockIdx.x * 128;
    const int nk   = K >> 5;

    const __half* Ag0 = A + (size_t)m0*K;
    const __half* Wg0 = W + (size_t)n0*K;

    wmma::fragment<wmma::accumulator,16,16,16,float> cf[4][4];
    #pragma unroll
    for (int i = 0; i < 4; i++)
        #pragma unroll
        for (int j = 0; j < 4; j++)
            wmma::fill_fragment(cf[i][j], 0.0f);

    #pragma unroll
    for (int s = 0; s < 3; s++) {
        if (s < nk) load_tile_h2(Ag0, Wg0, K, s, As + s*H2_AS, Bs + s*H2_BS, tid);
        asm volatile("cp.async.commit_group;\n" ::: "memory");
    }

    for (int it = 0; it < nk; it++) {
        if (it + 3 < nk) {
            int slot = (it + 3) & 3;
            load_tile_h2(Ag0, Wg0, K, it + 3, As + slot*H2_AS, Bs + slot*H2_BS, tid);
        }
        asm volatile("cp.async.commit_group;\n" ::: "memory");
        asm volatile("cp.async.wait_group 3;\n" ::: "memory");
        __syncthreads();

        const __half* Ab = As + (it & 3)*H2_AS;
        const __half* Bb = Bs + (it & 3)*H2_BS;
        #pragma unroll
        for (int kk = 0; kk < 32; kk += 16) {
            wmma::fragment<wmma::matrix_a,16,16,16,__half,wmma::row_major> af[4];
            wmma::fragment<wmma::matrix_b,16,16,16,__half,wmma::col_major> bf[4];
            #pragma unroll
            for (int i = 0; i < 4; i++)
                wmma::load_matrix_sync(af[i], Ab + (wm*64 + i*16)*H2LD + kk, H2LD);
            #pragma unroll
            for (int j = 0; j < 4; j++)
                wmma::load_matrix_sync(bf[j], Bb + (wn*64 + j*16)*H2LD + kk, H2LD);
            #pragma unroll
            for (int i = 0; i < 4; i++)
                #pragma unroll
                for (int j = 0; j < 4; j++)
                    wmma::mma_sync(cf[i][j], af[i], bf[j], cf[i][j]);
        }
        __syncthreads();
    }

    if (MODE == 0) {
        float* Cf = (float*)Cout;
        #pragma unroll
        for (int i = 0; i < 4; i++)
            #pragma unroll
            for (int j = 0; j < 4; j++)
                wmma::store_matrix_sync(&Cf[(size_t)(m0 + wm*64 + i*16)*N + n0 + wn*64 + j*16],
                                        cf[i][j], N, wmma::mem_row_major);
    } else {
        float* stage = reinterpret_cast<float*>(smh) + warp*256;   // 16x16 f32 per warp
        #pragma unroll
        for (int i = 0; i < 4; i++)
            #pragma unroll
            for (int j = 0; j < 4; j++) {
                wmma::store_matrix_sync(stage, cf[i][j], 16, wmma::mem_row_major);
                __syncwarp();
                int mb = m0 + wm*64 + i*16;
                int nb = n0 + wn*64 + j*16;
                #pragma unroll
                for (int e = lane; e < 256; e += 32) {
                    int rr = e >> 4, cc = e & 15;
                    float v = stage[e];
                    size_t base = (size_t)(mb + rr)*N + nb + cc;
                    if (MODE == 1) {
                        ((__half*)Cout)[base] = __float2half(v);
                    } else if (MODE == 3) {
                        float gg = 1.0f / (1.0f + __expf(-(v + bias[nb + cc])));
                        ((__half*)Cout)[base] = __float2half(gg*aux1[base] + aux2[base]);
                    } else {  // MODE 4
                        ((float*)Cout)[base] = v + bias[nb + cc];
                    }
                }
                __syncwarp();
            }
    }
}

// ===========================================================================
// small kernels
// ===========================================================================
__global__ __launch_bounds__(256)
void biasln_c_kernel(float* __restrict__ a, const float* __restrict__ bo,
                     const float* __restrict__ g, const float* __restrict__ b,
                     __half* __restrict__ lo)
{
    size_t base = (size_t)blockIdx.x * 1024;
    int t = threadIdx.x;
    float4 v  = *reinterpret_cast<float4*>(a + base + t*4);
    float4 bb = *reinterpret_cast<const float4*>(bo + t*4);
    v.x += bb.x; v.y += bb.y; v.z += bb.z; v.w += bb.w;
    *reinterpret_cast<float4*>(a + base + t*4) = v;

    float s = v.x + v.y + v.z + v.w;
    float q = v.x*v.x + v.y*v.y + v.z*v.z + v.w*v.w;
    #pragma unroll
    for (int o = 16; o; o >>= 1) {
        s += __shfl_xor_sync(0xffffffffu, s, o);
        q += __shfl_xor_sync(0xffffffffu, q, o);
    }
    __shared__ float red[16];
    if ((t & 31) == 0) { red[t>>5] = s; red[8 + (t>>5)] = q; }
    __syncthreads();
    float S = 0.f, Q = 0.f;
    #pragma unroll
    for (int i = 0; i < 8; i++) { S += red[i]; Q += red[8+i]; }
    float mu  = S * (1.0f/1024.0f);
    float var = Q * (1.0f/1024.0f) - mu*mu;
    float rs  = rsqrtf(var + 1e-5f);

    float4 gg = *reinterpret_cast<const float4*>(g + t*4);
    float4 b2 = *reinterpret_cast<const float4*>(b + t*4);
    __half2* o = reinterpret_cast<__half2*>(lo + base + t*4);
    o[0] = __floats2half2_rn(gg.x*(v.x - mu)*rs + b2.x, gg.y*(v.y - mu)*rs + b2.y);
    o[1] = __floats2half2_rn(gg.z*(v.z - mu)*rs + b2.z, gg.w*(v.w - mu)*rs + b2.w);
}

__global__ __launch_bounds__(256)
void fuse_bias_kernel(const __half* __restrict__ WkKh, const __half* __restrict__ WvVh,
                      const float* __restrict__ mob,
                      const float* __restrict__ bk, const float* __restrict__ bv,
                      float* __restrict__ bkr, float* __restrict__ bvr)
{
    int i = blockIdx.x & 1023;
    bool isv = blockIdx.x >= 1024;
    const __half* W = isv ? WvVh : WkKh;
    float s = 0.f;
    for (int k = threadIdx.x; k < 1024; k += 256)
        s += __half2float(W[(size_t)i*1024 + k]) * mob[k];
    #pragma unroll
    for (int o = 16; o; o >>= 1) s += __shfl_xor_sync(0xffffffffu, s, o);
    __shared__ float red[8];
    if ((threadIdx.x & 31) == 0) red[threadIdx.x >> 5] = s;
    __syncthreads();
    if (threadIdx.x == 0) {
        float S = 0.f;
        #pragma unroll
        for (int w = 0; w < 8; w++) S += red[w];
        (isv ? bvr : bkr)[i] = S + (isv ? bv : bk)[i];
    }
}

__global__ __launch_bounds__(256)
void pm_proj_kernel(const float* __restrict__ pm,
                    const __half* __restrict__ WkKh, const __half* __restrict__ WvVh,
                    const float* __restrict__ bk, const float* __restrict__ bv,
                    float* __restrict__ kp, float* __restrict__ vp)
{
    int id  = blockIdx.x;
    bool isv = id >= 4096;
    int p = (id & 4095) >> 10;
    int i = id & 1023;
    const __half* W = isv ? WvVh : WkKh;
    float s = 0.f;
    for (int k = threadIdx.x; k < 1024; k += 256)
        s += pm[p*1024 + k] * __half2float(W[(size_t)i*1024 + k]);
    #pragma unroll
    for (int o = 16; o; o >>= 1) s += __shfl_xor_sync(0xffffffffu, s, o);
    __shared__ float red[8];
    if ((threadIdx.x & 31) == 0) red[threadIdx.x >> 5] = s;
    __syncthreads();
    if (threadIdx.x == 0) {
        float S = 0.f;
        #pragma unroll
        for (int w = 0; w < 8; w++) S += red[w];
        (isv ? vp : kp)[p*1024 + i] = S + (isv ? bv : bk)[i];
    }
}

// ===========================================================================
// fp16 attention (R6): block per (segment, head); 8 warps; half in, half out
// ===========================================================================
#define PS_LD 148
#define QK_LD 136
#define PH_LD 152
#define ATTN_SMEM (64*PS_LD*4 + (64*QK_LD + 144*QK_LD + 144*QK_LD + 64*PH_LD)*2)

__global__ __launch_bounds__(256)
void attn_kernel(const __half* __restrict__ qkv,
                 const __half* __restrict__ kvr,
                 const float* __restrict__ kp, const float* __restrict__ vp,
                 const float* __restrict__ bq, const float* __restrict__ bk,
                 const float* __restrict__ bkr,
                 const float* __restrict__ bv, const float* __restrict__ bvr,
                 __half* __restrict__ outh)
{
    extern __shared__ __align__(16) float sm[];
    float*  ps  = sm;
    __half* qsh = reinterpret_cast<__half*>(sm + 64*PS_LD);
    __half* ksh = qsh + 64*QK_LD;
    __half* vsh = ksh + 144*QK_LD;
    __half* ph  = vsh + 144*QK_LD;

    const int seg  = blockIdx.x;
    const int h    = blockIdx.y;
    const int tid  = threadIdx.x;
    const int warp = tid >> 5;
    const int lane = tid & 31;
    const int c0   = h * 128;
    const float scale = 0.08838834764831845f;

    for (int i = tid; i < 64*16; i += 256) {
        int r = i >> 4, c8 = (i & 15) << 3;
        float4 raw = *reinterpret_cast<const float4*>(qkv + (size_t)(seg*64 + r)*3072 + c0 + c8);
        const __half2* hp = reinterpret_cast<const __half2*>(&raw);
        float bv8[8];
        *reinterpret_cast<float4*>(bv8)     = *reinterpret_cast<const float4*>(bq + c0 + c8);
        *reinterpret_cast<float4*>(bv8 + 4) = *reinterpret_cast<const float4*>(bq + c0 + c8 + 4);
        __half2 o[4];
        #pragma unroll
        for (int t = 0; t < 4; t++) {
            float2 f = __half22float2(hp[t]);
            o[t] = __floats2half2_rn((f.x + bv8[2*t])*scale, (f.y + bv8[2*t+1])*scale);
        }
        *reinterpret_cast<float4*>(qsh + r*QK_LD + c8) = *reinterpret_cast<float4*>(o);
    }
    for (int i = tid; i < 144*16; i += 256) {
        int r = i >> 4, c8 = (i & 15) << 3;
        float vals[8] = {0,0,0,0,0,0,0,0};
        if (r < 64) {
            float4 raw = *reinterpret_cast<const float4*>(kvr + (size_t)(seg*64 + r)*2048 + c0 + c8);
            const __half2* hp = reinterpret_cast<const __half2*>(&raw);
            float b8[8];
            *reinterpret_cast<float4*>(b8)     = *reinterpret_cast<const float4*>(bkr + c0 + c8);
            *reinterpret_cast<float4*>(b8 + 4) = *reinterpret_cast<const float4*>(bkr + c0 + c8 + 4);
            #pragma unroll
            for (int t = 0; t < 4; t++) {
                float2 f = __half22float2(hp[t]);
                vals[2*t] = f.x + b8[2*t]; vals[2*t+1] = f.y + b8[2*t+1];
            }
        } else if (r < 68) {
            *reinterpret_cast<float4*>(vals)     = *reinterpret_cast<const float4*>(kp + (size_t)(r-64)*1024 + c0 + c8);
            *reinterpret_cast<float4*>(vals + 4) = *reinterpret_cast<const float4*>(kp + (size_t)(r-64)*1024 + c0 + c8 + 4);
        } else if (r < 132) {
            float4 raw = *reinterpret_cast<const float4*>(qkv + (size_t)(seg*64 + r - 68)*3072 + 1024 + c0 + c8);
            const __half2* hp = reinterpret_cast<const __half2*>(&raw);
            float b8[8];
            *reinterpret_cast<float4*>(b8)     = *reinterpret_cast<const float4*>(bk + c0 + c8);
            *reinterpret_cast<float4*>(b8 + 4) = *reinterpret_cast<const float4*>(bk + c0 + c8 + 4);
            #pragma unroll
            for (int t = 0; t < 4; t++) {
                float2 f = __half22float2(hp[t]);
                vals[2*t] = f.x + b8[2*t]; vals[2*t+1] = f.y + b8[2*t+1];
            }
        }
        __half2 o[4];
        #pragma unroll
        for (int t = 0; t < 4; t++) o[t] = __floats2half2_rn(vals[2*t], vals[2*t+1]);
        *reinterpret_cast<float4*>(ksh + r*QK_LD + c8) = *reinterpret_cast<float4*>(o);
    }
    for (int i = tid; i < 144*16; i += 256) {
        int r = i >> 4, c8 = (i & 15) << 3;
        float vals[8] = {0,0,0,0,0,0,0,0};
        if (r < 64) {
            float4 raw = *reinterpret_cast<const float4*>(kvr + (size_t)(seg*64 + r)*2048 + 1024 + c0 + c8);
            const __half2* hp = reinterpret_cast<const __half2*>(&raw);
            float b8[8];
            *reinterpret_cast<float4*>(b8)     = *reinterpret_cast<const float4*>(bvr + c0 + c8);
            *reinterpret_cast<float4*>(b8 + 4) = *reinterpret_cast<const float4*>(bvr + c0 + c8 + 4);
            #pragma unroll
            for (int t = 0; t < 4; t++) {
                float2 f = __half22float2(hp[t]);
                vals[2*t] = f.x + b8[2*t]; vals[2*t+1] = f.y + b8[2*t+1];
            }
        } else if (r < 68) {
            *reinterpret_cast<float4*>(vals)     = *reinterpret_cast<const float4*>(vp + (size_t)(r-64)*1024 + c0 + c8);
            *reinterpret_cast<float4*>(vals + 4) = *reinterpret_cast<const float4*>(vp + (size_t)(r-64)*1024 + c0 + c8 + 4);
        } else if (r < 132) {
            float4 raw = *reinterpret_cast<const float4*>(qkv + (size_t)(seg*64 + r - 68)*3072 + 2048 + c0 + c8);
            const __half2* hp = reinterpret_cast<const __half2*>(&raw);
            float b8[8];
            *reinterpret_cast<float4*>(b8)     = *reinterpret_cast<const float4*>(bv + c0 + c8);
            *reinterpret_cast<float4*>(b8 + 4) = *reinterpret_cast<const float4*>(bv + c0 + c8 + 4);
            #pragma unroll
            for (int t = 0; t < 4; t++) {
                float2 f = __half22float2(hp[t]);
                vals[2*t] = f.x + b8[2*t]; vals[2*t+1] = f.y + b8[2*t+1];
            }
        }
        __half2 o[4];
        #pragma unroll
        for (int t = 0; t < 4; t++) o[t] = __floats2half2_rn(vals[2*t], vals[2*t+1]);
        *reinterpret_cast<float4*>(vsh + r*QK_LD + c8) = *reinterpret_cast<float4*>(o);
    }
    __syncthreads();

    for (int t = warp; t < 36; t += 8) {
        int ms = (t / 9) * 16;
        int ns = (t % 9) * 16;
        wmma::fragment<wmma::accumulator,16,16,16,float> acc;
        wmma::fill_fragment(acc, 0.0f);
        #pragma unroll
        for (int kk = 0; kk < 128; kk += 16) {
            wmma::fragment<wmma::matrix_a,16,16,16,__half,wmma::row_major> af;
            wmma::fragment<wmma::matrix_b,16,16,16,__half,wmma::col_major> bf;
            wmma::load_matrix_sync(af, qsh + ms*QK_LD + kk, QK_LD);
            wmma::load_matrix_sync(bf, ksh + ns*QK_LD + kk, QK_LD);
            wmma::mma_sync(acc, af, bf, acc);
        }
        wmma::store_matrix_sync(ps + ms*PS_LD + ns, acc, PS_LD, wmma::mem_row_major);
    }
    __syncthreads();

    for (int r = warp*8; r < warp*8 + 8; r++) {
        float* row = ps + r*PS_LD;
        float m = -1e30f;
        for (int c = lane; c < 132; c += 32) m = fmaxf(m, row[c]);
        #pragma unroll
        for (int o = 16; o; o >>= 1) m = fmaxf(m, __shfl_xor_sync(0xffffffffu, m, o));
        float s = 0.f;
        for (int c = lane; c < 132; c += 32) { float e = __expf(row[c] - m); row[c] = e; s += e; }
        #pragma unroll
        for (int o = 16; o; o >>= 1) s += __shfl_xor_sync(0xffffffffu, s, o);
        float inv = 1.0f / s;
        for (int c = lane; c < 132; c += 32) ph[r*PH_LD + c] = __float2half(row[c]*inv);
        if (lane < 20) ph[r*PH_LD + 132 + lane] = __float2half(0.0f);
    }
    __syncthreads();

    for (int t = warp; t < 32; t += 8) {
        int ms = (t >> 3) * 16;
        int ds = (t & 7) * 16;
        wmma::fragment<wmma::accumulator,16,16,16,float> acc;
        wmma::fill_fragment(acc, 0.0f);
        #pragma unroll
        for (int kk = 0; kk < 144; kk += 16) {
            wmma::fragment<wmma::matrix_a,16,16,16,__half,wmma::row_major> af;
            wmma::fragment<wmma::matrix_b,16,16,16,__half,wmma::row_major> bf;
            wmma::load_matrix_sync(af, ph + ms*PH_LD + kk, PH_LD);
            wmma::load_matrix_sync(bf, vsh + kk*QK_LD + ds, QK_LD);
            wmma::mma_sync(acc, af, bf, acc);
        }
        wmma::store_matrix_sync(ps + ms*PS_LD + ds, acc, PS_LD, wmma::mem_row_major);
    }
    __syncthreads();

    for (int i = tid; i < 64*16; i += 256) {
        int r = i >> 4, c8 = (i & 15) << 3;
        const float* src = ps + r*PS_LD + c8;
        __half2 o[4];
        #pragma unroll
        for (int t = 0; t < 4; t++) o[t] = __floats2half2_rn(src[2*t], src[2*t+1]);
        *reinterpret_cast<float4*>(outh + (size_t)(seg*64 + r)*1024 + c0 + c8) =
            *reinterpret_cast<float4*>(o);
    }
}

// ===========================================================================
extern "C" void kernel_launch(void* const* d_in, const int* in_sizes, int n_in,
                              void* d_out, int out_size)
{
    const float* x      = (const float*)d_in[0];
    const float* pm     = (const float*)d_in[1];
    const float* Wq     = (const float*)d_in[2];
    const float* Wk     = (const float*)d_in[3];
    const float* Wv     = (const float*)d_in[4];
    const float* mem_W1 = (const float*)d_in[5];
    const float* mem_b1 = (const float*)d_in[6];
    const float* ln1_g  = (const float*)d_in[7];
    const float* ln1_b  = (const float*)d_in[8];
    const float* mem_W2 = (const float*)d_in[9];
    const float* mem_b2 = (const float*)d_in[10];
    const float* ln2_g  = (const float*)d_in[11];
    const float* ln2_b  = (const float*)d_in[12];
    const float* mem_oW = (const float*)d_in[13];
    const float* mem_ob = (const float*)d_in[14];
    const float* mstate = (const float*)d_in[15];
    const float* mha_Wq = (const float*)d_in[16];
    const float* mha_bq = (const float*)d_in[17];
    const float* mha_Wk = (const float*)d_in[18];
    const float* mha_bk = (const float*)d_in[19];
    const float* mha_Wv = (const float*)d_in[20];
    const float* mha_bv = (const float*)d_in[21];
    const float* mha_Wo = (const float*)d_in[22];
    const float* mha_bo = (const float*)d_in[23];
    const float* gn_g   = (const float*)d_in[24];
    const float* gn_b   = (const float*)d_in[25];
    const float* gate_W = (const float*)d_in[26];
    const float* gate_b = (const float*)d_in[27];
    const float* out_W  = (const float*)d_in[28];
    const float* out_b  = (const float*)d_in[29];
    float* out = (float*)d_out;

    void* sp; cudaGetSymbolAddress(&sp, d_scratch);
    float* S0 = (float*)sp;
    float* A4 = S0;                                     // [16384][1024] f32
    float* kp  = A4 + 16777216ull;
    float* vp  = kp + 4096;
    float* bkr = vp + 4096;
    float* bvr = bkr + 1024;
    __half* xh     = (__half*)(bvr + 1024);
    __half* qkvh   = xh     + 16777216ull;              // [16384][3072]
    __half* kvrh   = qkvh   + 50331648ull;              // [16384][2048]
    __half* A3h    = kvrh   + 33554432ull;
    __half* A5h    = A3h    + 16777216ull;
    __half* uh     = A5h    + 16777216ull;
    __half* m2ah   = uh     + 16777216ull;
    __half* m2h    = m2ah   + 2097152ull;
    __half* Wallh  = m2h    + 2097152ull;               // [3072][1024]
    __half* Wkrvh  = Wallh  + 3145728ull;               // [2048][128]
    __half* W1qh   = Wkrvh  + 262144ull;                // [128][1024]
    __half* W2h    = W1qh   + 131072ull;                // [128][128]
    __half* Woh    = W2h    + 16384ull;
    __half* gateh  = Woh    + 1048576ull;
    __half* outh   = gateh  + 1048576ull;
    __half* mWq_h  = outh   + 1048576ull;
    __half* mWk_h  = mWq_h  + 1048576ull;
    __half* mWv_h  = mWk_h  + 1048576ull;
    __half* memW1h = mWv_h  + 1048576ull;               // [128][1024]
    __half* Wq_h   = memW1h + 131072ull;
    __half* Wk_h   = Wq_h   + 1048576ull;
    __half* Wv_h   = Wk_h   + 1048576ull;
    __half* moW_h  = Wv_h   + 1048576ull;               // [1024][128]
    __half* WkKh   = Wallh  + 1048576ull;
    __half* WvVh   = Wallh  + 2097152ull;

    cudaFuncSetAttribute(wall_prep_h_kernel, cudaFuncAttributeMaxDynamicSharedMemorySize, GSM_NT);
    cudaFuncSetAttribute(wkrv_prep_h_kernel, cudaFuncAttributeMaxDynamicSharedMemorySize, GSM_NT);
    cudaFuncSetAttribute(memnet_kernel<1,0>, cudaFuncAttributeMaxDynamicSharedMemorySize, GSM);
    cudaFuncSetAttribute(memnet_kernel<0,1>, cudaFuncAttributeMaxDynamicSharedMemorySize, GSM);
    cudaFuncSetAttribute(gemm_h2_kernel<0>,  cudaFuncAttributeMaxDynamicSharedMemorySize, GSM2);
    cudaFuncSetAttribute(gemm_h2_kernel<1>,  cudaFuncAttributeMaxDynamicSharedMemorySize, GSM2);
    cudaFuncSetAttribute(gemm_h2_kernel<3>,  cudaFuncAttributeMaxDynamicSharedMemorySize, GSM2);
    cudaFuncSetAttribute(gemm_h2_kernel<4>,  cudaFuncAttributeMaxDynamicSharedMemorySize, GSM2);
    cudaFuncSetAttribute(attn_kernel,        cudaFuncAttributeMaxDynamicSharedMemorySize, ATTN_SMEM);

    dim3 blk(256);

    // 1) one batched convert for all f32->f16 inputs
    ConvBatch cb;
    cb.src[0] = x;      cb.dst[0] = xh;     cb.n[0] = 16777216u;
    cb.src[1] = mem_W2; cb.dst[1] = W2h;    cb.n[1] = 16384u;
    cb.src[2] = mha_Wo; cb.dst[2] = Woh;    cb.n[2] = 1048576u;
    cb.src[3] = gate_W; cb.dst[3] = gateh;  cb.n[3] = 1048576u;
    cb.src[4] = out_W;  cb.dst[4] = outh;   cb.n[4] = 1048576u;
    cb.src[5] = mha_Wq; cb.dst[5] = mWq_h;  cb.n[5] = 1048576u;
    cb.src[6] = mha_Wk; cb.dst[6] = mWk_h;  cb.n[6] = 1048576u;
    cb.src[7] = mha_Wv; cb.dst[7] = mWv_h;  cb.n[7] = 1048576u;
    cb.src[8] = mem_W1; cb.dst[8] = memW1h; cb.n[8] = 131072u;
    cb.src[9] = Wq;     cb.dst[9] = Wq_h;   cb.n[9] = 1048576u;
    cb.src[10] = Wk;    cb.dst[10] = Wk_h;  cb.n[10] = 1048576u;
    cb.src[11] = Wv;    cb.dst[11] = Wv_h;  cb.n[11] = 1048576u;
    cb.src[12] = mem_oW; cb.dst[12] = moW_h; cb.n[12] = 131072u;
    conv_batch_kernel<<<dim3(1024, 13), blk>>>(cb);

    // 2-3) fp16 weight prep (half outputs, no staging)
    wall_prep_h_kernel<<<dim3(8,25), blk, GSM_NT>>>(mWq_h, mWk_h, mWv_h, memW1h,
                                                    Wq_h, Wk_h, Wv_h, Wallh, W1qh);
    wkrv_prep_h_kernel<<<dim3(1,16), blk, GSM_NT>>>(Wallh, moW_h, Wkrvh);

    // 4-5) memory net: fused GEMM + bias(+silu) + LN (+mstate)
    memnet_kernel<1,0><<<dim3(1,128), blk, GSM>>>(xh, W1qh, mem_b1, ln1_g, ln1_b,
                                                  nullptr, m2ah, 1024);
    memnet_kernel<0,1><<<dim3(1,128), blk, GSM>>>(m2ah, W2h, mem_b2, ln2_g, ln2_b,
                                                  mstate, m2h, 128);

    // 6-7) fused q|k|v + retrieved k|v (half outputs)
    gemm_h2_kernel<1><<<dim3(24,64), blk, GSM2>>>(xh,  Wallh, qkvh, nullptr, nullptr, nullptr, 16384, 3072, 1024);
    gemm_h2_kernel<1><<<dim3(16,64), blk, GSM2>>>(m2h, Wkrvh, kvrh, nullptr, nullptr, nullptr, 16384, 2048, 128);

    // 8-9) per-head constants
    fuse_bias_kernel<<<2048, 256>>>(WkKh, WvVh, mem_ob, mha_bk, mha_bv, bkr, bvr);
    pm_proj_kernel<<<8192, 256>>>(pm, WkKh, WvVh, mha_bk, mha_bv, kp, vp);

    // 10) attention
    attn_kernel<<<dim3(256, 8), 256, ATTN_SMEM>>>(qkvh, kvrh, kp, vp,
                                                  mha_bq, mha_bk, bkr, mha_bv, bvr, A3h);

    // 11-14) output path
    gemm_h2_kernel<0><<<dim3(8,64), blk, GSM2>>>(A3h, Woh, A4, nullptr, nullptr, nullptr, 16384, 1024, 1024);
    biasln_c_kernel<<<16384, 256>>>(A4, mha_bo, gn_g, gn_b, A5h);
    gemm_h2_kernel<3><<<dim3(8,64), blk, GSM2>>>(A5h, gateh, uh, gate_b, A4, x, 16384, 1024, 1024);
    gemm_h2_kernel<4><<<dim3(8,64), blk, GSM2>>>(uh, outh, out, out_b, nullptr, nullptr, 16384, 1024, 1024);
}

// round 10
// speedup vs baseline: 1.2814x; 1.2430x over previous
#include <cuda_runtime.h>
#include <cuda_fp16.h>
#include <mma.h>
#include <cstdint>

using namespace nvcuda;

// B=4, L=4096, C=1024, M=128, P=4, S=64, H=8, hd=128
// NSEG=256, TOKS=16384, context T=132

__device__ float d_scratch[162100000ull];

__device__ __forceinline__ void cp16(uint32_t s, const void* g) {
    asm volatile("cp.async.cg.shared.global [%0], [%1], 16;\n" :: "r"(s), "l"(g) : "memory");
}

// ===========================================================================
// batched f32 -> f16 convert (13 tensors in one launch)
// ===========================================================================
struct ConvBatch {
    const float* src[13];
    __half*      dst[13];
    unsigned     n[13];
};

__global__ __launch_bounds__(256)
void conv_batch_kernel(ConvBatch cb)
{
    int t = blockIdx.y;
    size_t n = cb.n[t];
    const float* in = cb.src[t];
    __half* out = cb.dst[t];
    for (size_t i = ((size_t)blockIdx.x*256 + threadIdx.x)*4; i < n;
         i += (size_t)gridDim.x*256*4) {
        float4 v = *reinterpret_cast<const float4*>(in + i);
        __half2 o2[2];
        o2[0] = __floats2half2_rn(v.x, v.y);
        o2[1] = __floats2half2_rn(v.z, v.w);
        *reinterpret_cast<float2*>(out + i) = *reinterpret_cast<float2*>(o2);
    }
}

// ===========================================================================
// fp16 NT GEMM for weight prep: C(half)[.,N] = A[M,K](h, K-major) @ B[K,N](h, row-major)
// ===========================================================================
#define NT_AS 9216
#define NT_BS 8704
#define GSM_NT (4*(NT_AS + NT_BS)*2)

__device__ void gemm_nt_h_body(const __half* __restrict__ A, const __half* __restrict__ B,
                               __half* __restrict__ C, int N, int K,
                               int am0, int n0, int cm0)
{
    extern __shared__ __align__(16) __half smh[];
    __half* As = smh;
    __half* Bs = smh + 4*NT_AS;

    const int tid  = threadIdx.x;
    const int warp = tid >> 5;
    const int lane = tid & 31;
    const int wm   = warp & 3;
    const int wn   = warp >> 2;
    const int nk   = K >> 6;

    auto load = [&](int it, int s) {
        const __half* Ag = A + (size_t)am0*K + it*64;
        const __half* Bg = B + (size_t)(it*64)*N + n0;
        uint32_t sA = (uint32_t)__cvta_generic_to_shared(As + s*NT_AS);
        uint32_t sB = (uint32_t)__cvta_generic_to_shared(Bs + s*NT_BS);
        #pragma unroll
        for (int i = 0; i < 4; i++) {
            int ch = tid + i*256;
            int r = ch >> 3, c = (ch & 7) << 3;
            cp16(sA + (uint32_t)(r*72 + c)*2u, Ag + (size_t)r*K + c);
            int kk = ch >> 4, c2 = (ch & 15) << 3;
            cp16(sB + (uint32_t)(kk*136 + c2)*2u, Bg + (size_t)kk*N + c2);
        }
    };

    wmma::fragment<wmma::accumulator,16,16,16,float> cf[2][4];
    #pragma unroll
    for (int i = 0; i < 2; i++)
        #pragma unroll
        for (int j = 0; j < 4; j++)
            wmma::fill_fragment(cf[i][j], 0.0f);

    #pragma unroll
    for (int s = 0; s < 3; s++) {
        if (s < nk) load(s, s);
        asm volatile("cp.async.commit_group;\n" ::: "memory");
    }

    for (int it = 0; it < nk; it++) {
        if (it + 3 < nk) load(it + 3, (it + 3) & 3);
        asm volatile("cp.async.commit_group;\n" ::: "memory");
        asm volatile("cp.async.wait_group 3;\n" ::: "memory");
        __syncthreads();

        const __half* Ab = As + (it & 3)*NT_AS;
        const __half* Bb = Bs + (it & 3)*NT_BS;
        #pragma unroll
        for (int kk = 0; kk < 64; kk += 16) {
            wmma::fragment<wmma::matrix_a,16,16,16,__half,wmma::row_major> af[2];
            wmma::fragment<wmma::matrix_b,16,16,16,__half,wmma::row_major> bf[4];
            #pragma unroll
            for (int i = 0; i < 2; i++)
                wmma::load_matrix_sync(af[i], Ab + (wm*32 + i*16)*72 + kk, 72);
            #pragma unroll
            for (int j = 0; j < 4; j++)
                wmma::load_matrix_sync(bf[j], Bb + kk*136 + wn*64 + j*16, 136);
            #pragma unroll
            for (int i = 0; i < 2; i++)
                #pragma unroll
                for (int j = 0; j < 4; j++)
                    wmma::mma_sync(cf[i][j], af[i], bf[j], cf[i][j]);
        }
        __syncthreads();
    }

    float* stage = reinterpret_cast<float*>(smh) + warp*256;
    #pragma unroll
    for (int i = 0; i < 2; i++)
        #pragma unroll
        for (int j = 0; j < 4; j++) {
            wmma::store_matrix_sync(stage, cf[i][j], 16, wmma::mem_row_major);
            __syncwarp();
            int mb = cm0 + wm*32 + i*16;
            int nb = n0 + wn*64 + j*16;
            #pragma unroll
            for (int e = lane; e < 256; e += 32) {
                int rr = e >> 4, cc = e & 15;
                C[(size_t)(mb + rr)*N + nb + cc] = __float2half(stage[e]);
            }
            __syncwarp();
        }
}

__global__ __launch_bounds__(256)
void wall_prep_h_kernel(const __half* mWq, const __half* mWk, const __half* mWv,
                        const __half* memW1,
                        const __half* Wq, const __half* Wk, const __half* Wv,
                        __half* Wallh, __half* W1qh)
{
    int by = blockIdx.y;
    const __half *A, *B; __half* Cb; int am0;
    if (by < 8)       { A = mWq;   B = Wq; Cb = Wallh;            am0 = by*128; }
    else if (by < 16) { A = mWk;   B = Wk; Cb = Wallh + 1048576;  am0 = (by-8)*128; }
    else if (by < 24) { A = mWv;   B = Wv; Cb = Wallh + 2097152;  am0 = (by-16)*128; }
    else              { A = memW1; B = Wq; Cb = W1qh;             am0 = 0; }
    gemm_nt_h_body(A, B, Cb, 1024, 1024, am0, blockIdx.x*128, am0);
}

__global__ __launch_bounds__(256)
void wkrv_prep_h_kernel(const __half* Wallh, const __half* moW, __half* Wkrvh)
{
    int by = blockIdx.y;
    const __half* A = (by < 8) ? (Wallh + 1048576) : (Wallh + 2097152);
    int am0 = (by & 7)*128;
    gemm_nt_h_body(A, moW, Wkrvh, 128, 1024, am0, 0, by*128);
}

// ===========================================================================
// shared tile loader: 128x64 halves (row stride 72)
// ===========================================================================
#define HLD 72
#define HSTS 9216
#define GSM 147456

__device__ __forceinline__ void load_tile_h(const __half* Ag0, const __half* Wg0,
                                            int K, int it, __half* As, __half* Bs, int tid)
{
    const __half* Ag = Ag0 + it*64;
    const __half* Wg = Wg0 + it*64;
    uint32_t sA = (uint32_t)__cvta_generic_to_shared(As);
    uint32_t sB = (uint32_t)__cvta_generic_to_shared(Bs);
    #pragma unroll
    for (int i = 0; i < 4; i++) {
        int ch = tid + i*256;
        int r = ch >> 3, c = (ch & 7) << 3;
        cp16(sA + (uint32_t)(r*HLD + c)*2u, Ag + (size_t)r*K + c);
        cp16(sB + (uint32_t)(r*HLD + c)*2u, Wg + (size_t)r*K + c);
    }
}

// ===========================================================================
// memory-net fused GEMM + bias (+silu) + LayerNorm (+mstate): N=128
// ===========================================================================
template<int DO_SILU, int ADD_MSTATE>
__global__ __launch_bounds__(256)
void memnet_kernel(const __half* __restrict__ A, const __half* __restrict__ W,
                   const float* __restrict__ bias,
                   const float* __restrict__ g, const float* __restrict__ b,
                   const float* __restrict__ mstate,
                   __half* __restrict__ out, int K)
{
    extern __shared__ __align__(16) __half smh[];
    __half* As = smh;
    __half* Bs = smh + 4*HSTS;

    const int tid  = threadIdx.x;
    const int warp = tid >> 5;
    const int lane = tid & 31;
    const int wm   = warp & 3;
    const int wn   = warp >> 2;
    const int m0   = blockIdx.y * 128;
    const int nk   = K >> 6;

    const __half* Ag0 = A + (size_t)m0*K;

    wmma::fragment<wmma::accumulator,16,16,16,float> cf[2][4];
    #pragma unroll
    for (int i = 0; i < 2; i++)
        #pragma unroll
        for (int j = 0; j < 4; j++)
            wmma::fill_fragment(cf[i][j], 0.0f);

    #pragma unroll
    for (int s = 0; s < 3; s++) {
        if (s < nk) load_tile_h(Ag0, W, K, s, As + s*HSTS, Bs + s*HSTS, tid);
        asm volatile("cp.async.commit_group;\n" ::: "memory");
    }

    for (int it = 0; it < nk; it++) {
        if (it + 3 < nk) {
            int slot = (it + 3) & 3;
            load_tile_h(Ag0, W, K, it + 3, As + slot*HSTS, Bs + slot*HSTS, tid);
        }
        asm volatile("cp.async.commit_group;\n" ::: "memory");
        asm volatile("cp.async.wait_group 3;\n" ::: "memory");
        __syncthreads();

        const __half* Ab = As + (it & 3)*HSTS;
        const __half* Bb = Bs + (it & 3)*HSTS;
        #pragma unroll
        for (int kk = 0; kk < 64; kk += 16) {
            wmma::fragment<wmma::matrix_a,16,16,16,__half,wmma::row_major> af[2];
            wmma::fragment<wmma::matrix_b,16,16,16,__half,wmma::col_major> bf[4];
            #pragma unroll
            for (int i = 0; i < 2; i++)
                wmma::load_matrix_sync(af[i], Ab + (wm*32 + i*16)*HLD + kk, HLD);
            #pragma unroll
            for (int j = 0; j < 4; j++)
                wmma::load_matrix_sync(bf[j], Bb + (wn*64 + j*16)*HLD + kk, HLD);
            #pragma unroll
            for (int i = 0; i < 2; i++)
                #pragma unroll
                for (int j = 0; j < 4; j++)
                    wmma::mma_sync(cf[i][j], af[i], bf[j], cf[i][j]);
        }
        __syncthreads();
    }

    float* tile = reinterpret_cast<float*>(smh);
    #pragma unroll
    for (int i = 0; i < 2; i++)
        #pragma unroll
        for (int j = 0; j < 4; j++)
            wmma::store_matrix_sync(tile + (wm*32 + i*16)*132 + wn*64 + j*16,
                                    cf[i][j], 132, wmma::mem_row_major);
    __syncthreads();

    float bb4[4], gg4[4], b24[4], ms4[4];
    *reinterpret_cast<float4*>(bb4) = *reinterpret_cast<const float4*>(bias + lane*4);
    *reinterpret_cast<float4*>(gg4) = *reinterpret_cast<const float4*>(g + lane*4);
    *reinterpret_cast<float4*>(b24) = *reinterpret_cast<const float4*>(b + lane*4);
    if (ADD_MSTATE)
        *reinterpret_cast<float4*>(ms4) = *reinterpret_cast<const float4*>(mstate + lane*4);

    #pragma unroll
    for (int rr = 0; rr < 16; rr++) {
        int row = warp*16 + rr;
        float4 v4 = *reinterpret_cast<const float4*>(tile + row*132 + lane*4);
        float t[4] = {v4.x + bb4[0], v4.y + bb4[1], v4.z + bb4[2], v4.w + bb4[3]};
        if (DO_SILU) {
            #pragma unroll
            for (int e = 0; e < 4; e++) t[e] = t[e] / (1.0f + __expf(-t[e]));
        }
        float s = t[0]+t[1]+t[2]+t[3];
        float q = t[0]*t[0]+t[1]*t[1]+t[2]*t[2]+t[3]*t[3];
        #pragma unroll
        for (int o = 16; o; o >>= 1) {
            s += __shfl_xor_sync(0xffffffffu, s, o);
            q += __shfl_xor_sync(0xffffffffu, q, o);
        }
        float mu  = s * (1.0f/128.0f);
        float var = q * (1.0f/128.0f) - mu*mu;
        float rs  = rsqrtf(var + 1e-5f);
        __half2 o2[2];
        float o0 = gg4[0]*(t[0]-mu)*rs + b24[0];
        float o1 = gg4[1]*(t[1]-mu)*rs + b24[1];
        float o2f = gg4[2]*(t[2]-mu)*rs + b24[2];
        float o3 = gg4[3]*(t[3]-mu)*rs + b24[3];
        if (ADD_MSTATE) { o0 += ms4[0]; o1 += ms4[1]; o2f += ms4[2]; o3 += ms4[3]; }
        o2[0] = __floats2half2_rn(o0, o1);
        o2[1] = __floats2half2_rn(o2f, o3);
        *reinterpret_cast<float2*>(out + (size_t)(m0 + row)*128 + lane*4) =
            *reinterpret_cast<float2*>(o2);
    }
}

// ===========================================================================
// main-path GEMM, occupancy-2: 128x128 CTA tile, 32x64 warp tile, Ktile 64,
// 3 stages (110592 B smem -> 2 CTAs/SM, 16 warps/SM).
// MODE 0: f32 direct store. MODE 1: half out.
// MODE 3: gate fusion u = sigmoid(acc+bias)*aux1 + aux2 -> half
// MODE 4: f32 + bias
// ===========================================================================
#define GSM_O2 (3*2*HSTS*2)

template<int MODE>
__global__ __launch_bounds__(256, 2)
void gemm_o2_kernel(const __half* __restrict__ A, const __half* __restrict__ W,
                    void* __restrict__ Cout, const float* __restrict__ bias,
                    const float* __restrict__ aux1, const float* __restrict__ aux2,
                    int M, int N, int K)
{
    extern __shared__ __align__(16) __half smh[];
    __half* As = smh;
    __half* Bs = smh + 3*HSTS;

    const int tid  = threadIdx.x;
    const int warp = tid >> 5;
    const int lane = tid & 31;
    const int wm   = warp & 3;
    const int wn   = warp >> 2;
    const int m0   = blockIdx.y * 128;
    const int n0   = blockIdx.x * 128;
    const int nk   = K >> 6;

    const __half* Ag0 = A + (size_t)m0*K;
    const __half* Wg0 = W + (size_t)n0*K;

    wmma::fragment<wmma::accumulator,16,16,16,float> cf[2][4];
    #pragma unroll
    for (int i = 0; i < 2; i++)
        #pragma unroll
        for (int j = 0; j < 4; j++)
            wmma::fill_fragment(cf[i][j], 0.0f);

    #pragma unroll
    for (int s = 0; s < 2; s++) {
        if (s < nk) load_tile_h(Ag0, Wg0, K, s, As + s*HSTS, Bs + s*HSTS, tid);
        asm volatile("cp.async.commit_group;\n" ::: "memory");
    }

    for (int it = 0; it < nk; it++) {
        if (it + 2 < nk) {
            int slot = (it + 2) % 3;
            load_tile_h(Ag0, Wg0, K, it + 2, As + slot*HSTS, Bs + slot*HSTS, tid);
        }
        asm volatile("cp.async.commit_group;\n" ::: "memory");
        asm volatile("cp.async.wait_group 2;\n" ::: "memory");
        __syncthreads();

        int cs = it % 3;
        const __half* Ab = As + cs*HSTS;
        const __half* Bb = Bs + cs*HSTS;
        #pragma unroll
        for (int kk = 0; kk < 64; kk += 16) {
            wmma::fragment<wmma::matrix_a,16,16,16,__half,wmma::row_major> af[2];
            wmma::fragment<wmma::matrix_b,16,16,16,__half,wmma::col_major> bf[4];
            #pragma unroll
            for (int i = 0; i < 2; i++)
                wmma::load_matrix_sync(af[i], Ab + (wm*32 + i*16)*HLD + kk, HLD);
            #pragma unroll
            for (int j = 0; j < 4; j++)
                wmma::load_matrix_sync(bf[j], Bb + (wn*64 + j*16)*HLD + kk, HLD);
            #pragma unroll
            for (int i = 0; i < 2; i++)
                #pragma unroll
                for (int j = 0; j < 4; j++)
                    wmma::mma_sync(cf[i][j], af[i], bf[j], cf[i][j]);
        }
        __syncthreads();
    }

    if (MODE == 0) {
        float* Cf = (float*)Cout;
        #pragma unroll
        for (int i = 0; i < 2; i++)
            #pragma unroll
            for (int j = 0; j < 4; j++)
                wmma::store_matrix_sync(&Cf[(size_t)(m0 + wm*32 + i*16)*N + n0 + wn*64 + j*16],
                                        cf[i][j], N, wmma::mem_row_major);
    } else {
        float* stage = reinterpret_cast<float*>(smh) + warp*256;
        #pragma unroll
        for (int i = 0; i < 2; i++)
            #pragma unroll
            for (int j = 0; j < 4; j++) {
                wmma::store_matrix_sync(stage, cf[i][j], 16, wmma::mem_row_major);
                __syncwarp();
                int mb = m0 + wm*32 + i*16;
                int nb = n0 + wn*64 + j*16;
                #pragma unroll
                for (int e = lane; e < 256; e += 32) {
                    int rr = e >> 4, cc = e & 15;
                    float v = stage[e];
                    size_t base = (size_t)(mb + rr)*N + nb + cc;
                    if (MODE == 1) {
                        ((__half*)Cout)[base] = __float2half(v);
                    } else if (MODE == 3) {
                        float gg = 1.0f / (1.0f + __expf(-(v + bias[nb + cc])));
                        ((__half*)Cout)[base] = __float2half(gg*aux1[base] + aux2[base]);
                    } else {  // MODE 4
                        ((float*)Cout)[base] = v + bias[nb + cc];
                    }
                }
                __syncwarp();
            }
    }
}

// ===========================================================================
// small kernels
// ===========================================================================
__global__ __launch_bounds__(256)
void biasln_c_kernel(float* __restrict__ a, const float* __restrict__ bo,
                     const float* __restrict__ g, const float* __restrict__ b,
                     __half* __restrict__ lo)
{
    size_t base = (size_t)blockIdx.x * 1024;
    int t = threadIdx.x;
    float4 v  = *reinterpret_cast<float4*>(a + base + t*4);
    float4 bb = *reinterpret_cast<const float4*>(bo + t*4);
    v.x += bb.x; v.y += bb.y; v.z += bb.z; v.w += bb.w;
    *reinterpret_cast<float4*>(a + base + t*4) = v;

    float s = v.x + v.y + v.z + v.w;
    float q = v.x*v.x + v.y*v.y + v.z*v.z + v.w*v.w;
    #pragma unroll
    for (int o = 16; o; o >>= 1) {
        s += __shfl_xor_sync(0xffffffffu, s, o);
        q += __shfl_xor_sync(0xffffffffu, q, o);
    }
    __shared__ float red[16];
    if ((t & 31) == 0) { red[t>>5] = s; red[8 + (t>>5)] = q; }
    __syncthreads();
    float S = 0.f, Q = 0.f;
    #pragma unroll
    for (int i = 0; i < 8; i++) { S += red[i]; Q += red[8+i]; }
    float mu  = S * (1.0f/1024.0f);
    float var = Q * (1.0f/1024.0f) - mu*mu;
    float rs  = rsqrtf(var + 1e-5f);

    float4 gg = *reinterpret_cast<const float4*>(g + t*4);
    float4 b2 = *reinterpret_cast<const float4*>(b + t*4);
    __half2* o = reinterpret_cast<__half2*>(lo + base + t*4);
    o[0] = __floats2half2_rn(gg.x*(v.x - mu)*rs + b2.x, gg.y*(v.y - mu)*rs + b2.y);
    o[1] = __floats2half2_rn(gg.z*(v.z - mu)*rs + b2.z, gg.w*(v.w - mu)*rs + b2.w);
}

__global__ __launch_bounds__(256)
void fuse_bias_kernel(const __half* __restrict__ WkKh, const __half* __restrict__ WvVh,
                      const float* __restrict__ mob,
                      const float* __restrict__ bk, const float* __restrict__ bv,
                      float* __restrict__ bkr, float* __restrict__ bvr)
{
    int i = blockIdx.x & 1023;
    bool isv = blockIdx.x >= 1024;
    const __half* W = isv ? WvVh : WkKh;
    float s = 0.f;
    for (int k = threadIdx.x; k < 1024; k += 256)
        s += __half2float(W[(size_t)i*1024 + k]) * mob[k];
    #pragma unroll
    for (int o = 16; o; o >>= 1) s += __shfl_xor_sync(0xffffffffu, s, o);
    __shared__ float red[8];
    if ((threadIdx.x & 31) == 0) red[threadIdx.x >> 5] = s;
    __syncthreads();
    if (threadIdx.x == 0) {
        float S = 0.f;
        #pragma unroll
        for (int w = 0; w < 8; w++) S += red[w];
        (isv ? bvr : bkr)[i] = S + (isv ? bv : bk)[i];
    }
}

__global__ __launch_bounds__(256)
void pm_proj_kernel(const float* __restrict__ pm,
                    const __half* __restrict__ WkKh, const __half* __restrict__ WvVh,
                    const float* __restrict__ bk, const float* __restrict__ bv,
                    float* __restrict__ kp, float* __restrict__ vp)
{
    int id  = blockIdx.x;
    bool isv = id >= 4096;
    int p = (id & 4095) >> 10;
    int i = id & 1023;
    const __half* W = isv ? WvVh : WkKh;
    float s = 0.f;
    for (int k = threadIdx.x; k < 1024; k += 256)
        s += pm[p*1024 + k] * __half2float(W[(size_t)i*1024 + k]);
    #pragma unroll
    for (int o = 16; o; o >>= 1) s += __shfl_xor_sync(0xffffffffu, s, o);
    __shared__ float red[8];
    if ((threadIdx.x & 31) == 0) red[threadIdx.x >> 5] = s;
    __syncthreads();
    if (threadIdx.x == 0) {
        float S = 0.f;
        #pragma unroll
        for (int w = 0; w < 8; w++) S += red[w];
        (isv ? vp : kp)[p*1024 + i] = S + (isv ? bv : bk)[i];
    }
}

// ===========================================================================
// fp16 attention: block per (segment, head); 8 warps; half in, half out
// ===========================================================================
#define PS_LD 148
#define QK_LD 136
#define PH_LD 152
#define ATTN_SMEM (64*PS_LD*4 + (64*QK_LD + 144*QK_LD + 144*QK_LD + 64*PH_LD)*2)

__global__ __launch_bounds__(256)
void attn_kernel(const __half* __restrict__ qkv,
                 const __half* __restrict__ kvr,
                 const float* __restrict__ kp, const float* __restrict__ vp,
                 const float* __restrict__ bq, const float* __restrict__ bk,
                 const float* __restrict__ bkr,
                 const float* __restrict__ bv, const float* __restrict__ bvr,
                 __half* __restrict__ outh)
{
    extern __shared__ __align__(16) float sm[];
    float*  ps  = sm;
    __half* qsh = reinterpret_cast<__half*>(sm + 64*PS_LD);
    __half* ksh = qsh + 64*QK_LD;
    __half* vsh = ksh + 144*QK_LD;
    __half* ph  = vsh + 144*QK_LD;

    const int seg  = blockIdx.x;
    const int h    = blockIdx.y;
    const int tid  = threadIdx.x;
    const int warp = tid >> 5;
    const int lane = tid & 31;
    const int c0   = h * 128;
    const float scale = 0.08838834764831845f;

    for (int i = tid; i < 64*16; i += 256) {
        int r = i >> 4, c8 = (i & 15) << 3;
        float4 raw = *reinterpret_cast<const float4*>(qkv + (size_t)(seg*64 + r)*3072 + c0 + c8);
        const __half2* hp = reinterpret_cast<const __half2*>(&raw);
        float bv8[8];
        *reinterpret_cast<float4*>(bv8)     = *reinterpret_cast<const float4*>(bq + c0 + c8);
        *reinterpret_cast<float4*>(bv8 + 4) = *reinterpret_cast<const float4*>(bq + c0 + c8 + 4);
        __half2 o[4];
        #pragma unroll
        for (int t = 0; t < 4; t++) {
            float2 f = __half22float2(hp[t]);
            o[t] = __floats2half2_rn((f.x + bv8[2*t])*scale, (f.y + bv8[2*t+1])*scale);
        }
        *reinterpret_cast<float4*>(qsh + r*QK_LD + c8) = *reinterpret_cast<float4*>(o);
    }
    for (int i = tid; i < 144*16; i += 256) {
        int r = i >> 4, c8 = (i & 15) << 3;
        float vals[8] = {0,0,0,0,0,0,0,0};
        if (r < 64) {
            float4 raw = *reinterpret_cast<const float4*>(kvr + (size_t)(seg*64 + r)*2048 + c0 + c8);
            const __half2* hp = reinterpret_cast<const __half2*>(&raw);
            float b8[8];
            *reinterpret_cast<float4*>(b8)     = *reinterpret_cast<const float4*>(bkr + c0 + c8);
            *reinterpret_cast<float4*>(b8 + 4) = *reinterpret_cast<const float4*>(bkr + c0 + c8 + 4);
            #pragma unroll
            for (int t = 0; t < 4; t++) {
                float2 f = __half22float2(hp[t]);
                vals[2*t] = f.x + b8[2*t]; vals[2*t+1] = f.y + b8[2*t+1];
            }
        } else if (r < 68) {
            *reinterpret_cast<float4*>(vals)     = *reinterpret_cast<const float4*>(kp + (size_t)(r-64)*1024 + c0 + c8);
            *reinterpret_cast<float4*>(vals + 4) = *reinterpret_cast<const float4*>(kp + (size_t)(r-64)*1024 + c0 + c8 + 4);
        } else if (r < 132) {
            float4 raw = *reinterpret_cast<const float4*>(qkv + (size_t)(seg*64 + r - 68)*3072 + 1024 + c0 + c8);
            const __half2* hp = reinterpret_cast<const __half2*>(&raw);
            float b8[8];
            *reinterpret_cast<float4*>(b8)     = *reinterpret_cast<const float4*>(bk + c0 + c8);
            *reinterpret_cast<float4*>(b8 + 4) = *reinterpret_cast<const float4*>(bk + c0 + c8 + 4);
            #pragma unroll
            for (int t = 0; t < 4; t++) {
                float2 f = __half22float2(hp[t]);
                vals[2*t] = f.x + b8[2*t]; vals[2*t+1] = f.y + b8[2*t+1];
            }
        }
        __half2 o[4];
        #pragma unroll
        for (int t = 0; t < 4; t++) o[t] = __floats2half2_rn(vals[2*t], vals[2*t+1]);
        *reinterpret_cast<float4*>(ksh + r*QK_LD + c8) = *reinterpret_cast<float4*>(o);
    }
    for (int i = tid; i < 144*16; i += 256) {
        int r = i >> 4, c8 = (i & 15) << 3;
        float vals[8] = {0,0,0,0,0,0,0,0};
        if (r < 64) {
            float4 raw = *reinterpret_cast<const float4*>(kvr + (size_t)(seg*64 + r)*2048 + 1024 + c0 + c8);
            const __half2* hp = reinterpret_cast<const __half2*>(&raw);
            float b8[8];
            *reinterpret_cast<float4*>(b8)     = *reinterpret_cast<const float4*>(bvr + c0 + c8);
            *reinterpret_cast<float4*>(b8 + 4) = *reinterpret_cast<const float4*>(bvr + c0 + c8 + 4);
            #pragma unroll
            for (int t = 0; t < 4; t++) {
                float2 f = __half22float2(hp[t]);
                vals[2*t] = f.x + b8[2*t]; vals[2*t+1] = f.y + b8[2*t+1];
            }
        } else if (r < 68) {
            *reinterpret_cast<float4*>(vals)     = *reinterpret_cast<const float4*>(vp + (size_t)(r-64)*1024 + c0 + c8);
            *reinterpret_cast<float4*>(vals + 4) = *reinterpret_cast<const float4*>(vp + (size_t)(r-64)*1024 + c0 + c8 + 4);
        } else if (r < 132) {
            float4 raw = *reinterpret_cast<const float4*>(qkv + (size_t)(seg*64 + r - 68)*3072 + 2048 + c0 + c8);
            const __half2* hp = reinterpret_cast<const __half2*>(&raw);
            float b8[8];
            *reinterpret_cast<float4*>(b8)     = *reinterpret_cast<const float4*>(bv + c0 + c8);
            *reinterpret_cast<float4*>(b8 + 4) = *reinterpret_cast<const float4*>(bv + c0 + c8 + 4);
            #pragma unroll
            for (int t = 0; t < 4; t++) {
                float2 f = __half22float2(hp[t]);
                vals[2*t] = f.x + b8[2*t]; vals[2*t+1] = f.y + b8[2*t+1];
            }
        }
        __half2 o[4];
        #pragma unroll
        for (int t = 0; t < 4; t++) o[t] = __floats2half2_rn(vals[2*t], vals[2*t+1]);
        *reinterpret_cast<float4*>(vsh + r*QK_LD + c8) = *reinterpret_cast<float4*>(o);
    }
    __syncthreads();

    for (int t = warp; t < 36; t += 8) {
        int ms = (t / 9) * 16;
        int ns = (t % 9) * 16;
        wmma::fragment<wmma::accumulator,16,16,16,float> acc;
        wmma::fill_fragment(acc, 0.0f);
        #pragma unroll
        for (int kk = 0; kk < 128; kk += 16) {
            wmma::fragment<wmma::matrix_a,16,16,16,__half,wmma::row_major> af;
            wmma::fragment<wmma::matrix_b,16,16,16,__half,wmma::col_major> bf;
            wmma::load_matrix_sync(af, qsh + ms*QK_LD + kk, QK_LD);
            wmma::load_matrix_sync(bf, ksh + ns*QK_LD + kk, QK_LD);
            wmma::mma_sync(acc, af, bf, acc);
        }
        wmma::store_matrix_sync(ps + ms*PS_LD + ns, acc, PS_LD, wmma::mem_row_major);
    }
    __syncthreads();

    for (int r = warp*8; r < warp*8 + 8; r++) {
        float* row = ps + r*PS_LD;
        float m = -1e30f;
        for (int c = lane; c < 132; c += 32) m = fmaxf(m, row[c]);
        #pragma unroll
        for (int o = 16; o; o >>= 1) m = fmaxf(m, __shfl_xor_sync(0xffffffffu, m, o));
        float s = 0.f;
        for (int c = lane; c < 132; c += 32) { float e = __expf(row[c] - m); row[c] = e; s += e; }
        #pragma unroll
        for (int o = 16; o; o >>= 1) s += __shfl_xor_sync(0xffffffffu, s, o);
        float inv = 1.0f / s;
        for (int c = lane; c < 132; c += 32) ph[r*PH_LD + c] = __float2half(row[c]*inv);
        if (lane < 20) ph[r*PH_LD + 132 + lane] = __float2half(0.0f);
    }
    __syncthreads();

    for (int t = warp; t < 32; t += 8) {
        int ms = (t >> 3) * 16;
        int ds = (t & 7) * 16;
        wmma::fragment<wmma::accumulator,16,16,16,float> acc;
        wmma::fill_fragment(acc, 0.0f);
        #pragma unroll
        for (int kk = 0; kk < 144; kk += 16) {
            wmma::fragment<wmma::matrix_a,16,16,16,__half,wmma::row_major> af;
            wmma::fragment<wmma::matrix_b,16,16,16,__half,wmma::row_major> bf;
            wmma::load_matrix_sync(af, ph + ms*PH_LD + kk, PH_LD);
            wmma::load_matrix_sync(bf, vsh + kk*QK_LD + ds, QK_LD);
            wmma::mma_sync(acc, af, bf, acc);
        }
        wmma::store_matrix_sync(ps + ms*PS_LD + ds, acc, PS_LD, wmma::mem_row_major);
    }
    __syncthreads();

    for (int i = tid; i < 64*16; i += 256) {
        int r = i >> 4, c8 = (i & 15) << 3;
        const float* src = ps + r*PS_LD + c8;
        __half2 o[4];
        #pragma unroll
        for (int t = 0; t < 4; t++) o[t] = __floats2half2_rn(src[2*t], src[2*t+1]);
        *reinterpret_cast<float4*>(outh + (size_t)(seg*64 + r)*1024 + c0 + c8) =
            *reinterpret_cast<float4*>(o);
    }
}

// ===========================================================================
extern "C" void kernel_launch(void* const* d_in, const int* in_sizes, int n_in,
                              void* d_out, int out_size)
{
    const float* x      = (const float*)d_in[0];
    const float* pm     = (const float*)d_in[1];
    const float* Wq     = (const float*)d_in[2];
    const float* Wk     = (const float*)d_in[3];
    const float* Wv     = (const float*)d_in[4];
    const float* mem_W1 = (const float*)d_in[5];
    const float* mem_b1 = (const float*)d_in[6];
    const float* ln1_g  = (const float*)d_in[7];
    const float* ln1_b  = (const float*)d_in[8];
    const float* mem_W2 = (const float*)d_in[9];
    const float* mem_b2 = (const float*)d_in[10];
    const float* ln2_g  = (const float*)d_in[11];
    const float* ln2_b  = (const float*)d_in[12];
    const float* mem_oW = (const float*)d_in[13];
    const float* mem_ob = (const float*)d_in[14];
    const float* mstate = (const float*)d_in[15];
    const float* mha_Wq = (const float*)d_in[16];
    const float* mha_bq = (const float*)d_in[17];
    const float* mha_Wk = (const float*)d_in[18];
    const float* mha_bk = (const float*)d_in[19];
    const float* mha_Wv = (const float*)d_in[20];
    const float* mha_bv = (const float*)d_in[21];
    const float* mha_Wo = (const float*)d_in[22];
    const float* mha_bo = (const float*)d_in[23];
    const float* gn_g   = (const float*)d_in[24];
    const float* gn_b   = (const float*)d_in[25];
    const float* gate_W = (const float*)d_in[26];
    const float* gate_b = (const float*)d_in[27];
    const float* out_W  = (const float*)d_in[28];
    const float* out_b  = (const float*)d_in[29];
    float* out = (float*)d_out;

    void* sp; cudaGetSymbolAddress(&sp, d_scratch);
    float* S0 = (float*)sp;
    float* A4 = S0;
    float* kp  = A4 + 16777216ull;
    float* vp  = kp + 4096;
    float* bkr = vp + 4096;
    float* bvr = bkr + 1024;
    __half* xh     = (__half*)(bvr + 1024);
    __half* qkvh   = xh     + 16777216ull;
    __half* kvrh   = qkvh   + 50331648ull;
    __half* A3h    = kvrh   + 33554432ull;
    __half* A5h    = A3h    + 16777216ull;
    __half* uh     = A5h    + 16777216ull;
    __half* m2ah   = uh     + 16777216ull;
    __half* m2h    = m2ah   + 2097152ull;
    __half* Wallh  = m2h    + 2097152ull;
    __half* Wkrvh  = Wallh  + 3145728ull;
    __half* W1qh   = Wkrvh  + 262144ull;
    __half* W2h    = W1qh   + 131072ull;
    __half* Woh    = W2h    + 16384ull;
    __half* gateh  = Woh    + 1048576ull;
    __half* outh   = gateh  + 1048576ull;
    __half* mWq_h  = outh   + 1048576ull;
    __half* mWk_h  = mWq_h  + 1048576ull;
    __half* mWv_h  = mWk_h  + 1048576ull;
    __half* memW1h = mWv_h  + 1048576ull;
    __half* Wq_h   = memW1h + 131072ull;
    __half* Wk_h   = Wq_h   + 1048576ull;
    __half* Wv_h   = Wk_h   + 1048576ull;
    __half* moW_h  = Wv_h   + 1048576ull;
    __half* WkKh   = Wallh  + 1048576ull;
    __half* WvVh   = Wallh  + 2097152ull;

    cudaFuncSetAttribute(wall_prep_h_kernel, cudaFuncAttributeMaxDynamicSharedMemorySize, GSM_NT);
    cudaFuncSetAttribute(wkrv_prep_h_kernel, cudaFuncAttributeMaxDynamicSharedMemorySize, GSM_NT);
    cudaFuncSetAttribute(memnet_kernel<1,0>, cudaFuncAttributeMaxDynamicSharedMemorySize, GSM);
    cudaFuncSetAttribute(memnet_kernel<0,1>, cudaFuncAttributeMaxDynamicSharedMemorySize, GSM);
    cudaFuncSetAttribute(gemm_o2_kernel<0>,  cudaFuncAttributeMaxDynamicSharedMemorySize, GSM_O2);
    cudaFuncSetAttribute(gemm_o2_kernel<1>,  cudaFuncAttributeMaxDynamicSharedMemorySize, GSM_O2);
    cudaFuncSetAttribute(gemm_o2_kernel<3>,  cudaFuncAttributeMaxDynamicSharedMemorySize, GSM_O2);
    cudaFuncSetAttribute(gemm_o2_kernel<4>,  cudaFuncAttributeMaxDynamicSharedMemorySize, GSM_O2);
    cudaFuncSetAttribute(attn_kernel,        cudaFuncAttributeMaxDynamicSharedMemorySize, ATTN_SMEM);

    dim3 blk(256);

    // 1) one batched convert for all f32->f16 inputs
    ConvBatch cb;
    cb.src[0] = x;      cb.dst[0] = xh;     cb.n[0] = 16777216u;
    cb.src[1] = mem_W2; cb.dst[1] = W2h;    cb.n[1] = 16384u;
    cb.src[2] = mha_Wo; cb.dst[2] = Woh;    cb.n[2] = 1048576u;
    cb.src[3] = gate_W; cb.dst[3] = gateh;  cb.n[3] = 1048576u;
    cb.src[4] = out_W;  cb.dst[4] = outh;   cb.n[4] = 1048576u;
    cb.src[5] = mha_Wq; cb.dst[5] = mWq_h;  cb.n[5] = 1048576u;
    cb.src[6] = mha_Wk; cb.dst[6] = mWk_h;  cb.n[6] = 1048576u;
    cb.src[7] = mha_Wv; cb.dst[7] = mWv_h;  cb.n[7] = 1048576u;
    cb.src[8] = mem_W1; cb.dst[8] = memW1h; cb.n[8] = 131072u;
    cb.src[9] = Wq;     cb.dst[9] = Wq_h;   cb.n[9] = 1048576u;
    cb.src[10] = Wk;    cb.dst[10] = Wk_h;  cb.n[10] = 1048576u;
    cb.src[11] = Wv;    cb.dst[11] = Wv_h;  cb.n[11] = 1048576u;
    cb.src[12] = mem_oW; cb.dst[12] = moW_h; cb.n[12] = 131072u;
    conv_batch_kernel<<<dim3(1024, 13), blk>>>(cb);

    // 2-3) fp16 weight prep
    wall_prep_h_kernel<<<dim3(8,25), blk, GSM_NT>>>(mWq_h, mWk_h, mWv_h, memW1h,
                                                    Wq_h, Wk_h, Wv_h, Wallh, W1qh);
    wkrv_prep_h_kernel<<<dim3(1,16), blk, GSM_NT>>>(Wallh, moW_h, Wkrvh);

    // 4-5) memory net fused
    memnet_kernel<1,0><<<dim3(1,128), blk, GSM>>>(xh, W1qh, mem_b1, ln1_g, ln1_b,
                                                  nullptr, m2ah, 1024);
    memnet_kernel<0,1><<<dim3(1,128), blk, GSM>>>(m2ah, W2h, mem_b2, ln2_g, ln2_b,
                                                  mstate, m2h, 128);

    // 6-7) fused q|k|v + retrieved k|v (occ-2 GEMM, half outputs)
    gemm_o2_kernel<1><<<dim3(24,128), blk, GSM_O2>>>(xh,  Wallh, qkvh, nullptr, nullptr, nullptr, 16384, 3072, 1024);
    gemm_o2_kernel<1><<<dim3(16,128), blk, GSM_O2>>>(m2h, Wkrvh, kvrh, nullptr, nullptr, nullptr, 16384, 2048, 128);

    // 8-9) per-head constants
    fuse_bias_kernel<<<2048, 256>>>(WkKh, WvVh, mem_ob, mha_bk, mha_bv, bkr, bvr);
    pm_proj_kernel<<<8192, 256>>>(pm, WkKh, WvVh, mha_bk, mha_bv, kp, vp);

    // 10) attention
    attn_kernel<<<dim3(256, 8), 256, ATTN_SMEM>>>(qkvh, kvrh, kp, vp,
                                                  mha_bq, mha_bk, bkr, mha_bv, bvr, A3h);

    // 11-14) output path
    gemm_o2_kernel<0><<<dim3(8,128), blk, GSM_O2>>>(A3h, Woh, A4, nullptr, nullptr, nullptr, 16384, 1024, 1024);
    biasln_c_kernel<<<16384, 256>>>(A4, mha_bo, gn_g, gn_b, A5h);
    gemm_o2_kernel<3><<<dim3(8,128), blk, GSM_O2>>>(A5h, gateh, uh, gate_b, A4, x, 16384, 1024, 1024);
    gemm_o2_kernel<4><<<dim3(8,128), blk, GSM_O2>>>(uh, outh, out, out_b, nullptr, nullptr, 16384, 1024, 1024);
}

// round 11
// speedup vs baseline: 1.2923x; 1.0085x over previous
#include <cuda_runtime.h>
#include <cuda_fp16.h>
#include <mma.h>
#include <cstdint>

using namespace nvcuda;

// B=4, L=4096, C=1024, M=128, P=4, S=64, H=8, hd=128
// NSEG=256, TOKS=16384, context T=132

__device__ float d_scratch[162100000ull];

__device__ __forceinline__ void cp16(uint32_t s, const void* g) {
    asm volatile("cp.async.cg.shared.global [%0], [%1], 16;\n" :: "r"(s), "l"(g) : "memory");
}

// ===========================================================================
// batched f32 -> f16 convert (13 tensors in one launch)
// ===========================================================================
struct ConvBatch {
    const float* src[13];
    __half*      dst[13];
    unsigned     n[13];
};

__global__ __launch_bounds__(256)
void conv_batch_kernel(ConvBatch cb)
{
    int t = blockIdx.y;
    size_t n = cb.n[t];
    const float* in = cb.src[t];
    __half* out = cb.dst[t];
    for (size_t i = ((size_t)blockIdx.x*256 + threadIdx.x)*4; i < n;
         i += (size_t)gridDim.x*256*4) {
        float4 v = *reinterpret_cast<const float4*>(in + i);
        __half2 o2[2];
        o2[0] = __floats2half2_rn(v.x, v.y);
        o2[1] = __floats2half2_rn(v.z, v.w);
        *reinterpret_cast<float2*>(out + i) = *reinterpret_cast<float2*>(o2);
    }
}

// ===========================================================================
// fp16 NT GEMM weight prep: C(half) = A[M,K](K-major) @ B[K,N](row-major)
// 128x128 tile, Ktile 64, 3 stages -> 107520 B smem, 2 CTAs/SM
// ===========================================================================
#define NT_AS 9216
#define NT_BS 8704
#define GSM_NT (3*(NT_AS + NT_BS)*2)

__device__ void gemm_nt_h_body(const __half* __restrict__ A, const __half* __restrict__ B,
                               __half* __restrict__ C, int N, int K,
                               int am0, int n0, int cm0)
{
    extern __shared__ __align__(16) __half smh[];
    __half* As = smh;
    __half* Bs = smh + 3*NT_AS;

    const int tid  = threadIdx.x;
    const int warp = tid >> 5;
    const int lane = tid & 31;
    const int wm   = warp & 3;
    const int wn   = warp >> 2;
    const int nk   = K >> 6;

    auto load = [&](int it, int s) {
        const __half* Ag = A + (size_t)am0*K + it*64;
        const __half* Bg = B + (size_t)(it*64)*N + n0;
        uint32_t sA = (uint32_t)__cvta_generic_to_shared(As + s*NT_AS);
        uint32_t sB = (uint32_t)__cvta_generic_to_shared(Bs + s*NT_BS);
        #pragma unroll
        for (int i = 0; i < 4; i++) {
            int ch = tid + i*256;
            int r = ch >> 3, c = (ch & 7) << 3;
            cp16(sA + (uint32_t)(r*72 + c)*2u, Ag + (size_t)r*K + c);
            int kk = ch >> 4, c2 = (ch & 15) << 3;
            cp16(sB + (uint32_t)(kk*136 + c2)*2u, Bg + (size_t)kk*N + c2);
        }
    };

    wmma::fragment<wmma::accumulator,16,16,16,float> cf[2][4];
    #pragma unroll
    for (int i = 0; i < 2; i++)
        #pragma unroll
        for (int j = 0; j < 4; j++)
            wmma::fill_fragment(cf[i][j], 0.0f);

    #pragma unroll
    for (int s = 0; s < 2; s++) {
        if (s < nk) load(s, s);
        asm volatile("cp.async.commit_group;\n" ::: "memory");
    }

    for (int it = 0; it < nk; it++) {
        if (it + 2 < nk) load(it + 2, (it + 2) % 3);
        asm volatile("cp.async.commit_group;\n" ::: "memory");
        asm volatile("cp.async.wait_group 2;\n" ::: "memory");
        __syncthreads();

        int cs = it % 3;
        const __half* Ab = As + cs*NT_AS;
        const __half* Bb = Bs + cs*NT_BS;
        #pragma unroll
        for (int kk = 0; kk < 64; kk += 16) {
            wmma::fragment<wmma::matrix_a,16,16,16,__half,wmma::row_major> af[2];
            wmma::fragment<wmma::matrix_b,16,16,16,__half,wmma::row_major> bf[4];
            #pragma unroll
            for (int i = 0; i < 2; i++)
                wmma::load_matrix_sync(af[i], Ab + (wm*32 + i*16)*72 + kk, 72);
            #pragma unroll
            for (int j = 0; j < 4; j++)
                wmma::load_matrix_sync(bf[j], Bb + kk*136 + wn*64 + j*16, 136);
            #pragma unroll
            for (int i = 0; i < 2; i++)
                #pragma unroll
                for (int j = 0; j < 4; j++)
                    wmma::mma_sync(cf[i][j], af[i], bf[j], cf[i][j]);
        }
        __syncthreads();
    }

    float* stage = reinterpret_cast<float*>(smh) + warp*256;
    #pragma unroll
    for (int i = 0; i < 2; i++)
        #pragma unroll
        for (int j = 0; j < 4; j++) {
            wmma::store_matrix_sync(stage, cf[i][j], 16, wmma::mem_row_major);
            __syncwarp();
            int mb = cm0 + wm*32 + i*16;
            int nb = n0 + wn*64 + j*16;
            #pragma unroll
            for (int e = lane; e < 256; e += 32) {
                int rr = e >> 4, cc = e & 15;
                C[(size_t)(mb + rr)*N + nb + cc] = __float2half(stage[e]);
            }
            __syncwarp();
        }
}

__global__ __launch_bounds__(256, 2)
void wall_prep_h_kernel(const __half* mWq, const __half* mWk, const __half* mWv,
                        const __half* memW1,
                        const __half* Wq, const __half* Wk, const __half* Wv,
                        __half* Wallh, __half* W1qh)
{
    int by = blockIdx.y;
    const __half *A, *B; __half* Cb; int am0;
    if (by < 8)       { A = mWq;   B = Wq; Cb = Wallh;            am0 = by*128; }
    else if (by < 16) { A = mWk;   B = Wk; Cb = Wallh + 1048576;  am0 = (by-8)*128; }
    else if (by < 24) { A = mWv;   B = Wv; Cb = Wallh + 2097152;  am0 = (by-16)*128; }
    else              { A = memW1; B = Wq; Cb = W1qh;             am0 = 0; }
    gemm_nt_h_body(A, B, Cb, 1024, 1024, am0, blockIdx.x*128, am0);
}

__global__ __launch_bounds__(256, 2)
void wkrv_prep_h_kernel(const __half* Wallh, const __half* moW, __half* Wkrvh)
{
    int by = blockIdx.y;
    const __half* A = (by < 8) ? (Wallh + 1048576) : (Wallh + 2097152);
    int am0 = (by & 7)*128;
    gemm_nt_h_body(A, moW, Wkrvh, 128, 1024, am0, 0, by*128);
}

// ===========================================================================
// shared tile loader: 128x64 halves (row stride 72)
// ===========================================================================
#define HLD 72
#define HSTS 9216

__device__ __forceinline__ void load_tile_h(const __half* Ag0, const __half* Wg0,
                                            int K, int it, __half* As, __half* Bs, int tid)
{
    const __half* Ag = Ag0 + it*64;
    const __half* Wg = Wg0 + it*64;
    uint32_t sA = (uint32_t)__cvta_generic_to_shared(As);
    uint32_t sB = (uint32_t)__cvta_generic_to_shared(Bs);
    #pragma unroll
    for (int i = 0; i < 4; i++) {
        int ch = tid + i*256;
        int r = ch >> 3, c = (ch & 7) << 3;
        cp16(sA + (uint32_t)(r*HLD + c)*2u, Ag + (size_t)r*K + c);
        cp16(sB + (uint32_t)(r*HLD + c)*2u, Wg + (size_t)r*K + c);
    }
}

// ===========================================================================
// memory-net fused GEMM + bias (+silu) + LayerNorm (+mstate): N=128
// 3-stage, 110592 B smem -> 2 CTAs/SM
// ===========================================================================
#define GSM_MN (3*2*HSTS*2)

template<int DO_SILU, int ADD_MSTATE>
__global__ __launch_bounds__(256, 2)
void memnet_kernel(const __half* __restrict__ A, const __half* __restrict__ W,
                   const float* __restrict__ bias,
                   const float* __restrict__ g, const float* __restrict__ b,
                   const float* __restrict__ mstate,
                   __half* __restrict__ out, int K)
{
    extern __shared__ __align__(16) __half smh[];
    __half* As = smh;
    __half* Bs = smh + 3*HSTS;

    const int tid  = threadIdx.x;
    const int warp = tid >> 5;
    const int lane = tid & 31;
    const int wm   = warp & 3;
    const int wn   = warp >> 2;
    const int m0   = blockIdx.y * 128;
    const int nk   = K >> 6;

    const __half* Ag0 = A + (size_t)m0*K;

    wmma::fragment<wmma::accumulator,16,16,16,float> cf[2][4];
    #pragma unroll
    for (int i = 0; i < 2; i++)
        #pragma unroll
        for (int j = 0; j < 4; j++)
            wmma::fill_fragment(cf[i][j], 0.0f);

    #pragma unroll
    for (int s = 0; s < 2; s++) {
        if (s < nk) load_tile_h(Ag0, W, K, s, As + s*HSTS, Bs + s*HSTS, tid);
        asm volatile("cp.async.commit_group;\n" ::: "memory");
    }

    for (int it = 0; it < nk; it++) {
        if (it + 2 < nk) {
            int slot = (it + 2) % 3;
            load_tile_h(Ag0, W, K, it + 2, As + slot*HSTS, Bs + slot*HSTS, tid);
        }
        asm volatile("cp.async.commit_group;\n" ::: "memory");
        asm volatile("cp.async.wait_group 2;\n" ::: "memory");
        __syncthreads();

        int cs = it % 3;
        const __half* Ab = As + cs*HSTS;
        const __half* Bb = Bs + cs*HSTS;
        #pragma unroll
        for (int kk = 0; kk < 64; kk += 16) {
            wmma::fragment<wmma::matrix_a,16,16,16,__half,wmma::row_major> af[2];
            wmma::fragment<wmma::matrix_b,16,16,16,__half,wmma::col_major> bf[4];
            #pragma unroll
            for (int i = 0; i < 2; i++)
                wmma::load_matrix_sync(af[i], Ab + (wm*32 + i*16)*HLD + kk, HLD);
            #pragma unroll
            for (int j = 0; j < 4; j++)
                wmma::load_matrix_sync(bf[j], Bb + (wn*64 + j*16)*HLD + kk, HLD);
            #pragma unroll
            for (int i = 0; i < 2; i++)
                #pragma unroll
                for (int j = 0; j < 4; j++)
                    wmma::mma_sync(cf[i][j], af[i], bf[j], cf[i][j]);
        }
        __syncthreads();
    }

    float* tile = reinterpret_cast<float*>(smh);
    #pragma unroll
    for (int i = 0; i < 2; i++)
        #pragma unroll
        for (int j = 0; j < 4; j++)
            wmma::store_matrix_sync(tile + (wm*32 + i*16)*132 + wn*64 + j*16,
                                    cf[i][j], 132, wmma::mem_row_major);
    __syncthreads();

    float bb4[4], gg4[4], b24[4], ms4[4];
    *reinterpret_cast<float4*>(bb4) = *reinterpret_cast<const float4*>(bias + lane*4);
    *reinterpret_cast<float4*>(gg4) = *reinterpret_cast<const float4*>(g + lane*4);
    *reinterpret_cast<float4*>(b24) = *reinterpret_cast<const float4*>(b + lane*4);
    if (ADD_MSTATE)
        *reinterpret_cast<float4*>(ms4) = *reinterpret_cast<const float4*>(mstate + lane*4);

    #pragma unroll
    for (int rr = 0; rr < 16; rr++) {
        int row = warp*16 + rr;
        float4 v4 = *reinterpret_cast<const float4*>(tile + row*132 + lane*4);
        float t[4] = {v4.x + bb4[0], v4.y + bb4[1], v4.z + bb4[2], v4.w + bb4[3]};
        if (DO_SILU) {
            #pragma unroll
            for (int e = 0; e < 4; e++) t[e] = t[e] / (1.0f + __expf(-t[e]));
        }
        float s = t[0]+t[1]+t[2]+t[3];
        float q = t[0]*t[0]+t[1]*t[1]+t[2]*t[2]+t[3]*t[3];
        #pragma unroll
        for (int o = 16; o; o >>= 1) {
            s += __shfl_xor_sync(0xffffffffu, s, o);
            q += __shfl_xor_sync(0xffffffffu, q, o);
        }
        float mu  = s * (1.0f/128.0f);
        float var = q * (1.0f/128.0f) - mu*mu;
        float rs  = rsqrtf(var + 1e-5f);
        __half2 o2[2];
        float o0 = gg4[0]*(t[0]-mu)*rs + b24[0];
        float o1 = gg4[1]*(t[1]-mu)*rs + b24[1];
        float o2f = gg4[2]*(t[2]-mu)*rs + b24[2];
        float o3 = gg4[3]*(t[3]-mu)*rs + b24[3];
        if (ADD_MSTATE) { o0 += ms4[0]; o1 += ms4[1]; o2f += ms4[2]; o3 += ms4[3]; }
        o2[0] = __floats2half2_rn(o0, o1);
        o2[1] = __floats2half2_rn(o2f, o3);
        *reinterpret_cast<float2*>(out + (size_t)(m0 + row)*128 + lane*4) =
            *reinterpret_cast<float2*>(o2);
    }
}

// ===========================================================================
// main-path GEMM, occupancy-2: 128x128 CTA tile, 32x64 warp tile, Ktile 64,
// 3 stages (110592 B smem -> 2 CTAs/SM).
// MODE 0: f32 direct store. MODE 1: half out.
// MODE 3: gate fusion u = sigmoid(acc+bias)*aux1h + aux2 -> half
// MODE 4: f32 + bias
// ===========================================================================
#define GSM_O2 (3*2*HSTS*2)

template<int MODE>
__global__ __launch_bounds__(256, 2)
void gemm_o2_kernel(const __half* __restrict__ A, const __half* __restrict__ W,
                    void* __restrict__ Cout, const float* __restrict__ bias,
                    const __half* __restrict__ aux1h, const float* __restrict__ aux2,
                    int M, int N, int K)
{
    extern __shared__ __align__(16) __half smh[];
    __half* As = smh;
    __half* Bs = smh + 3*HSTS;

    const int tid  = threadIdx.x;
    const int warp = tid >> 5;
    const int lane = tid & 31;
    const int wm   = warp & 3;
    const int wn   = warp >> 2;
    const int m0   = blockIdx.y * 128;
    const int n0   = blockIdx.x * 128;
    const int nk   = K >> 6;

    const __half* Ag0 = A + (size_t)m0*K;
    const __half* Wg0 = W + (size_t)n0*K;

    wmma::fragment<wmma::accumulator,16,16,16,float> cf[2][4];
    #pragma unroll
    for (int i = 0; i < 2; i++)
        #pragma unroll
        for (int j = 0; j < 4; j++)
            wmma::fill_fragment(cf[i][j], 0.0f);

    #pragma unroll
    for (int s = 0; s < 2; s++) {
        if (s < nk) load_tile_h(Ag0, Wg0, K, s, As + s*HSTS, Bs + s*HSTS, tid);
        asm volatile("cp.async.commit_group;\n" ::: "memory");
    }

    for (int it = 0; it < nk; it++) {
        if (it + 2 < nk) {
            int slot = (it + 2) % 3;
            load_tile_h(Ag0, Wg0, K, it + 2, As + slot*HSTS, Bs + slot*HSTS, tid);
        }
        asm volatile("cp.async.commit_group;\n" ::: "memory");
        asm volatile("cp.async.wait_group 2;\n" ::: "memory");
        __syncthreads();

        int cs = it % 3;
        const __half* Ab = As + cs*HSTS;
        const __half* Bb = Bs + cs*HSTS;
        #pragma unroll
        for (int kk = 0; kk < 64; kk += 16) {
            wmma::fragment<wmma::matrix_a,16,16,16,__half,wmma::row_major> af[2];
            wmma::fragment<wmma::matrix_b,16,16,16,__half,wmma::col_major> bf[4];
            #pragma unroll
            for (int i = 0; i < 2; i++)
                wmma::load_matrix_sync(af[i], Ab + (wm*32 + i*16)*HLD + kk, HLD);
            #pragma unroll
            for (int j = 0; j < 4; j++)
                wmma::load_matrix_sync(bf[j], Bb + (wn*64 + j*16)*HLD + kk, HLD);
            #pragma unroll
            for (int i = 0; i < 2; i++)
                #pragma unroll
                for (int j = 0; j < 4; j++)
                    wmma::mma_sync(cf[i][j], af[i], bf[j], cf[i][j]);
        }
        __syncthreads();
    }

    if (MODE == 0) {
        float* Cf = (float*)Cout;
        #pragma unroll
        for (int i = 0; i < 2; i++)
            #pragma unroll
            for (int j = 0; j < 4; j++)
                wmma::store_matrix_sync(&Cf[(size_t)(m0 + wm*32 + i*16)*N + n0 + wn*64 + j*16],
                                        cf[i][j], N, wmma::mem_row_major);
    } else {
        float* stage = reinterpret_cast<float*>(smh) + warp*256;
        #pragma unroll
        for (int i = 0; i < 2; i++)
            #pragma unroll
            for (int j = 0; j < 4; j++) {
                wmma::store_matrix_sync(stage, cf[i][j], 16, wmma::mem_row_major);
                __syncwarp();
                int mb = m0 + wm*32 + i*16;
                int nb = n0 + wn*64 + j*16;
                #pragma unroll
                for (int e = lane; e < 256; e += 32) {
                    int rr = e >> 4, cc = e & 15;
                    float v = stage[e];
                    size_t base = (size_t)(mb + rr)*N + nb + cc;
                    if (MODE == 1) {
                        ((__half*)Cout)[base] = __float2half(v);
                    } else if (MODE == 3) {
                        float gg = 1.0f / (1.0f + __expf(-(v + bias[nb + cc])));
                        ((__half*)Cout)[base] =
                            __float2half(gg*__half2float(aux1h[base]) + aux2[base]);
                    } else {  // MODE 4
                        ((float*)Cout)[base] = v + bias[nb + cc];
                    }
                }
                __syncwarp();
            }
    }
}

// ===========================================================================
// small kernels
// ===========================================================================
// bias + LN over C=1024: reads f32 a, writes biased half (ab) + LN half (lo)
__global__ __launch_bounds__(256)
void biasln_c_kernel(const float* __restrict__ a, const float* __restrict__ bo,
                     const float* __restrict__ g, const float* __restrict__ b,
                     __half* __restrict__ ab, __half* __restrict__ lo)
{
    size_t base = (size_t)blockIdx.x * 1024;
    int t = threadIdx.x;
    float4 v  = *reinterpret_cast<const float4*>(a + base + t*4);
    float4 bb = *reinterpret_cast<const float4*>(bo + t*4);
    v.x += bb.x; v.y += bb.y; v.z += bb.z; v.w += bb.w;
    {
        __half2 o2[2];
        o2[0] = __floats2half2_rn(v.x, v.y);
        o2[1] = __floats2half2_rn(v.z, v.w);
        *reinterpret_cast<float2*>(ab + base + t*4) = *reinterpret_cast<float2*>(o2);
    }

    float s = v.x + v.y + v.z + v.w;
    float q = v.x*v.x + v.y*v.y + v.z*v.z + v.w*v.w;
    #pragma unroll
    for (int o = 16; o; o >>= 1) {
        s += __shfl_xor_sync(0xffffffffu, s, o);
        q += __shfl_xor_sync(0xffffffffu, q, o);
    }
    __shared__ float red[16];
    if ((t & 31) == 0) { red[t>>5] = s; red[8 + (t>>5)] = q; }
    __syncthreads();
    float S = 0.f, Q = 0.f;
    #pragma unroll
    for (int i = 0; i < 8; i++) { S += red[i]; Q += red[8+i]; }
    float mu  = S * (1.0f/1024.0f);
    float var = Q * (1.0f/1024.0f) - mu*mu;
    float rs  = rsqrtf(var + 1e-5f);

    float4 gg = *reinterpret_cast<const float4*>(g + t*4);
    float4 b2 = *reinterpret_cast<const float4*>(b + t*4);
    __half2* o = reinterpret_cast<__half2*>(lo + base + t*4);
    o[0] = __floats2half2_rn(gg.x*(v.x - mu)*rs + b2.x, gg.y*(v.y - mu)*rs + b2.y);
    o[1] = __floats2half2_rn(gg.z*(v.z - mu)*rs + b2.z, gg.w*(v.w - mu)*rs + b2.w);
}

__global__ __launch_bounds__(256)
void fuse_bias_kernel(const __half* __restrict__ WkKh, const __half* __restrict__ WvVh,
                      const float* __restrict__ mob,
                      const float* __restrict__ bk, const float* __restrict__ bv,
                      float* __restrict__ bkr, float* __restrict__ bvr)
{
    int i = blockIdx.x & 1023;
    bool isv = blockIdx.x >= 1024;
    const __half* W = isv ? WvVh : WkKh;
    float s = 0.f;
    for (int k = threadIdx.x; k < 1024; k += 256)
        s += __half2float(W[(size_t)i*1024 + k]) * mob[k];
    #pragma unroll
    for (int o = 16; o; o >>= 1) s += __shfl_xor_sync(0xffffffffu, s, o);
    __shared__ float red[8];
    if ((threadIdx.x & 31) == 0) red[threadIdx.x >> 5] = s;
    __syncthreads();
    if (threadIdx.x == 0) {
        float S = 0.f;
        #pragma unroll
        for (int w = 0; w < 8; w++) S += red[w];
        (isv ? bvr : bkr)[i] = S + (isv ? bv : bk)[i];
    }
}

__global__ __launch_bounds__(256)
void pm_proj_kernel(const float* __restrict__ pm,
                    const __half* __restrict__ WkKh, const __half* __restrict__ WvVh,
                    const float* __restrict__ bk, const float* __restrict__ bv,
                    float* __restrict__ kp, float* __restrict__ vp)
{
    int id  = blockIdx.x;
    bool isv = id >= 4096;
    int p = (id & 4095) >> 10;
    int i = id & 1023;
    const __half* W = isv ? WvVh : WkKh;
    float s = 0.f;
    for (int k = threadIdx.x; k < 1024; k += 256)
        s += pm[p*1024 + k] * __half2float(W[(size_t)i*1024 + k]);
    #pragma unroll
    for (int o = 16; o; o >>= 1) s += __shfl_xor_sync(0xffffffffu, s, o);
    __shared__ float red[8];
    if ((threadIdx.x & 31) == 0) red[threadIdx.x >> 5] = s;
    __syncthreads();
    if (threadIdx.x == 0) {
        float S = 0.f;
        #pragma unroll
        for (int w = 0; w < 8; w++) S += red[w];
        (isv ? vp : kp)[p*1024 + i] = S + (isv ? bv : bk)[i];
    }
}

// ===========================================================================
// fp16 attention: block per (segment, head); 8 warps; half in, half out
// ===========================================================================
#define PS_LD 148
#define QK_LD 136
#define PH_LD 152
#define ATTN_SMEM (64*PS_LD*4 + (64*QK_LD + 144*QK_LD + 144*QK_LD + 64*PH_LD)*2)

__global__ __launch_bounds__(256)
void attn_kernel(const __half* __restrict__ qkv,
                 const __half* __restrict__ kvr,
                 const float* __restrict__ kp, const float* __restrict__ vp,
                 const float* __restrict__ bq, const float* __restrict__ bk,
                 const float* __restrict__ bkr,
                 const float* __restrict__ bv, const float* __restrict__ bvr,
                 __half* __restrict__ outh)
{
    extern __shared__ __align__(16) float sm[];
    float*  ps  = sm;
    __half* qsh = reinterpret_cast<__half*>(sm + 64*PS_LD);
    __half* ksh = qsh + 64*QK_LD;
    __half* vsh = ksh + 144*QK_LD;
    __half* ph  = vsh + 144*QK_LD;

    const int seg  = blockIdx.x;
    const int h    = blockIdx.y;
    const int tid  = threadIdx.x;
    const int warp = tid >> 5;
    const int lane = tid & 31;
    const int c0   = h * 128;
    const float scale = 0.08838834764831845f;

    for (int i = tid; i < 64*16; i += 256) {
        int r = i >> 4, c8 = (i & 15) << 3;
        float4 raw = *reinterpret_cast<const float4*>(qkv + (size_t)(seg*64 + r)*3072 + c0 + c8);
        const __half2* hp = reinterpret_cast<const __half2*>(&raw);
        float bv8[8];
        *reinterpret_cast<float4*>(bv8)     = *reinterpret_cast<const float4*>(bq + c0 + c8);
        *reinterpret_cast<float4*>(bv8 + 4) = *reinterpret_cast<const float4*>(bq + c0 + c8 + 4);
        __half2 o[4];
        #pragma unroll
        for (int t = 0; t < 4; t++) {
            float2 f = __half22float2(hp[t]);
            o[t] = __floats2half2_rn((f.x + bv8[2*t])*scale, (f.y + bv8[2*t+1])*scale);
        }
        *reinterpret_cast<float4*>(qsh + r*QK_LD + c8) = *reinterpret_cast<float4*>(o);
    }
    for (int i = tid; i < 144*16; i += 256) {
        int r = i >> 4, c8 = (i & 15) << 3;
        float vals[8] = {0,0,0,0,0,0,0,0};
        if (r < 64) {
            float4 raw = *reinterpret_cast<const float4*>(kvr + (size_t)(seg*64 + r)*2048 + c0 + c8);
            const __half2* hp = reinterpret_cast<const __half2*>(&raw);
            float b8[8];
            *reinterpret_cast<float4*>(b8)     = *reinterpret_cast<const float4*>(bkr + c0 + c8);
            *reinterpret_cast<float4*>(b8 + 4) = *reinterpret_cast<const float4*>(bkr + c0 + c8 + 4);
            #pragma unroll
            for (int t = 0; t < 4; t++) {
                float2 f = __half22float2(hp[t]);
                vals[2*t] = f.x + b8[2*t]; vals[2*t+1] = f.y + b8[2*t+1];
            }
        } else if (r < 68) {
            *reinterpret_cast<float4*>(vals)     = *reinterpret_cast<const float4*>(kp + (size_t)(r-64)*1024 + c0 + c8);
            *reinterpret_cast<float4*>(vals + 4) = *reinterpret_cast<const float4*>(kp + (size_t)(r-64)*1024 + c0 + c8 + 4);
        } else if (r < 132) {
            float4 raw = *reinterpret_cast<const float4*>(qkv + (size_t)(seg*64 + r - 68)*3072 + 1024 + c0 + c8);
            const __half2* hp = reinterpret_cast<const __half2*>(&raw);
            float b8[8];
            *reinterpret_cast<float4*>(b8)     = *reinterpret_cast<const float4*>(bk + c0 + c8);
            *reinterpret_cast<float4*>(b8 + 4) = *reinterpret_cast<const float4*>(bk + c0 + c8 + 4);
            #pragma unroll
            for (int t = 0; t < 4; t++) {
                float2 f = __half22float2(hp[t]);
                vals[2*t] = f.x + b8[2*t]; vals[2*t+1] = f.y + b8[2*t+1];
            }
        }
        __half2 o[4];
        #pragma unroll
        for (int t = 0; t < 4; t++) o[t] = __floats2half2_rn(vals[2*t], vals[2*t+1]);
        *reinterpret_cast<float4*>(ksh + r*QK_LD + c8) = *reinterpret_cast<float4*>(o);
    }
    for (int i = tid; i < 144*16; i += 256) {
        int r = i >> 4, c8 = (i & 15) << 3;
        float vals[8] = {0,0,0,0,0,0,0,0};
        if (r < 64) {
            float4 raw = *reinterpret_cast<const float4*>(kvr + (size_t)(seg*64 + r)*2048 + 1024 + c0 + c8);
            const __half2* hp = reinterpret_cast<const __half2*>(&raw);
            float b8[8];
            *reinterpret_cast<float4*>(b8)     = *reinterpret_cast<const float4*>(bvr + c0 + c8);
            *reinterpret_cast<float4*>(b8 + 4) = *reinterpret_cast<const float4*>(bvr + c0 + c8 + 4);
            #pragma unroll
            for (int t = 0; t < 4; t++) {
                float2 f = __half22float2(hp[t]);
                vals[2*t] = f.x + b8[2*t]; vals[2*t+1] = f.y + b8[2*t+1];
            }
        } else if (r < 68) {
            *reinterpret_cast<float4*>(vals)     = *reinterpret_cast<const float4*>(vp + (size_t)(r-64)*1024 + c0 + c8);
            *reinterpret_cast<float4*>(vals + 4) = *reinterpret_cast<const float4*>(vp + (size_t)(r-64)*1024 + c0 + c8 + 4);
        } else if (r < 132) {
            float4 raw = *reinterpret_cast<const float4*>(qkv + (size_t)(seg*64 + r - 68)*3072 + 2048 + c0 + c8);
            const __half2* hp = reinterpret_cast<const __half2*>(&raw);
            float b8[8];
            *reinterpret_cast<float4*>(b8)     = *reinterpret_cast<const float4*>(bv + c0 + c8);
            *reinterpret_cast<float4*>(b8 + 4) = *reinterpret_cast<const float4*>(bv + c0 + c8 + 4);
            #pragma unroll
            for (int t = 0; t < 4; t++) {
                float2 f = __half22float2(hp[t]);
                vals[2*t] = f.x + b8[2*t]; vals[2*t+1] = f.y + b8[2*t+1];
            }
        }
        __half2 o[4];
        #pragma unroll
        for (int t = 0; t < 4; t++) o[t] = __floats2half2_rn(vals[2*t], vals[2*t+1]);
        *reinterpret_cast<float4*>(vsh + r*QK_LD + c8) = *reinterpret_cast<float4*>(o);
    }
    __syncthreads();

    for (int t = warp; t < 36; t += 8) {
        int ms = (t / 9) * 16;
        int ns = (t % 9) * 16;
        wmma::fragment<wmma::accumulator,16,16,16,float> acc;
        wmma::fill_fragment(acc, 0.0f);
        #pragma unroll
        for (int kk = 0; kk < 128; kk += 16) {
            wmma::fragment<wmma::matrix_a,16,16,16,__half,wmma::row_major> af;
            wmma::fragment<wmma::matrix_b,16,16,16,__half,wmma::col_major> bf;
            wmma::load_matrix_sync(af, qsh + ms*QK_LD + kk, QK_LD);
            wmma::load_matrix_sync(bf, ksh + ns*QK_LD + kk, QK_LD);
            wmma::mma_sync(acc, af, bf, acc);
        }
        wmma::store_matrix_sync(ps + ms*PS_LD + ns, acc, PS_LD, wmma::mem_row_major);
    }
    __syncthreads();

    for (int r = warp*8; r < warp*8 + 8; r++) {
        float* row = ps + r*PS_LD;
        float m = -1e30f;
        for (int c = lane; c < 132; c += 32) m = fmaxf(m, row[c]);
        #pragma unroll
        for (int o = 16; o; o >>= 1) m = fmaxf(m, __shfl_xor_sync(0xffffffffu, m, o));
        float s = 0.f;
        for (int c = lane; c < 132; c += 32) { float e = __expf(row[c] - m); row[c] = e; s += e; }
        #pragma unroll
        for (int o = 16; o; o >>= 1) s += __shfl_xor_sync(0xffffffffu, s, o);
        float inv = 1.0f / s;
        for (int c = lane; c < 132; c += 32) ph[r*PH_LD + c] = __float2half(row[c]*inv);
        if (lane < 20) ph[r*PH_LD + 132 + lane] = __float2half(0.0f);
    }
    __syncthreads();

    for (int t = warp; t < 32; t += 8) {
        int ms = (t >> 3) * 16;
        int ds = (t & 7) * 16;
        wmma::fragment<wmma::accumulator,16,16,16,float> acc;
        wmma::fill_fragment(acc, 0.0f);
        #pragma unroll
        for (int kk = 0; kk < 144; kk += 16) {
            wmma::fragment<wmma::matrix_a,16,16,16,__half,wmma::row_major> af;
            wmma::fragment<wmma::matrix_b,16,16,16,__half,wmma::row_major> bf;
            wmma::load_matrix_sync(af, ph + ms*PH_LD + kk, PH_LD);
            wmma::load_matrix_sync(bf, vsh + kk*QK_LD + ds, QK_LD);
            wmma::mma_sync(acc, af, bf, acc);
        }
        wmma::store_matrix_sync(ps + ms*PS_LD + ds, acc, PS_LD, wmma::mem_row_major);
    }
    __syncthreads();

    for (int i = tid; i < 64*16; i += 256) {
        int r = i >> 4, c8 = (i & 15) << 3;
        const float* src = ps + r*PS_LD + c8;
        __half2 o[4];
        #pragma unroll
        for (int t = 0; t < 4; t++) o[t] = __floats2half2_rn(src[2*t], src[2*t+1]);
        *reinterpret_cast<float4*>(outh + (size_t)(seg*64 + r)*1024 + c0 + c8) =
            *reinterpret_cast<float4*>(o);
    }
}

// ===========================================================================
extern "C" void kernel_launch(void* const* d_in, const int* in_sizes, int n_in,
                              void* d_out, int out_size)
{
    const float* x      = (const float*)d_in[0];
    const float* pm     = (const float*)d_in[1];
    const float* Wq     = (const float*)d_in[2];
    const float* Wk     = (const float*)d_in[3];
    const float* Wv     = (const float*)d_in[4];
    const float* mem_W1 = (const float*)d_in[5];
    const float* mem_b1 = (const float*)d_in[6];
    const float* ln1_g  = (const float*)d_in[7];
    const float* ln1_b  = (const float*)d_in[8];
    const float* mem_W2 = (const float*)d_in[9];
    const float* mem_b2 = (const float*)d_in[10];
    const float* ln2_g  = (const float*)d_in[11];
    const float* ln2_b  = (const float*)d_in[12];
    const float* mem_oW = (const float*)d_in[13];
    const float* mem_ob = (const float*)d_in[14];
    const float* mstate = (const float*)d_in[15];
    const float* mha_Wq = (const float*)d_in[16];
    const float* mha_bq = (const float*)d_in[17];
    const float* mha_Wk = (const float*)d_in[18];
    const float* mha_bk = (const float*)d_in[19];
    const float* mha_Wv = (const float*)d_in[20];
    const float* mha_bv = (const float*)d_in[21];
    const float* mha_Wo = (const float*)d_in[22];
    const float* mha_bo = (const float*)d_in[23];
    const float* gn_g   = (const float*)d_in[24];
    const float* gn_b   = (const float*)d_in[25];
    const float* gate_W = (const float*)d_in[26];
    const float* gate_b = (const float*)d_in[27];
    const float* out_W  = (const float*)d_in[28];
    const float* out_b  = (const float*)d_in[29];
    float* out = (float*)d_out;

    void* sp; cudaGetSymbolAddress(&sp, d_scratch);
    float* S0 = (float*)sp;
    float* A4 = S0;                                     // [16384][1024] f32
    float* kp  = A4 + 16777216ull;
    float* vp  = kp + 4096;
    float* bkr = vp + 4096;
    float* bvr = bkr + 1024;
    __half* xh     = (__half*)(bvr + 1024);
    __half* qkvh   = xh     + 16777216ull;
    __half* kvrh   = qkvh   + 50331648ull;
    __half* A3h    = kvrh   + 33554432ull;
    __half* A4h    = A3h    + 16777216ull;              // biased attnp (half)
    __half* A5h    = A4h    + 16777216ull;
    __half* uh     = A5h    + 16777216ull;
    __half* m2ah   = uh     + 16777216ull;
    __half* m2h    = m2ah   + 2097152ull;
    __half* Wallh  = m2h    + 2097152ull;
    __half* Wkrvh  = Wallh  + 3145728ull;
    __half* W1qh   = Wkrvh  + 262144ull;
    __half* W2h    = W1qh   + 131072ull;
    __half* Woh    = W2h    + 16384ull;
    __half* gateh  = Woh    + 1048576ull;
    __half* outh   = gateh  + 1048576ull;
    __half* mWq_h  = outh   + 1048576ull;
    __half* mWk_h  = mWq_h  + 1048576ull;
    __half* mWv_h  = mWk_h  + 1048576ull;
    __half* memW1h = mWv_h  + 1048576ull;
    __half* Wq_h   = memW1h + 131072ull;
    __half* Wk_h   = Wq_h   + 1048576ull;
    __half* Wv_h   = Wk_h   + 1048576ull;
    __half* moW_h  = Wv_h   + 1048576ull;
    __half* WkKh   = Wallh  + 1048576ull;
    __half* WvVh   = Wallh  + 2097152ull;

    cudaFuncSetAttribute(wall_prep_h_kernel, cudaFuncAttributeMaxDynamicSharedMemorySize, GSM_NT);
    cudaFuncSetAttribute(wkrv_prep_h_kernel, cudaFuncAttributeMaxDynamicSharedMemorySize, GSM_NT);
    cudaFuncSetAttribute(memnet_kernel<1,0>, cudaFuncAttributeMaxDynamicSharedMemorySize, GSM_MN);
    cudaFuncSetAttribute(memnet_kernel<0,1>, cudaFuncAttributeMaxDynamicSharedMemorySize, GSM_MN);
    cudaFuncSetAttribute(gemm_o2_kernel<0>,  cudaFuncAttributeMaxDynamicSharedMemorySize, GSM_O2);
    cudaFuncSetAttribute(gemm_o2_kernel<1>,  cudaFuncAttributeMaxDynamicSharedMemorySize, GSM_O2);
    cudaFuncSetAttribute(gemm_o2_kernel<3>,  cudaFuncAttributeMaxDynamicSharedMemorySize, GSM_O2);
    cudaFuncSetAttribute(gemm_o2_kernel<4>,  cudaFuncAttributeMaxDynamicSharedMemorySize, GSM_O2);
    cudaFuncSetAttribute(attn_kernel,        cudaFuncAttributeMaxDynamicSharedMemorySize, ATTN_SMEM);

    dim3 blk(256);

    // 1) one batched convert for all f32->f16 inputs
    ConvBatch cb;
    cb.src[0] = x;      cb.dst[0] = xh;     cb.n[0] = 16777216u;
    cb.src[1] = mem_W2; cb.dst[1] = W2h;    cb.n[1] = 16384u;
    cb.src[2] = mha_Wo; cb.dst[2] = Woh;    cb.n[2] = 1048576u;
    cb.src[3] = gate_W; cb.dst[3] = gateh;  cb.n[3] = 1048576u;
    cb.src[4] = out_W;  cb.dst[4] = outh;   cb.n[4] = 1048576u;
    cb.src[5] = mha_Wq; cb.dst[5] = mWq_h;  cb.n[5] = 1048576u;
    cb.src[6] = mha_Wk; cb.dst[6] = mWk_h;  cb.n[6] = 1048576u;
    cb.src[7] = mha_Wv; cb.dst[7] = mWv_h;  cb.n[7] = 1048576u;
    cb.src[8] = mem_W1; cb.dst[8] = memW1h; cb.n[8] = 131072u;
    cb.src[9] = Wq;     cb.dst[9] = Wq_h;   cb.n[9] = 1048576u;
    cb.src[10] = Wk;    cb.dst[10] = Wk_h;  cb.n[10] = 1048576u;
    cb.src[11] = Wv;    cb.dst[11] = Wv_h;  cb.n[11] = 1048576u;
    cb.src[12] = mem_oW; cb.dst[12] = moW_h; cb.n[12] = 131072u;
    conv_batch_kernel<<<dim3(1024, 13), blk>>>(cb);

    // 2-3) fp16 weight prep (occ-2)
    wall_prep_h_kernel<<<dim3(8,25), blk, GSM_NT>>>(mWq_h, mWk_h, mWv_h, memW1h,
                                                    Wq_h, Wk_h, Wv_h, Wallh, W1qh);
    wkrv_prep_h_kernel<<<dim3(1,16), blk, GSM_NT>>>(Wallh, moW_h, Wkrvh);

    // 4-5) memory net fused (occ-2)
    memnet_kernel<1,0><<<dim3(1,128), blk, GSM_MN>>>(xh, W1qh, mem_b1, ln1_g, ln1_b,
                                                     nullptr, m2ah, 1024);
    memnet_kernel<0,1><<<dim3(1,128), blk, GSM_MN>>>(m2ah, W2h, mem_b2, ln2_g, ln2_b,
                                                     mstate, m2h, 128);

    // 6-7) fused q|k|v + retrieved k|v (occ-2 GEMM, half outputs)
    gemm_o2_kernel<1><<<dim3(24,128), blk, GSM_O2>>>(xh,  Wallh, qkvh, nullptr, nullptr, nullptr, 16384, 3072, 1024);
    gemm_o2_kernel<1><<<dim3(16,128), blk, GSM_O2>>>(m2h, Wkrvh, kvrh, nullptr, nullptr, nullptr, 16384, 2048, 128);

    // 8-9) per-head constants
    fuse_bias_kernel<<<2048, 256>>>(WkKh, WvVh, mem_ob, mha_bk, mha_bv, bkr, bvr);
    pm_proj_kernel<<<8192, 256>>>(pm, WkKh, WvVh, mha_bk, mha_bv, kp, vp);

    // 10) attention
    attn_kernel<<<dim3(256, 8), 256, ATTN_SMEM>>>(qkvh, kvrh, kp, vp,
                                                  mha_bq, mha_bk, bkr, mha_bv, bvr, A3h);

    // 11-14) output path
    gemm_o2_kernel<0><<<dim3(8,128), blk, GSM_O2>>>(A3h, Woh, A4, nullptr, nullptr, nullptr, 16384, 1024, 1024);
    biasln_c_kernel<<<16384, 256>>>(A4, mha_bo, gn_g, gn_b, A4h, A5h);
    gemm_o2_kernel<3><<<dim3(8,128), blk, GSM_O2>>>(A5h, gateh, uh, gate_b, A4h, x, 16384, 1024, 1024);
    gemm_o2_kernel<4><<<dim3(8,128), blk, GSM_O2>>>(uh, outh, out, out_b, nullptr, nullptr, 16384, 1024, 1024);
}

// round 13
// speedup vs baseline: 1.3927x; 1.0777x over previous
#include <cuda_runtime.h>
#include <cuda_fp16.h>
#include <mma.h>
#include <cstdint>

using namespace nvcuda;

// B=4, L=4096, C=1024, M=128, P=4, S=64, H=8, hd=128
// NSEG=256, TOKS=16384, context T=132

__device__ float d_scratch[162100000ull];

__device__ __forceinline__ void cp16(uint32_t s, const void* g) {
    asm volatile("cp.async.cg.shared.global [%0], [%1], 16;\n" :: "r"(s), "l"(g) : "memory");
}

// ===========================================================================
// batched f32 -> f16 convert (13 tensors in one launch)
// ===========================================================================
struct ConvBatch {
    const float* src[13];
    __half*      dst[13];
    unsigned     n[13];
};

__global__ __launch_bounds__(256)
void conv_batch_kernel(ConvBatch cb)
{
    int t = blockIdx.y;
    size_t n = cb.n[t];
    const float* in = cb.src[t];
    __half* out = cb.dst[t];
    for (size_t i = ((size_t)blockIdx.x*256 + threadIdx.x)*4; i < n;
         i += (size_t)gridDim.x*256*4) {
        float4 v = *reinterpret_cast<const float4*>(in + i);
        __half2 o2[2];
        o2[0] = __floats2half2_rn(v.x, v.y);
        o2[1] = __floats2half2_rn(v.z, v.w);
        *reinterpret_cast<float2*>(out + i) = *reinterpret_cast<float2*>(o2);
    }
}

// ===========================================================================
// fp16 NT GEMM weight prep: C(half) = A[M,K](K-major) @ B[K,N](row-major)
// 128x128 tile, Ktile 64, 3 stages, 2 CTAs/SM
// ===========================================================================
#define NT_AS 9216
#define NT_BS 8704
#define GSM_NT (3*(NT_AS + NT_BS)*2)

__device__ void gemm_nt_h_body(const __half* __restrict__ A, const __half* __restrict__ B,
                               __half* __restrict__ C, int N, int K,
                               int am0, int n0, int cm0)
{
    extern __shared__ __align__(16) __half smh[];
    __half* As = smh;
    __half* Bs = smh + 3*NT_AS;

    const int tid  = threadIdx.x;
    const int warp = tid >> 5;
    const int lane = tid & 31;
    const int wm   = warp & 3;
    const int wn   = warp >> 2;
    const int nk   = K >> 6;

    auto load = [&](int it, int s) {
        const __half* Ag = A + (size_t)am0*K + it*64;
        const __half* Bg = B + (size_t)(it*64)*N + n0;
        uint32_t sA = (uint32_t)__cvta_generic_to_shared(As + s*NT_AS);
        uint32_t sB = (uint32_t)__cvta_generic_to_shared(Bs + s*NT_BS);
        #pragma unroll
        for (int i = 0; i < 4; i++) {
            int ch = tid + i*256;
            int r = ch >> 3, c = (ch & 7) << 3;
            cp16(sA + (uint32_t)(r*72 + c)*2u, Ag + (size_t)r*K + c);
            int kk = ch >> 4, c2 = (ch & 15) << 3;
            cp16(sB + (uint32_t)(kk*136 + c2)*2u, Bg + (size_t)kk*N + c2);
        }
    };

    wmma::fragment<wmma::accumulator,16,16,16,float> cf[2][4];
    #pragma unroll
    for (int i = 0; i < 2; i++)
        #pragma unroll
        for (int j = 0; j < 4; j++)
            wmma::fill_fragment(cf[i][j], 0.0f);

    #pragma unroll
    for (int s = 0; s < 2; s++) {
        if (s < nk) load(s, s);
        asm volatile("cp.async.commit_group;\n" ::: "memory");
    }

    for (int it = 0; it < nk; it++) {
        if (it + 2 < nk) load(it + 2, (it + 2) % 3);
        asm volatile("cp.async.commit_group;\n" ::: "memory");
        asm volatile("cp.async.wait_group 2;\n" ::: "memory");
        __syncthreads();

        int cs = it % 3;
        const __half* Ab = As + cs*NT_AS;
        const __half* Bb = Bs + cs*NT_BS;
        #pragma unroll
        for (int kk = 0; kk < 64; kk += 16) {
            wmma::fragment<wmma::matrix_a,16,16,16,__half,wmma::row_major> af[2];
            wmma::fragment<wmma::matrix_b,16,16,16,__half,wmma::row_major> bf[4];
            #pragma unroll
            for (int i = 0; i < 2; i++)
                wmma::load_matrix_sync(af[i], Ab + (wm*32 + i*16)*72 + kk, 72);
            #pragma unroll
            for (int j = 0; j < 4; j++)
                wmma::load_matrix_sync(bf[j], Bb + kk*136 + wn*64 + j*16, 136);
            #pragma unroll
            for (int i = 0; i < 2; i++)
                #pragma unroll
                for (int j = 0; j < 4; j++)
                    wmma::mma_sync(cf[i][j], af[i], bf[j], cf[i][j]);
        }
        __syncthreads();
    }

    float* stage = reinterpret_cast<float*>(smh) + warp*256;
    #pragma unroll
    for (int i = 0; i < 2; i++)
        #pragma unroll
        for (int j = 0; j < 4; j++) {
            wmma::store_matrix_sync(stage, cf[i][j], 16, wmma::mem_row_major);
            __syncwarp();
            int mb = cm0 + wm*32 + i*16;
            int nb = n0 + wn*64 + j*16;
            #pragma unroll
            for (int e = lane; e < 256; e += 32) {
                int rr = e >> 4, cc = e & 15;
                C[(size_t)(mb + rr)*N + nb + cc] = __float2half(stage[e]);
            }
            __syncwarp();
        }
}

__global__ __launch_bounds__(256, 2)
void wall_prep_h_kernel(const __half* mWq, const __half* mWk, const __half* mWv,
                        const __half* memW1,
                        const __half* Wq, const __half* Wk, const __half* Wv,
                        __half* Wallh, __half* W1qh)
{
    int by = blockIdx.y;
    const __half *A, *B; __half* Cb; int am0;
    if (by < 8)       { A = mWq;   B = Wq; Cb = Wallh;            am0 = by*128; }
    else if (by < 16) { A = mWk;   B = Wk; Cb = Wallh + 1048576;  am0 = (by-8)*128; }
    else if (by < 24) { A = mWv;   B = Wv; Cb = Wallh + 2097152;  am0 = (by-16)*128; }
    else              { A = memW1; B = Wq; Cb = W1qh;             am0 = 0; }
    gemm_nt_h_body(A, B, Cb, 1024, 1024, am0, blockIdx.x*128, am0);
}

__global__ __launch_bounds__(256, 2)
void wkrv_prep_h_kernel(const __half* Wallh, const __half* moW, __half* Wkrvh)
{
    int by = blockIdx.y;
    const __half* A = (by < 8) ? (Wallh + 1048576) : (Wallh + 2097152);
    int am0 = (by & 7)*128;
    gemm_nt_h_body(A, moW, Wkrvh, 128, 1024, am0, 0, by*128);
}

// ===========================================================================
// shared tile loader: 128x64 halves (row stride 72)
// ===========================================================================
#define HLD 72
#define HSTS 9216

__device__ __forceinline__ void load_tile_h(const __half* Ag0, const __half* Wg0,
                                            int K, int it, __half* As, __half* Bs, int tid)
{
    const __half* Ag = Ag0 + it*64;
    const __half* Wg = Wg0 + it*64;
    uint32_t sA = (uint32_t)__cvta_generic_to_shared(As);
    uint32_t sB = (uint32_t)__cvta_generic_to_shared(Bs);
    #pragma unroll
    for (int i = 0; i < 4; i++) {
        int ch = tid + i*256;
        int r = ch >> 3, c = (ch & 7) << 3;
        cp16(sA + (uint32_t)(r*HLD + c)*2u, Ag + (size_t)r*K + c);
        cp16(sB + (uint32_t)(r*HLD + c)*2u, Wg + (size_t)r*K + c);
    }
}

// ===========================================================================
// memory-net fused GEMM + bias (+silu) + LayerNorm (+mstate)
// M-tile 64, N=128 full; warp tile 32x32; grid (1, 256); 3 stages
// stage: A 64x72h (4608h) + B 128x72h (9216h); smem 82944 B -> 2 CTAs/SM
// ===========================================================================
#define MN_AS 4608
#define MN_BS 9216
#define GSM_MN (3*(MN_AS + MN_BS)*2)

__device__ __forceinline__ void load_tile_mn(const __half* Ag0, const __half* Wg0,
                                             int K, int it, __half* As, __half* Bs, int tid)
{
    const __half* Ag = Ag0 + it*64;
    const __half* Wg = Wg0 + it*64;
    uint32_t sA = (uint32_t)__cvta_generic_to_shared(As);
    uint32_t sB = (uint32_t)__cvta_generic_to_shared(Bs);
    #pragma unroll
    for (int i = 0; i < 2; i++) {
        int ch = tid + i*256;                 // 512 chunks: 64 rows x 8
        int r = ch >> 3, c = (ch & 7) << 3;
        cp16(sA + (uint32_t)(r*HLD + c)*2u, Ag + (size_t)r*K + c);
    }
    #pragma unroll
    for (int i = 0; i < 4; i++) {
        int ch = tid + i*256;                 // 1024 chunks: 128 rows x 8
        int r = ch >> 3, c = (ch & 7) << 3;
        cp16(sB + (uint32_t)(r*HLD + c)*2u, Wg + (size_t)r*K + c);
    }
}

template<int DO_SILU, int ADD_MSTATE>
__global__ __launch_bounds__(256, 2)
void memnet_kernel(const __half* __restrict__ A, const __half* __restrict__ W,
                   const float* __restrict__ bias,
                   const float* __restrict__ g, const float* __restrict__ b,
                   const float* __restrict__ mstate,
                   __half* __restrict__ out, int K)
{
    extern __shared__ __align__(16) __half smh[];
    __half* As = smh;
    __half* Bs = smh + 3*MN_AS;

    const int tid  = threadIdx.x;
    const int warp = tid >> 5;
    const int lane = tid & 31;
    const int wm   = warp >> 2;   // 2 m-groups of 32
    const int wn   = warp & 3;    // 4 n-groups of 32
    const int m0   = blockIdx.y * 64;
    const int nk   = K >> 6;

    const __half* Ag0 = A + (size_t)m0*K;

    wmma::fragment<wmma::accumulator,16,16,16,float> cf[2][2];
    #pragma unroll
    for (int i = 0; i < 2; i++)
        #pragma unroll
        for (int j = 0; j < 2; j++)
            wmma::fill_fragment(cf[i][j], 0.0f);

    #pragma unroll
    for (int s = 0; s < 2; s++) {
        if (s < nk) load_tile_mn(Ag0, W, K, s, As + s*MN_AS, Bs + s*MN_BS, tid);
        asm volatile("cp.async.commit_group;\n" ::: "memory");
    }

    for (int it = 0; it < nk; it++) {
        if (it + 2 < nk) {
            int slot = (it + 2) % 3;
            load_tile_mn(Ag0, W, K, it + 2, As + slot*MN_AS, Bs + slot*MN_BS, tid);
        }
        asm volatile("cp.async.commit_group;\n" ::: "memory");
        asm volatile("cp.async.wait_group 2;\n" ::: "memory");
        __syncthreads();

        int cs = it % 3;
        const __half* Ab = As + cs*MN_AS;
        const __half* Bb = Bs + cs*MN_BS;
        #pragma unroll
        for (int kk = 0; kk < 64; kk += 16) {
            wmma::fragment<wmma::matrix_a,16,16,16,__half,wmma::row_major> af[2];
            wmma::fragment<wmma::matrix_b,16,16,16,__half,wmma::col_major> bf[2];
            #pragma unroll
            for (int i = 0; i < 2; i++)
                wmma::load_matrix_sync(af[i], Ab + (wm*32 + i*16)*HLD + kk, HLD);
            #pragma unroll
            for (int j = 0; j < 2; j++)
                wmma::load_matrix_sync(bf[j], Bb + (wn*32 + j*16)*HLD + kk, HLD);
            #pragma unroll
            for (int i = 0; i < 2; i++)
                #pragma unroll
                for (int j = 0; j < 2; j++)
                    wmma::mma_sync(cf[i][j], af[i], bf[j], cf[i][j]);
        }
        __syncthreads();
    }

    // epilogue: f32 tile [64][132] in smem, then per-row bias(+silu)+LN(+mstate)
    float* tile = reinterpret_cast<float*>(smh);
    #pragma unroll
    for (int i = 0; i < 2; i++)
        #pragma unroll
        for (int j = 0; j < 2; j++)
            wmma::store_matrix_sync(tile + (wm*32 + i*16)*132 + wn*32 + j*16,
                                    cf[i][j], 132, wmma::mem_row_major);
    __syncthreads();

    float bb4[4], gg4[4], b24[4], ms4[4];
    *reinterpret_cast<float4*>(bb4) = *reinterpret_cast<const float4*>(bias + lane*4);
    *reinterpret_cast<float4*>(gg4) = *reinterpret_cast<const float4*>(g + lane*4);
    *reinterpret_cast<float4*>(b24) = *reinterpret_cast<const float4*>(b + lane*4);
    if (ADD_MSTATE)
        *reinterpret_cast<float4*>(ms4) = *reinterpret_cast<const float4*>(mstate + lane*4);

    #pragma unroll
    for (int rr = 0; rr < 8; rr++) {
        int row = warp*8 + rr;
        float4 v4 = *reinterpret_cast<const float4*>(tile + row*132 + lane*4);
        float t[4] = {v4.x + bb4[0], v4.y + bb4[1], v4.z + bb4[2], v4.w + bb4[3]};
        if (DO_SILU) {
            #pragma unroll
            for (int e = 0; e < 4; e++) t[e] = t[e] / (1.0f + __expf(-t[e]));
        }
        float s = t[0]+t[1]+t[2]+t[3];
        float q = t[0]*t[0]+t[1]*t[1]+t[2]*t[2]+t[3]*t[3];
        #pragma unroll
        for (int o = 16; o; o >>= 1) {
            s += __shfl_xor_sync(0xffffffffu, s, o);
            q += __shfl_xor_sync(0xffffffffu, q, o);
        }
        float mu  = s * (1.0f/128.0f);
        float var = q * (1.0f/128.0f) - mu*mu;
        float rs  = rsqrtf(var + 1e-5f);
        __half2 o2[2];
        float o0 = gg4[0]*(t[0]-mu)*rs + b24[0];
        float o1 = gg4[1]*(t[1]-mu)*rs + b24[1];
        float o2f = gg4[2]*(t[2]-mu)*rs + b24[2];
        float o3 = gg4[3]*(t[3]-mu)*rs + b24[3];
        if (ADD_MSTATE) { o0 += ms4[0]; o1 += ms4[1]; o2f += ms4[2]; o3 += ms4[3]; }
        o2[0] = __floats2half2_rn(o0, o1);
        o2[1] = __floats2half2_rn(o2f, o3);
        *reinterpret_cast<float2*>(out + (size_t)(m0 + row)*128 + lane*4) =
            *reinterpret_cast<float2*>(o2);
    }
}

// ===========================================================================
// main-path GEMM, occupancy-2: 128x128 CTA tile, 32x64 warp tile, Ktile 64,
// 3 stages. MODE 0: f32. MODE 1: half. MODE 3: gate fusion. MODE 4: f32+bias.
// ===========================================================================
#define GSM_O2 (3*2*HSTS*2)

template<int MODE>
__global__ __launch_bounds__(256, 2)
void gemm_o2_kernel(const __half* __restrict__ A, const __half* __restrict__ W,
                    void* __restrict__ Cout, const float* __restrict__ bias,
                    const __half* __restrict__ aux1h, const float* __restrict__ aux2,
                    int M, int N, int K)
{
    extern __shared__ __align__(16) __half smh[];
    __half* As = smh;
    __half* Bs = smh + 3*HSTS;

    const int tid  = threadIdx.x;
    const int warp = tid >> 5;
    const int lane = tid & 31;
    const int wm   = warp & 3;
    const int wn   = warp >> 2;
    const int m0   = blockIdx.y * 128;
    const int n0   = blockIdx.x * 128;
    const int nk   = K >> 6;

    const __half* Ag0 = A + (size_t)m0*K;
    const __half* Wg0 = W + (size_t)n0*K;

    wmma::fragment<wmma::accumulator,16,16,16,float> cf[2][4];
    #pragma unroll
    for (int i = 0; i < 2; i++)
        #pragma unroll
        for (int j = 0; j < 4; j++)
            wmma::fill_fragment(cf[i][j], 0.0f);

    #pragma unroll
    for (int s = 0; s < 2; s++) {
        if (s < nk) load_tile_h(Ag0, Wg0, K, s, As + s*HSTS, Bs + s*HSTS, tid);
        asm volatile("cp.async.commit_group;\n" ::: "memory");
    }

    for (int it = 0; it < nk; it++) {
        if (it + 2 < nk) {
            int slot = (it + 2) % 3;
            load_tile_h(Ag0, Wg0, K, it + 2, As + slot*HSTS, Bs + slot*HSTS, tid);
        }
        asm volatile("cp.async.commit_group;\n" ::: "memory");
        asm volatile("cp.async.wait_group 2;\n" ::: "memory");
        __syncthreads();

        int cs = it % 3;
        const __half* Ab = As + cs*HSTS;
        const __half* Bb = Bs + cs*HSTS;
        #pragma unroll
        for (int kk = 0; kk < 64; kk += 16) {
            wmma::fragment<wmma::matrix_a,16,16,16,__half,wmma::row_major> af[2];
            wmma::fragment<wmma::matrix_b,16,16,16,__half,wmma::col_major> bf[4];
            #pragma unroll
            for (int i = 0; i < 2; i++)
                wmma::load_matrix_sync(af[i], Ab + (wm*32 + i*16)*HLD + kk, HLD);
            #pragma unroll
            for (int j = 0; j < 4; j++)
                wmma::load_matrix_sync(bf[j], Bb + (wn*64 + j*16)*HLD + kk, HLD);
            #pragma unroll
            for (int i = 0; i < 2; i++)
                #pragma unroll
                for (int j = 0; j < 4; j++)
                    wmma::mma_sync(cf[i][j], af[i], bf[j], cf[i][j]);
        }
        __syncthreads();
    }

    if (MODE == 0) {
        float* Cf = (float*)Cout;
        #pragma unroll
        for (int i = 0; i < 2; i++)
            #pragma unroll
            for (int j = 0; j < 4; j++)
                wmma::store_matrix_sync(&Cf[(size_t)(m0 + wm*32 + i*16)*N + n0 + wn*64 + j*16],
                                        cf[i][j], N, wmma::mem_row_major);
    } else {
        float* stage = reinterpret_cast<float*>(smh) + warp*256;
        #pragma unroll
        for (int i = 0; i < 2; i++)
            #pragma unroll
            for (int j = 0; j < 4; j++) {
                wmma::store_matrix_sync(stage, cf[i][j], 16, wmma::mem_row_major);
                __syncwarp();
                int mb = m0 + wm*32 + i*16;
                int nb = n0 + wn*64 + j*16;
                #pragma unroll
                for (int e = lane; e < 256; e += 32) {
                    int rr = e >> 4, cc = e & 15;
                    float v = stage[e];
                    size_t base = (size_t)(mb + rr)*N + nb + cc;
                    if (MODE == 1) {
                        ((__half*)Cout)[base] = __float2half(v);
                    } else if (MODE == 3) {
                        float gg = 1.0f / (1.0f + __expf(-(v + bias[nb + cc])));
                        ((__half*)Cout)[base] =
                            __float2half(gg*__half2float(aux1h[base]) + aux2[base]);
                    } else {  // MODE 4
                        ((float*)Cout)[base] = v + bias[nb + cc];
                    }
                }
                __syncwarp();
            }
    }
}

// ===========================================================================
// small kernels
// ===========================================================================
__global__ __launch_bounds__(256)
void biasln_c_kernel(const float* __restrict__ a, const float* __restrict__ bo,
                     const float* __restrict__ g, const float* __restrict__ b,
                     __half* __restrict__ ab, __half* __restrict__ lo)
{
    size_t base = (size_t)blockIdx.x * 1024;
    int t = threadIdx.x;
    float4 v  = *reinterpret_cast<const float4*>(a + base + t*4);
    float4 bb = *reinterpret_cast<const float4*>(bo + t*4);
    v.x += bb.x; v.y += bb.y; v.z += bb.z; v.w += bb.w;
    {
        __half2 o2[2];
        o2[0] = __floats2half2_rn(v.x, v.y);
        o2[1] = __floats2half2_rn(v.z, v.w);
        *reinterpret_cast<float2*>(ab + base + t*4) = *reinterpret_cast<float2*>(o2);
    }

    float s = v.x + v.y + v.z + v.w;
    float q = v.x*v.x + v.y*v.y + v.z*v.z + v.w*v.w;
    #pragma unroll
    for (int o = 16; o; o >>= 1) {
        s += __shfl_xor_sync(0xffffffffu, s, o);
        q += __shfl_xor_sync(0xffffffffu, q, o);
    }
    __shared__ float red[16];
    if ((t & 31) == 0) { red[t>>5] = s; red[8 + (t>>5)] = q; }
    __syncthreads();
    float S = 0.f, Q = 0.f;
    #pragma unroll
    for (int i = 0; i < 8; i++) { S += red[i]; Q += red[8+i]; }
    float mu  = S * (1.0f/1024.0f);
    float var = Q * (1.0f/1024.0f) - mu*mu;
    float rs  = rsqrtf(var + 1e-5f);

    float4 gg = *reinterpret_cast<const float4*>(g + t*4);
    float4 b2 = *reinterpret_cast<const float4*>(b + t*4);
    __half2* o = reinterpret_cast<__half2*>(lo + base + t*4);
    o[0] = __floats2half2_rn(gg.x*(v.x - mu)*rs + b2.x, gg.y*(v.y - mu)*rs + b2.y);
    o[1] = __floats2half2_rn(gg.z*(v.z - mu)*rs + b2.z, gg.w*(v.w - mu)*rs + b2.w);
}

__global__ __launch_bounds__(256)
void fuse_bias_kernel(const __half* __restrict__ WkKh, const __half* __restrict__ WvVh,
                      const float* __restrict__ mob,
                      const float* __restrict__ bk, const float* __restrict__ bv,
                      float* __restrict__ bkr, float* __restrict__ bvr)
{
    int i = blockIdx.x & 1023;
    bool isv = blockIdx.x >= 1024;
    const __half* W = isv ? WvVh : WkKh;
    float s = 0.f;
    for (int k = threadIdx.x; k < 1024; k += 256)
        s += __half2float(W[(size_t)i*1024 + k]) * mob[k];
    #pragma unroll
    for (int o = 16; o; o >>= 1) s += __shfl_xor_sync(0xffffffffu, s, o);
    __shared__ float red[8];
    if ((threadIdx.x & 31) == 0) red[threadIdx.x >> 5] = s;
    __syncthreads();
    if (threadIdx.x == 0) {
        float S = 0.f;
        #pragma unroll
        for (int w = 0; w < 8; w++) S += red[w];
        (isv ? bvr : bkr)[i] = S + (isv ? bv : bk)[i];
    }
}

__global__ __launch_bounds__(256)
void pm_proj_kernel(const float* __restrict__ pm,
                    const __half* __restrict__ WkKh, const __half* __restrict__ WvVh,
                    const float* __restrict__ bk, const float* __restrict__ bv,
                    float* __restrict__ kp, float* __restrict__ vp)
{
    int id  = blockIdx.x;
    bool isv = id >= 4096;
    int p = (id & 4095) >> 10;
    int i = id & 1023;
    const __half* W = isv ? WvVh : WkKh;
    float s = 0.f;
    for (int k = threadIdx.x; k < 1024; k += 256)
        s += pm[p*1024 + k] * __half2float(W[(size_t)i*1024 + k]);
    #pragma unroll
    for (int o = 16; o; o >>= 1) s += __shfl_xor_sync(0xffffffffu, s, o);
    __shared__ float red[8];
    if ((threadIdx.x & 31) == 0) red[threadIdx.x >> 5] = s;
    __syncthreads();
    if (threadIdx.x == 0) {
        float S = 0.f;
        #pragma unroll
        for (int w = 0; w < 8; w++) S += red[w];
        (isv ? vp : kp)[p*1024 + i] = S + (isv ? bv : bk)[i];
    }
}

// ===========================================================================
// fp16 attention: 2 CTAs per (segment, head) — each handles 32 q rows.
// grid (256, 16): h = by>>1, qhalf = by&1. 8 warps.
// smem: ps f32[32][148] | qsh h[32][136] | ksh h[144][136] | vsh h[144][136]
//       | ph h[32][152]  = 115712 B -> 2 CTAs/SM
// ===========================================================================
#define PS_LD 148
#define QK_LD 136
#define PH_LD 152
#define ATTN_SMEM (32*PS_LD*4 + (32*QK_LD + 144*QK_LD + 144*QK_LD + 32*PH_LD)*2)

__global__ __launch_bounds__(256, 2)
void attn_kernel(const __half* __restrict__ qkv,
                 const __half* __restrict__ kvr,
                 const float* __restrict__ kp, const float* __restrict__ vp,
                 const float* __restrict__ bq, const float* __restrict__ bk,
                 const float* __restrict__ bkr,
                 const float* __restrict__ bv, const float* __restrict__ bvr,
                 __half* __restrict__ outh)
{
    extern __shared__ __align__(16) float sm[];
    float*  ps  = sm;
    __half* qsh = reinterpret_cast<__half*>(sm + 32*PS_LD);
    __half* ksh = qsh + 32*QK_LD;
    __half* vsh = ksh + 144*QK_LD;
    __half* ph  = vsh + 144*QK_LD;

    const int seg  = blockIdx.x;
    const int h    = blockIdx.y >> 1;
    const int qh   = blockIdx.y & 1;
    const int tid  = threadIdx.x;
    const int warp = tid >> 5;
    const int lane = tid & 31;
    const int c0   = h * 128;
    const int q0   = seg*64 + qh*32;
    const float scale = 0.08838834764831845f;

    // q rows (32)
    for (int i = tid; i < 32*16; i += 256) {
        int r = i >> 4, c8 = (i & 15) << 3;
        float4 raw = *reinterpret_cast<const float4*>(qkv + (size_t)(q0 + r)*3072 + c0 + c8);
        const __half2* hp = reinterpret_cast<const __half2*>(&raw);
        float bv8[8];
        *reinterpret_cast<float4*>(bv8)     = *reinterpret_cast<const float4*>(bq + c0 + c8);
        *reinterpret_cast<float4*>(bv8 + 4) = *reinterpret_cast<const float4*>(bq + c0 + c8 + 4);
        __half2 o[4];
        #pragma unroll
        for (int t = 0; t < 4; t++) {
            float2 f = __half22float2(hp[t]);
            o[t] = __floats2half2_rn((f.x + bv8[2*t])*scale, (f.y + bv8[2*t+1])*scale);
        }
        *reinterpret_cast<float4*>(qsh + r*QK_LD + c8) = *reinterpret_cast<float4*>(o);
    }
    // k rows (144; >=132 zero)
    for (int i = tid; i < 144*16; i += 256) {
        int r = i >> 4, c8 = (i & 15) << 3;
        float vals[8] = {0,0,0,0,0,0,0,0};
        if (r < 64) {
            float4 raw = *reinterpret_cast<const float4*>(kvr + (size_t)(seg*64 + r)*2048 + c0 + c8);
            const __half2* hp = reinterpret_cast<const __half2*>(&raw);
            float b8[8];
            *reinterpret_cast<float4*>(b8)     = *reinterpret_cast<const float4*>(bkr + c0 + c8);
            *reinterpret_cast<float4*>(b8 + 4) = *reinterpret_cast<const float4*>(bkr + c0 + c8 + 4);
            #pragma unroll
            for (int t = 0; t < 4; t++) {
                float2 f = __half22float2(hp[t]);
                vals[2*t] = f.x + b8[2*t]; vals[2*t+1] = f.y + b8[2*t+1];
            }
        } else if (r < 68) {
            *reinterpret_cast<float4*>(vals)     = *reinterpret_cast<const float4*>(kp + (size_t)(r-64)*1024 + c0 + c8);
            *reinterpret_cast<float4*>(vals + 4) = *reinterpret_cast<const float4*>(kp + (size_t)(r-64)*1024 + c0 + c8 + 4);
        } else if (r < 132) {
            float4 raw = *reinterpret_cast<const float4*>(qkv + (size_t)(seg*64 + r - 68)*3072 + 1024 + c0 + c8);
            const __half2* hp = reinterpret_cast<const __half2*>(&raw);
            float b8[8];
            *reinterpret_cast<float4*>(b8)     = *reinterpret_cast<const float4*>(bk + c0 + c8);
            *reinterpret_cast<float4*>(b8 + 4) = *reinterpret_cast<const float4*>(bk + c0 + c8 + 4);
            #pragma unroll
            for (int t = 0; t < 4; t++) {
                float2 f = __half22float2(hp[t]);
                vals[2*t] = f.x + b8[2*t]; vals[2*t+1] = f.y + b8[2*t+1];
            }
        }
        __half2 o[4];
        #pragma unroll
        for (int t = 0; t < 4; t++) o[t] = __floats2half2_rn(vals[2*t], vals[2*t+1]);
        *reinterpret_cast<float4*>(ksh + r*QK_LD + c8) = *reinterpret_cast<float4*>(o);
    }
    // v rows (144; >=132 zero)
    for (int i = tid; i < 144*16; i += 256) {
        int r = i >> 4, c8 = (i & 15) << 3;
        float vals[8] = {0,0,0,0,0,0,0,0};
        if (r < 64) {
            float4 raw = *reinterpret_cast<const float4*>(kvr + (size_t)(seg*64 + r)*2048 + 1024 + c0 + c8);
            const __half2* hp = reinterpret_cast<const __half2*>(&raw);
            float b8[8];
            *reinterpret_cast<float4*>(b8)     = *reinterpret_cast<const float4*>(bvr + c0 + c8);
            *reinterpret_cast<float4*>(b8 + 4) = *reinterpret_cast<const float4*>(bvr + c0 + c8 + 4);
            #pragma unroll
            for (int t = 0; t < 4; t++) {
                float2 f = __half22float2(hp[t]);
                vals[2*t] = f.x + b8[2*t]; vals[2*t+1] = f.y + b8[2*t+1];
            }
        } else if (r < 68) {
            *reinterpret_cast<float4*>(vals)     = *reinterpret_cast<const float4*>(vp + (size_t)(r-64)*1024 + c0 + c8);
            *reinterpret_cast<float4*>(vals + 4) = *reinterpret_cast<const float4*>(vp + (size_t)(r-64)*1024 + c0 + c8 + 4);
        } else if (r < 132) {
            float4 raw = *reinterpret_cast<const float4*>(qkv + (size_t)(seg*64 + r - 68)*3072 + 2048 + c0 + c8);
            const __half2* hp = reinterpret_cast<const __half2*>(&raw);
            float b8[8];
            *reinterpret_cast<float4*>(b8)     = *reinterpret_cast<const float4*>(bv + c0 + c8);
            *reinterpret_cast<float4*>(b8 + 4) = *reinterpret_cast<const float4*>(bv + c0 + c8 + 4);
            #pragma unroll
            for (int t = 0; t < 4; t++) {
                float2 f = __half22float2(hp[t]);
                vals[2*t] = f.x + b8[2*t]; vals[2*t+1] = f.y + b8[2*t+1];
            }
        }
        __half2 o[4];
        #pragma unroll
        for (int t = 0; t < 4; t++) o[t] = __floats2half2_rn(vals[2*t], vals[2*t+1]);
        *reinterpret_cast<float4*>(vsh + r*QK_LD + c8) = *reinterpret_cast<float4*>(o);
    }
    __syncthreads();

    // scores = q @ k^T : 32 x 144 (2x9 tiles)
    for (int t = warp; t < 18; t += 8) {
        int ms = (t / 9) * 16;
        int ns = (t % 9) * 16;
        wmma::fragment<wmma::accumulator,16,16,16,float> acc;
        wmma::fill_fragment(acc, 0.0f);
        #pragma unroll
        for (int kk = 0; kk < 128; kk += 16) {
            wmma::fragment<wmma::matrix_a,16,16,16,__half,wmma::row_major> af;
            wmma::fragment<wmma::matrix_b,16,16,16,__half,wmma::col_major> bf;
            wmma::load_matrix_sync(af, qsh + ms*QK_LD + kk, QK_LD);
            wmma::load_matrix_sync(bf, ksh + ns*QK_LD + kk, QK_LD);
            wmma::mma_sync(acc, af, bf, acc);
        }
        wmma::store_matrix_sync(ps + ms*PS_LD + ns, acc, PS_LD, wmma::mem_row_major);
    }
    __syncthreads();

    // softmax: warp w handles rows 4w..4w+4 (132 valid cols)
    for (int r = warp*4; r < warp*4 + 4; r++) {
        float* row = ps + r*PS_LD;
        float m = -1e30f;
        for (int c = lane; c < 132; c += 32) m = fmaxf(m, row[c]);
        #pragma unroll
        for (int o = 16; o; o >>= 1) m = fmaxf(m, __shfl_xor_sync(0xffffffffu, m, o));
        float s = 0.f;
        for (int c = lane; c < 132; c += 32) { float e = __expf(row[c] - m); row[c] = e; s += e; }
        #pragma unroll
        for (int o = 16; o; o >>= 1) s += __shfl_xor_sync(0xffffffffu, s, o);
        float inv = 1.0f / s;
        for (int c = lane; c < 132; c += 32) ph[r*PH_LD + c] = __float2half(row[c]*inv);
        if (lane < 20) ph[r*PH_LD + 132 + lane] = __float2half(0.0f);
    }
    __syncthreads();

    // out = p @ v : 32 x 128 (2x8 tiles), k=144
    for (int t = warp; t < 16; t += 8) {
        int ms = (t >> 3) * 16;
        int ds = (t & 7) * 16;
        wmma::fragment<wmma::accumulator,16,16,16,float> acc;
        wmma::fill_fragment(acc, 0.0f);
        #pragma unroll
        for (int kk = 0; kk < 144; kk += 16) {
            wmma::fragment<wmma::matrix_a,16,16,16,__half,wmma::row_major> af;
            wmma::fragment<wmma::matrix_b,16,16,16,__half,wmma::row_major> bf;
            wmma::load_matrix_sync(af, ph + ms*PH_LD + kk, PH_LD);
            wmma::load_matrix_sync(bf, vsh + kk*QK_LD + ds, QK_LD);
            wmma::mma_sync(acc, af, bf, acc);
        }
        wmma::store_matrix_sync(ps + ms*PS_LD + ds, acc, PS_LD, wmma::mem_row_major);
    }
    __syncthreads();

    for (int i = tid; i < 32*16; i += 256) {
        int r = i >> 4, c8 = (i & 15) << 3;
        const float* src = ps + r*PS_LD + c8;
        __half2 o[4];
        #pragma unroll
        for (int t = 0; t < 4; t++) o[t] = __floats2half2_rn(src[2*t], src[2*t+1]);
        *reinterpret_cast<float4*>(outh + (size_t)(q0 + r)*1024 + c0 + c8) =
            *reinterpret_cast<float4*>(o);
    }
}

// ===========================================================================
extern "C" void kernel_launch(void* const* d_in, const int* in_sizes, int n_in,
                              void* d_out, int out_size)
{
    const float* x      = (const float*)d_in[0];
    const float* pm     = (const float*)d_in[1];
    const float* Wq     = (const float*)d_in[2];
    const float* Wk     = (const float*)d_in[3];
    const float* Wv     = (const float*)d_in[4];
    const float* mem_W1 = (const float*)d_in[5];
    const float* mem_b1 = (const float*)d_in[6];
    const float* ln1_g  = (const float*)d_in[7];
    const float* ln1_b  = (const float*)d_in[8];
    const float* mem_W2 = (const float*)d_in[9];
    const float* mem_b2 = (const float*)d_in[10];
    const float* ln2_g  = (const float*)d_in[11];
    const float* ln2_b  = (const float*)d_in[12];
    const float* mem_oW = (const float*)d_in[13];
    const float* mem_ob = (const float*)d_in[14];
    const float* mstate = (const float*)d_in[15];
    const float* mha_Wq = (const float*)d_in[16];
    const float* mha_bq = (const float*)d_in[17];
    const float* mha_Wk = (const float*)d_in[18];
    const float* mha_bk = (const float*)d_in[19];
    const float* mha_Wv = (const float*)d_in[20];
    const float* mha_bv = (const float*)d_in[21];
    const float* mha_Wo = (const float*)d_in[22];
    const float* mha_bo = (const float*)d_in[23];
    const float* gn_g   = (const float*)d_in[24];
    const float* gn_b   = (const float*)d_in[25];
    const float* gate_W = (const float*)d_in[26];
    const float* gate_b = (const float*)d_in[27];
    const float* out_W  = (const float*)d_in[28];
    const float* out_b  = (const float*)d_in[29];
    float* out = (float*)d_out;

    void* sp; cudaGetSymbolAddress(&sp, d_scratch);
    float* S0 = (float*)sp;
    float* A4 = S0;                                     // [16384][1024] f32
    float* kp  = A4 + 16777216ull;
    float* vp  = kp + 4096;
    float* bkr = vp + 4096;
    float* bvr = bkr + 1024;
    __half* xh     = (__half*)(bvr + 1024);
    __half* qkvh   = xh     + 16777216ull;
    __half* kvrh   = qkvh   + 50331648ull;
    __half* A3h    = kvrh   + 33554432ull;
    __half* A4h    = A3h    + 16777216ull;
    __half* A5h    = A4h    + 16777216ull;
    __half* uh     = A5h    + 16777216ull;
    __half* m2ah   = uh     + 16777216ull;
    __half* m2h    = m2ah   + 2097152ull;
    __half* Wallh  = m2h    + 2097152ull;
    __half* Wkrvh  = Wallh  + 3145728ull;
    __half* W1qh   = Wkrvh  + 262144ull;
    __half* W2h    = W1qh   + 131072ull;
    __half* Woh    = W2h    + 16384ull;
    __half* gateh  = Woh    + 1048576ull;
    __half* outh   = gateh  + 1048576ull;
    __half* mWq_h  = outh   + 1048576ull;
    __half* mWk_h  = mWq_h  + 1048576ull;
    __half* mWv_h  = mWk_h  + 1048576ull;
    __half* memW1h = mWv_h  + 1048576ull;
    __half* Wq_h   = memW1h + 131072ull;
    __half* Wk_h   = Wq_h   + 1048576ull;
    __half* Wv_h   = Wk_h   + 1048576ull;
    __half* moW_h  = Wv_h   + 1048576ull;
    __half* WkKh   = Wallh  + 1048576ull;
    __half* WvVh   = Wallh  + 2097152ull;

    cudaFuncSetAttribute(wall_prep_h_kernel, cudaFuncAttributeMaxDynamicSharedMemorySize, GSM_NT);
    cudaFuncSetAttribute(wkrv_prep_h_kernel, cudaFuncAttributeMaxDynamicSharedMemorySize, GSM_NT);
    cudaFuncSetAttribute(memnet_kernel<1,0>, cudaFuncAttributeMaxDynamicSharedMemorySize, GSM_MN);
    cudaFuncSetAttribute(memnet_kernel<0,1>, cudaFuncAttributeMaxDynamicSharedMemorySize, GSM_MN);
    cudaFuncSetAttribute(gemm_o2_kernel<0>,  cudaFuncAttributeMaxDynamicSharedMemorySize, GSM_O2);
    cudaFuncSetAttribute(gemm_o2_kernel<1>,  cudaFuncAttributeMaxDynamicSharedMemorySize, GSM_O2);
    cudaFuncSetAttribute(gemm_o2_kernel<3>,  cudaFuncAttributeMaxDynamicSharedMemorySize, GSM_O2);
    cudaFuncSetAttribute(gemm_o2_kernel<4>,  cudaFuncAttributeMaxDynamicSharedMemorySize, GSM_O2);
    cudaFuncSetAttribute(attn_kernel,        cudaFuncAttributeMaxDynamicSharedMemorySize, ATTN_SMEM);

    dim3 blk(256);

    // 1) batched f32->f16 converts
    ConvBatch cb;
    cb.src[0] = x;      cb.dst[0] = xh;     cb.n[0] = 16777216u;
    cb.src[1] = mem_W2; cb.dst[1] = W2h;    cb.n[1] = 16384u;
    cb.src[2] = mha_Wo; cb.dst[2] = Woh;    cb.n[2] = 1048576u;
    cb.src[3] = gate_W; cb.dst[3] = gateh;  cb.n[3] = 1048576u;
    cb.src[4] = out_W;  cb.dst[4] = outh;   cb.n[4] = 1048576u;
    cb.src[5] = mha_Wq; cb.dst[5] = mWq_h;  cb.n[5] = 1048576u;
    cb.src[6] = mha_Wk; cb.dst[6] = mWk_h;  cb.n[6] = 1048576u;
    cb.src[7] = mha_Wv; cb.dst[7] = mWv_h;  cb.n[7] = 1048576u;
    cb.src[8] = mem_W1; cb.dst[8] = memW1h; cb.n[8] = 131072u;
    cb.src[9] = Wq;     cb.dst[9] = Wq_h;   cb.n[9] = 1048576u;
    cb.src[10] = Wk;    cb.dst[10] = Wk_h;  cb.n[10] = 1048576u;
    cb.src[11] = Wv;    cb.dst[11] = Wv_h;  cb.n[11] = 1048576u;
    cb.src[12] = mem_oW; cb.dst[12] = moW_h; cb.n[12] = 131072u;
    conv_batch_kernel<<<dim3(1024, 13), blk>>>(cb);

    // 2-3) fp16 weight prep (occ-2)
    wall_prep_h_kernel<<<dim3(8,25), blk, GSM_NT>>>(mWq_h, mWk_h, mWv_h, memW1h,
                                                    Wq_h, Wk_h, Wv_h, Wallh, W1qh);
    wkrv_prep_h_kernel<<<dim3(1,16), blk, GSM_NT>>>(Wallh, moW_h, Wkrvh);

    // 4-5) memory net fused (M-tile 64, grid 256)
    memnet_kernel<1,0><<<dim3(1,256), blk, GSM_MN>>>(xh, W1qh, mem_b1, ln1_g, ln1_b,
                                                     nullptr, m2ah, 1024);
    memnet_kernel<0,1><<<dim3(1,256), blk, GSM_MN>>>(m2ah, W2h, mem_b2, ln2_g, ln2_b,
                                                     mstate, m2h, 128);

    // 6-7) fused q|k|v + retrieved k|v (occ-2 GEMM, half outputs)
    gemm_o2_kernel<1><<<dim3(24,128), blk, GSM_O2>>>(xh,  Wallh, qkvh, nullptr, nullptr, nullptr, 16384, 3072, 1024);
    gemm_o2_kernel<1><<<dim3(16,128), blk, GSM_O2>>>(m2h, Wkrvh, kvrh, nullptr, nullptr, nullptr, 16384, 2048, 128);

    // 8-9) per-head constants
    fuse_bias_kernel<<<2048, 256>>>(WkKh, WvVh, mem_ob, mha_bk, mha_bv, bkr, bvr);
    pm_proj_kernel<<<8192, 256>>>(pm, WkKh, WvVh, mha_bk, mha_bv, kp, vp);

    // 10) attention (2 CTAs per seg-head, occ-2)
    attn_kernel<<<dim3(256, 16), 256, ATTN_SMEM>>>(qkvh, kvrh, kp, vp,
                                                   mha_bq, mha_bk, bkr, mha_bv, bvr, A3h);

    // 11-14) output path
    gemm_o2_kernel<0><<<dim3(8,128), blk, GSM_O2>>>(A3h, Woh, A4, nullptr, nullptr, nullptr, 16384, 1024, 1024);
    biasln_c_kernel<<<16384, 256>>>(A4, mha_bo, gn_g, gn_b, A4h, A5h);
    gemm_o2_kernel<3><<<dim3(8,128), blk, GSM_O2>>>(A5h, gateh, uh, gate_b, A4h, x, 16384, 1024, 1024);
    gemm_o2_kernel<4><<<dim3(8,128), blk, GSM_O2>>>(uh, outh, out, out_b, nullptr, nullptr, 16384, 1024, 1024);
}